// round 1
// baseline (speedup 1.0000x reference)
#include <cuda_runtime.h>
#include <math.h>

#define Tn 4096
#define Cn 256
#define Bn 2
#define SCALE_QK 0.35355339059327373f   // 64^-0.25

// ---- scratch (__device__ globals: allocation-free) ----
__device__ float g_xn  [Bn * Cn  * Tn];   // group-normed x          [B,256,T]
__device__ float g_qkv [Bn * 768 * Tn];   // qkv (q,k pre-scaled)    [B,768,T]
__device__ float g_attn[Bn * Cn  * Tn];   // attention output 'a'    [B,256,T]

// ============================================================================
// 1) GroupNorm: one block per (batch, group). 32 groups, 8 ch/group, 32768 el.
// ============================================================================
__global__ __launch_bounds__(256) void gn_kernel(const float* __restrict__ x,
                                                 const float* __restrict__ w,
                                                 const float* __restrict__ bias) {
    const int b = blockIdx.x >> 5;
    const int g = blockIdx.x & 31;
    const size_t base = ((size_t)b * Cn + g * 8) * Tn;
    const float4* xp = (const float4*)(x + base);
    float4* op = (float4*)(g_xn + base);
    const int N4 = 8 * Tn / 4;  // 8192 float4s

    float s = 0.f, s2 = 0.f;
    for (int i = threadIdx.x; i < N4; i += 256) {
        float4 v = xp[i];
        s  += v.x + v.y + v.z + v.w;
        s2 += v.x*v.x + v.y*v.y + v.z*v.z + v.w*v.w;
    }
    __shared__ float rs[256], rs2[256];
    rs[threadIdx.x] = s; rs2[threadIdx.x] = s2;
    __syncthreads();
    for (int off = 128; off > 0; off >>= 1) {
        if (threadIdx.x < off) {
            rs [threadIdx.x] += rs [threadIdx.x + off];
            rs2[threadIdx.x] += rs2[threadIdx.x + off];
        }
        __syncthreads();
    }
    const float inv  = 1.f / (8.f * Tn);
    const float mean = rs[0] * inv;
    const float var  = rs2[0] * inv - mean * mean;
    const float rstd = rsqrtf(var + 1e-5f);

    for (int i = threadIdx.x; i < N4; i += 256) {
        int c = g * 8 + (i >> 10);          // Tn/4 = 1024 float4 per channel
        float wc = w[c] * rstd;
        float bc = bias[c] - mean * wc;
        float4 v = xp[i];
        v.x = v.x * wc + bc; v.y = v.y * wc + bc;
        v.z = v.z * wc + bc; v.w = v.w * wc + bc;
        op[i] = v;
    }
}

// ============================================================================
// 2/4) GEMM: out[b,m,n] = sum_k A[m,k] * Bmat[b,k,n]  (K = 256)
//   MODE 0: A=qkv_w  Bmat=g_xn   out=g_qkv  (+bias, scale q/k rows)
//   MODE 1: A=proj_w Bmat=g_attn out=d_out  (+bias, +residual x)
// 64x64 block tile, 16 K-slice, 4x4 register tile per thread (256 threads).
// ============================================================================
template<int MODE>
__global__ __launch_bounds__(256) void gemm_kernel(const float* __restrict__ A,
                                                   const float* __restrict__ bias,
                                                   const float* __restrict__ resid,
                                                   float* __restrict__ out_param) {
    __shared__ float a_s[16][68];
    __shared__ float b_s[16][68];
    const int K = 256;
    const int tid = threadIdx.x;
    const int ty = tid >> 4, tx = tid & 15;
    const int m0 = blockIdx.y * 64, n0 = blockIdx.x * 64;
    const float* __restrict__ Bmat = (MODE == 0) ? g_xn : g_attn;
    float* __restrict__ outp       = (MODE == 0) ? g_qkv : out_param;
    const size_t bb = (size_t)blockIdx.z * K * Tn;

    float acc[4][4] = {};
    for (int k0 = 0; k0 < K; k0 += 16) {
        {   // A tile 64m x 16k -> a_s[k][m]
            int m = tid >> 2, kq = tid & 3;
            float4 v = *(const float4*)(A + (size_t)(m0 + m) * K + k0 + kq * 4);
            a_s[kq*4+0][m] = v.x; a_s[kq*4+1][m] = v.y;
            a_s[kq*4+2][m] = v.z; a_s[kq*4+3][m] = v.w;
        }
        {   // B tile 16k x 64n
            int k = tid >> 4, nq = tid & 15;
            *(float4*)&b_s[k][nq*4] =
                *(const float4*)(Bmat + bb + (size_t)(k0 + k) * Tn + n0 + nq * 4);
        }
        __syncthreads();
        #pragma unroll
        for (int k = 0; k < 16; k++) {
            float4 a4 = *(float4*)&a_s[k][ty*4];
            float4 b4 = *(float4*)&b_s[k][tx*4];
            float av[4] = {a4.x, a4.y, a4.z, a4.w};
            float bv[4] = {b4.x, b4.y, b4.z, b4.w};
            #pragma unroll
            for (int i = 0; i < 4; i++)
                #pragma unroll
                for (int j = 0; j < 4; j++)
                    acc[i][j] += av[i] * bv[j];
        }
        __syncthreads();
    }
    #pragma unroll
    for (int i = 0; i < 4; i++) {
        const int m = m0 + ty * 4 + i;
        const float bi = bias[m];
        float scale = 1.f;
        if (MODE == 0) { if ((m % 192) < 128) scale = SCALE_QK; }
        const size_t orow = ((size_t)blockIdx.z * (MODE == 0 ? 768 : Cn) + m) * Tn + n0;
        #pragma unroll
        for (int j = 0; j < 4; j++) {
            float v = (acc[i][j] + bi) * scale;
            if (MODE == 1) v += resid[orow + tx * 4 + j];
            outp[orow + tx * 4 + j] = v;
        }
    }
}

// ============================================================================
// 3) Flash attention. Grid: (T/64 t-tiles, B*NH). ch = 64, online softmax.
//    q,k already scaled by 64^-0.25. Layouts in smem: q/k/v [c][x], p [t][s].
// ============================================================================
__global__ __launch_bounds__(256) void attn_kernel() {
    extern __shared__ float sm[];
    float (*q_s)[68] = (float(*)[68])(sm);
    float (*k_s)[68] = (float(*)[68])(sm + 64 * 68);
    float (*v_s)[68] = (float(*)[68])(sm + 2 * 64 * 68);
    float (*p_s)[68] = (float(*)[68])(sm + 3 * 64 * 68);

    const int tid = threadIdx.x;
    const int ty = tid >> 4, tx = tid & 15;
    const int t0 = blockIdx.x * 64;
    const int bh = blockIdx.y;
    const int b = bh >> 2, h = bh & 3;
    const float* qp = g_qkv + ((size_t)b * 768 + h * 192) * Tn;
    const float* kp = qp + (size_t)64 * Tn;
    const float* vp = qp + (size_t)128 * Tn;
    float* ap = g_attn + ((size_t)b * Cn + h * 64) * Tn;

    // Q tile: q_s[c][t]
    for (int q = tid; q < 1024; q += 256) {
        int c = q >> 4, tq = q & 15;
        *(float4*)&q_s[c][tq*4] = *(const float4*)(qp + (size_t)c * Tn + t0 + tq * 4);
    }

    float m_i[4], l_i[4], o[4][4];
    #pragma unroll
    for (int i = 0; i < 4; i++) {
        m_i[i] = -1e30f; l_i[i] = 0.f;
        #pragma unroll
        for (int j = 0; j < 4; j++) o[i][j] = 0.f;
    }

    for (int s0 = 0; s0 < Tn; s0 += 64) {
        __syncthreads();   // q_s visible (iter 0); k/v/p reuse safe (iters > 0)
        for (int q = tid; q < 1024; q += 256) {
            int c = q >> 4, sq = q & 15;
            *(float4*)&k_s[c][sq*4] = *(const float4*)(kp + (size_t)c * Tn + s0 + sq * 4);
            *(float4*)&v_s[c][sq*4] = *(const float4*)(vp + (size_t)c * Tn + s0 + sq * 4);
        }
        __syncthreads();

        // S = Q^T K  (outer product over c)
        float s_acc[4][4] = {};
        #pragma unroll 8
        for (int c = 0; c < 64; c++) {
            float4 q4 = *(float4*)&q_s[c][ty*4];
            float4 k4 = *(float4*)&k_s[c][tx*4];
            float qv[4] = {q4.x, q4.y, q4.z, q4.w};
            float kv[4] = {k4.x, k4.y, k4.z, k4.w};
            #pragma unroll
            for (int i = 0; i < 4; i++)
                #pragma unroll
                for (int j = 0; j < 4; j++)
                    s_acc[i][j] += qv[i] * kv[j];
        }

        // online softmax (rows owned by 16-lane half-warp groups sharing ty)
        float mnew[4];
        #pragma unroll
        for (int i = 0; i < 4; i++) {
            float r = fmaxf(fmaxf(s_acc[i][0], s_acc[i][1]),
                            fmaxf(s_acc[i][2], s_acc[i][3]));
            #pragma unroll
            for (int off = 8; off > 0; off >>= 1)
                r = fmaxf(r, __shfl_xor_sync(0xffffffffu, r, off));
            mnew[i] = fmaxf(m_i[i], r);
        }
        #pragma unroll
        for (int i = 0; i < 4; i++) {
            float alpha = __expf(m_i[i] - mnew[i]);
            m_i[i] = mnew[i];
            float rsum = 0.f;
            #pragma unroll
            for (int j = 0; j < 4; j++) {
                float p = __expf(s_acc[i][j] - mnew[i]);
                s_acc[i][j] = p;
                rsum += p;
            }
            #pragma unroll
            for (int off = 8; off > 0; off >>= 1)
                rsum += __shfl_xor_sync(0xffffffffu, rsum, off);
            l_i[i] = l_i[i] * alpha + rsum;
            #pragma unroll
            for (int j = 0; j < 4; j++) o[i][j] *= alpha;
            *(float4*)&p_s[ty*4+i][tx*4] =
                make_float4(s_acc[i][0], s_acc[i][1], s_acc[i][2], s_acc[i][3]);
        }
        __syncthreads();

        // O += P @ V^T (inner product over s; row reads of p_s and v_s)
        #pragma unroll 4
        for (int s4 = 0; s4 < 64; s4 += 4) {
            float4 pv[4], vv[4];
            #pragma unroll
            for (int i = 0; i < 4; i++) pv[i] = *(float4*)&p_s[ty*4+i][s4];
            #pragma unroll
            for (int j = 0; j < 4; j++) vv[j] = *(float4*)&v_s[tx*4+j][s4];
            #pragma unroll
            for (int i = 0; i < 4; i++)
                #pragma unroll
                for (int j = 0; j < 4; j++) {
                    o[i][j] += pv[i].x * vv[j].x;
                    o[i][j] += pv[i].y * vv[j].y;
                    o[i][j] += pv[i].z * vv[j].z;
                    o[i][j] += pv[i].w * vv[j].w;
                }
        }
    }

    // normalize + stage O into smem as [c][t], then coalesced writeback
    __syncthreads();
    #pragma unroll
    for (int i = 0; i < 4; i++) {
        float rl = 1.f / l_i[i];
        #pragma unroll
        for (int j = 0; j < 4; j++)
            p_s[tx*4+j][ty*4+i] = o[i][j] * rl;
    }
    __syncthreads();
    for (int q = tid; q < 1024; q += 256) {
        int c = q >> 4, tq = q & 15;
        *(float4*)(ap + (size_t)c * Tn + t0 + tq * 4) = *(float4*)&p_s[c][tq*4];
    }
}

// ============================================================================
extern "C" void kernel_launch(void* const* d_in, const int* in_sizes, int n_in,
                              void* d_out, int out_size) {
    const float* x     = (const float*)d_in[0];
    const float* nw    = (const float*)d_in[1];
    const float* nb    = (const float*)d_in[2];
    const float* qkvw  = (const float*)d_in[3];
    const float* qkvb  = (const float*)d_in[4];
    const float* projw = (const float*)d_in[5];
    const float* projb = (const float*)d_in[6];
    float* out = (float*)d_out;

    const int ATTN_SMEM = 4 * 64 * 68 * sizeof(float);  // 69632 B
    cudaFuncSetAttribute(attn_kernel, cudaFuncAttributeMaxDynamicSharedMemorySize,
                         ATTN_SMEM);

    gn_kernel<<<Bn * 32, 256>>>(x, nw, nb);
    gemm_kernel<0><<<dim3(Tn / 64, 768 / 64, Bn), 256>>>(qkvw, qkvb, nullptr, nullptr);
    attn_kernel<<<dim3(Tn / 64, Bn * 4), 256, ATTN_SMEM>>>();
    gemm_kernel<1><<<dim3(Tn / 64, Cn / 64, Bn), 256>>>(projw, projb, x, out);
}

// round 2
// speedup vs baseline: 4.1350x; 4.1350x over previous
#include <cuda_runtime.h>
#include <math.h>

#define Tn 4096
#define Cn 256
#define Bn 2
#define SCALE_QK 0.35355339059327373f   // 64^-0.25

// ---- scratch (__device__ globals: allocation-free) ----
__device__ float g_xn  [Bn * Cn  * Tn];   // group-normed x          [B,256,T]
__device__ float g_qkv [Bn * 768 * Tn];   // qkv (q,k pre-scaled)    [B,768,T]
__device__ float g_attn[Bn * Cn  * Tn];   // attention output 'a'    [B,256,T]

// ---- tf32 helpers ----
__device__ __forceinline__ float f2tf(float x) {
    float r;
    asm("cvt.rna.tf32.f32 %0, %1;" : "=f"(r) : "f"(x));
    return r;
}
__device__ __forceinline__ void mma_tf32(float c[4],
                                         unsigned a0, unsigned a1, unsigned a2, unsigned a3,
                                         unsigned b0, unsigned b1) {
    asm volatile(
        "mma.sync.aligned.m16n8k8.row.col.f32.tf32.tf32.f32 "
        "{%0,%1,%2,%3},{%4,%5,%6,%7},{%8,%9},{%0,%1,%2,%3};"
        : "+f"(c[0]), "+f"(c[1]), "+f"(c[2]), "+f"(c[3])
        : "r"(a0), "r"(a1), "r"(a2), "r"(a3), "r"(b0), "r"(b1));
}

// ============================================================================
// 1) GroupNorm: one block per (batch, group). 32 groups, 8 ch/group, 32768 el.
// ============================================================================
__global__ __launch_bounds__(256) void gn_kernel(const float* __restrict__ x,
                                                 const float* __restrict__ w,
                                                 const float* __restrict__ bias) {
    const int b = blockIdx.x >> 5;
    const int g = blockIdx.x & 31;
    const size_t base = ((size_t)b * Cn + g * 8) * Tn;
    const float4* xp = (const float4*)(x + base);
    float4* op = (float4*)(g_xn + base);
    const int N4 = 8 * Tn / 4;  // 8192 float4s

    float s = 0.f, s2 = 0.f;
    for (int i = threadIdx.x; i < N4; i += 256) {
        float4 v = xp[i];
        s  += v.x + v.y + v.z + v.w;
        s2 += v.x*v.x + v.y*v.y + v.z*v.z + v.w*v.w;
    }
    __shared__ float rs[256], rs2[256];
    rs[threadIdx.x] = s; rs2[threadIdx.x] = s2;
    __syncthreads();
    for (int off = 128; off > 0; off >>= 1) {
        if (threadIdx.x < off) {
            rs [threadIdx.x] += rs [threadIdx.x + off];
            rs2[threadIdx.x] += rs2[threadIdx.x + off];
        }
        __syncthreads();
    }
    const float inv  = 1.f / (8.f * Tn);
    const float mean = rs[0] * inv;
    const float var  = rs2[0] * inv - mean * mean;
    const float rstd = rsqrtf(var + 1e-5f);

    for (int i = threadIdx.x; i < N4; i += 256) {
        int c = g * 8 + (i >> 10);
        float wc = w[c] * rstd;
        float bc = bias[c] - mean * wc;
        float4 v = xp[i];
        v.x = v.x * wc + bc; v.y = v.y * wc + bc;
        v.z = v.z * wc + bc; v.w = v.w * wc + bc;
        op[i] = v;
    }
}

// ============================================================================
// 2/4) GEMM (CUDA-core fp32, unchanged): out[b,m,n] = sum_k A[m,k]*Bmat[b,k,n]
// ============================================================================
template<int MODE>
__global__ __launch_bounds__(256) void gemm_kernel(const float* __restrict__ A,
                                                   const float* __restrict__ bias,
                                                   const float* __restrict__ resid,
                                                   float* __restrict__ out_param) {
    __shared__ float a_s[16][68];
    __shared__ float b_s[16][68];
    const int K = 256;
    const int tid = threadIdx.x;
    const int ty = tid >> 4, tx = tid & 15;
    const int m0 = blockIdx.y * 64, n0 = blockIdx.x * 64;
    const float* __restrict__ Bmat = (MODE == 0) ? g_xn : g_attn;
    float* __restrict__ outp       = (MODE == 0) ? g_qkv : out_param;
    const size_t bb = (size_t)blockIdx.z * K * Tn;

    float acc[4][4] = {};
    for (int k0 = 0; k0 < K; k0 += 16) {
        {
            int m = tid >> 2, kq = tid & 3;
            float4 v = *(const float4*)(A + (size_t)(m0 + m) * K + k0 + kq * 4);
            a_s[kq*4+0][m] = v.x; a_s[kq*4+1][m] = v.y;
            a_s[kq*4+2][m] = v.z; a_s[kq*4+3][m] = v.w;
        }
        {
            int k = tid >> 4, nq = tid & 15;
            *(float4*)&b_s[k][nq*4] =
                *(const float4*)(Bmat + bb + (size_t)(k0 + k) * Tn + n0 + nq * 4);
        }
        __syncthreads();
        #pragma unroll
        for (int k = 0; k < 16; k++) {
            float4 a4 = *(float4*)&a_s[k][ty*4];
            float4 b4 = *(float4*)&b_s[k][tx*4];
            float av[4] = {a4.x, a4.y, a4.z, a4.w};
            float bv[4] = {b4.x, b4.y, b4.z, b4.w};
            #pragma unroll
            for (int i = 0; i < 4; i++)
                #pragma unroll
                for (int j = 0; j < 4; j++)
                    acc[i][j] += av[i] * bv[j];
        }
        __syncthreads();
    }
    #pragma unroll
    for (int i = 0; i < 4; i++) {
        const int m = m0 + ty * 4 + i;
        const float bi = bias[m];
        float scale = 1.f;
        if (MODE == 0) { if ((m % 192) < 128) scale = SCALE_QK; }
        const size_t orow = ((size_t)blockIdx.z * (MODE == 0 ? 768 : Cn) + m) * Tn + n0;
        #pragma unroll
        for (int j = 0; j < 4; j++) {
            float v = (acc[i][j] + bi) * scale;
            if (MODE == 1) v += resid[orow + tx * 4 + j];
            outp[orow + tx * 4 + j] = v;
        }
    }
}

// ============================================================================
// 3) Flash attention on tensor cores (tf32 mma.sync, fp32 accum + softmax).
//    Block: 256 thr / 8 warps. Q-tile 128 t-rows (16 per warp), KV-tile 64.
//    Smem: one shared 128x68 buffer for Q-staging / P / O-staging (aliased),
//          K [64][72], V [64][76] — strides chosen bank-conflict-free.
// ============================================================================
#define QPS 68
#define KSS 72
#define VSS 76

__global__ __launch_bounds__(256, 2) void attn_kernel() {
    extern __shared__ float sm[];
    float* qp_s = sm;                    // [128][QPS]  Q-stage / P / O-stage
    float* k_s  = sm + 128 * QPS;        // [64][KSS]
    float* v_s  = k_s + 64 * KSS;        // [64][VSS]

    const int tid  = threadIdx.x;
    const int wid  = tid >> 5;
    const int lane = tid & 31;
    const int g    = lane >> 2;          // group row 0..7
    const int t4   = lane & 3;           // thread-in-group
    const int tw   = wid * 16;           // warp's t-row base in tile

    const int t0 = blockIdx.x * 128;
    const int bh = blockIdx.y;
    const int b  = bh >> 2, h = bh & 3;
    const float* qg = g_qkv + ((size_t)b * 768 + h * 192) * Tn;
    const float* kg = qg + (size_t)64 * Tn;
    const float* vg = qg + (size_t)128 * Tn;
    float* ap = g_attn + ((size_t)b * Cn + h * 64) * Tn;

    // ---- stage Q transposed [t][c], tf32-converted ----
    for (int i = tid; i < 2048; i += 256) {
        int c = i >> 5, tj = (i & 31) * 4;
        float4 v = *(const float4*)(qg + (size_t)c * Tn + t0 + tj);
        qp_s[(tj + 0) * QPS + c] = f2tf(v.x);
        qp_s[(tj + 1) * QPS + c] = f2tf(v.y);
        qp_s[(tj + 2) * QPS + c] = f2tf(v.z);
        qp_s[(tj + 3) * QPS + c] = f2tf(v.w);
    }
    __syncthreads();

    // ---- hoist Q fragments (whole KV loop) ----
    unsigned qf[8][4];
    #pragma unroll
    for (int kk = 0; kk < 8; kk++) {
        qf[kk][0] = __float_as_uint(qp_s[(tw + g    ) * QPS + kk * 8 + t4    ]);
        qf[kk][1] = __float_as_uint(qp_s[(tw + g + 8) * QPS + kk * 8 + t4    ]);
        qf[kk][2] = __float_as_uint(qp_s[(tw + g    ) * QPS + kk * 8 + t4 + 4]);
        qf[kk][3] = __float_as_uint(qp_s[(tw + g + 8) * QPS + kk * 8 + t4 + 4]);
    }

    float acc_o[8][4];
    #pragma unroll
    for (int n = 0; n < 8; n++)
        #pragma unroll
        for (int r = 0; r < 4; r++) acc_o[n][r] = 0.f;
    float m0 = -1e30f, m1 = -1e30f, l0 = 0.f, l1 = 0.f;

    for (int s0 = 0; s0 < Tn; s0 += 64) {
        __syncthreads();   // prior P·V reads done before overwriting K/V
        for (int i = tid; i < 1024; i += 256) {
            int c = i >> 4, sj = (i & 15) * 4;
            float4 kv = *(const float4*)(kg + (size_t)c * Tn + s0 + sj);
            k_s[c * KSS + sj + 0] = f2tf(kv.x);
            k_s[c * KSS + sj + 1] = f2tf(kv.y);
            k_s[c * KSS + sj + 2] = f2tf(kv.z);
            k_s[c * KSS + sj + 3] = f2tf(kv.w);
            float4 vv = *(const float4*)(vg + (size_t)c * Tn + s0 + sj);
            v_s[c * VSS + sj + 0] = f2tf(vv.x);
            v_s[c * VSS + sj + 1] = f2tf(vv.y);
            v_s[c * VSS + sj + 2] = f2tf(vv.z);
            v_s[c * VSS + sj + 3] = f2tf(vv.w);
        }
        __syncthreads();

        // ---- S = Q^T K ----
        float sacc[8][4];
        #pragma unroll
        for (int n = 0; n < 8; n++)
            #pragma unroll
            for (int r = 0; r < 4; r++) sacc[n][r] = 0.f;
        #pragma unroll
        for (int kk = 0; kk < 8; kk++) {
            #pragma unroll
            for (int n = 0; n < 8; n++) {
                unsigned bb0 = __float_as_uint(k_s[(kk * 8 + t4    ) * KSS + n * 8 + g]);
                unsigned bb1 = __float_as_uint(k_s[(kk * 8 + t4 + 4) * KSS + n * 8 + g]);
                mma_tf32(sacc[n], qf[kk][0], qf[kk][1], qf[kk][2], qf[kk][3], bb0, bb1);
            }
        }

        // ---- online softmax (row g -> regs 0,1 ; row g+8 -> regs 2,3) ----
        {
            float ml = -1e30f;
            #pragma unroll
            for (int n = 0; n < 8; n++) ml = fmaxf(ml, fmaxf(sacc[n][0], sacc[n][1]));
            ml = fmaxf(ml, __shfl_xor_sync(0xffffffffu, ml, 1));
            ml = fmaxf(ml, __shfl_xor_sync(0xffffffffu, ml, 2));
            float mn = fmaxf(m0, ml);
            float al = __expf(m0 - mn);
            float ps = 0.f;
            #pragma unroll
            for (int n = 0; n < 8; n++) {
                float p0 = __expf(sacc[n][0] - mn);
                float p1 = __expf(sacc[n][1] - mn);
                ps += p0 + p1;
                float2 pw = make_float2(f2tf(p0), f2tf(p1));
                *(float2*)&qp_s[(tw + g) * QPS + n * 8 + 2 * t4] = pw;
            }
            ps += __shfl_xor_sync(0xffffffffu, ps, 1);
            ps += __shfl_xor_sync(0xffffffffu, ps, 2);
            l0 = l0 * al + ps;  m0 = mn;
            #pragma unroll
            for (int n = 0; n < 8; n++) { acc_o[n][0] *= al; acc_o[n][1] *= al; }
        }
        {
            float ml = -1e30f;
            #pragma unroll
            for (int n = 0; n < 8; n++) ml = fmaxf(ml, fmaxf(sacc[n][2], sacc[n][3]));
            ml = fmaxf(ml, __shfl_xor_sync(0xffffffffu, ml, 1));
            ml = fmaxf(ml, __shfl_xor_sync(0xffffffffu, ml, 2));
            float mn = fmaxf(m1, ml);
            float al = __expf(m1 - mn);
            float ps = 0.f;
            #pragma unroll
            for (int n = 0; n < 8; n++) {
                float p0 = __expf(sacc[n][2] - mn);
                float p1 = __expf(sacc[n][3] - mn);
                ps += p0 + p1;
                float2 pw = make_float2(f2tf(p0), f2tf(p1));
                *(float2*)&qp_s[(tw + g + 8) * QPS + n * 8 + 2 * t4] = pw;
            }
            ps += __shfl_xor_sync(0xffffffffu, ps, 1);
            ps += __shfl_xor_sync(0xffffffffu, ps, 2);
            l1 = l1 * al + ps;  m1 = mn;
            #pragma unroll
            for (int n = 0; n < 8; n++) { acc_o[n][2] *= al; acc_o[n][3] *= al; }
        }
        __syncthreads();

        // ---- O += P V^T  (A = P[t][s], B[k=s][n=c] = v_s[c][s]) ----
        #pragma unroll
        for (int kk = 0; kk < 8; kk++) {
            unsigned a0 = __float_as_uint(qp_s[(tw + g    ) * QPS + kk * 8 + t4    ]);
            unsigned a1 = __float_as_uint(qp_s[(tw + g + 8) * QPS + kk * 8 + t4    ]);
            unsigned a2 = __float_as_uint(qp_s[(tw + g    ) * QPS + kk * 8 + t4 + 4]);
            unsigned a3 = __float_as_uint(qp_s[(tw + g + 8) * QPS + kk * 8 + t4 + 4]);
            #pragma unroll
            for (int n = 0; n < 8; n++) {
                unsigned bb0 = __float_as_uint(v_s[(n * 8 + g) * VSS + kk * 8 + t4    ]);
                unsigned bb1 = __float_as_uint(v_s[(n * 8 + g) * VSS + kk * 8 + t4 + 4]);
                mma_tf32(acc_o[n], a0, a1, a2, a3, bb0, bb1);
            }
        }
    }

    // ---- normalize, stage O as [t][c], coalesced writeback [c][t] ----
    __syncthreads();
    {
        float rl0 = 1.f / l0, rl1 = 1.f / l1;
        #pragma unroll
        for (int n = 0; n < 8; n++) {
            *(float2*)&qp_s[(tw + g    ) * QPS + n * 8 + 2 * t4] =
                make_float2(acc_o[n][0] * rl0, acc_o[n][1] * rl0);
            *(float2*)&qp_s[(tw + g + 8) * QPS + n * 8 + 2 * t4] =
                make_float2(acc_o[n][2] * rl1, acc_o[n][3] * rl1);
        }
    }
    __syncthreads();
    for (int i = tid; i < 2048; i += 256) {
        int c = i >> 5, tj = (i & 31) * 4;
        float4 o4;
        o4.x = qp_s[(tj + 0) * QPS + c];
        o4.y = qp_s[(tj + 1) * QPS + c];
        o4.z = qp_s[(tj + 2) * QPS + c];
        o4.w = qp_s[(tj + 3) * QPS + c];
        *(float4*)(ap + (size_t)c * Tn + t0 + tj) = o4;
    }
}

// ============================================================================
extern "C" void kernel_launch(void* const* d_in, const int* in_sizes, int n_in,
                              void* d_out, int out_size) {
    const float* x     = (const float*)d_in[0];
    const float* nw    = (const float*)d_in[1];
    const float* nb    = (const float*)d_in[2];
    const float* qkvw  = (const float*)d_in[3];
    const float* qkvb  = (const float*)d_in[4];
    const float* projw = (const float*)d_in[5];
    const float* projb = (const float*)d_in[6];
    float* out = (float*)d_out;

    const int ATTN_SMEM = (128 * QPS + 64 * KSS + 64 * VSS) * sizeof(float); // 72704
    cudaFuncSetAttribute(attn_kernel, cudaFuncAttributeMaxDynamicSharedMemorySize,
                         ATTN_SMEM);

    gn_kernel<<<Bn * 32, 256>>>(x, nw, nb);
    gemm_kernel<0><<<dim3(Tn / 64, 768 / 64, Bn), 256>>>(qkvw, qkvb, nullptr, nullptr);
    attn_kernel<<<dim3(Tn / 128, Bn * 4), 256, ATTN_SMEM>>>();
    gemm_kernel<1><<<dim3(Tn / 64, Cn / 64, Bn), 256>>>(projw, projb, x, out);
}

// round 3
// speedup vs baseline: 4.8166x; 1.1648x over previous
#include <cuda_runtime.h>
#include <math.h>

#define Tn 4096
#define Cn 256
#define Bn 2
#define SCALE_QK 0.35355339059327373f   // 64^-0.25

// ---- scratch (__device__ globals: allocation-free) ----
__device__ float g_xn  [Bn * Cn  * Tn];   // group-normed x          [B,256,T]
__device__ float g_qkv [Bn * 768 * Tn];   // qkv (q,k pre-scaled)    [B,768,T]
__device__ float g_attn[Bn * Cn  * Tn];   // attention output 'a'    [B,256,T]

// ---- tf32 helpers ----
__device__ __forceinline__ float f2tf(float x) {
    float r;
    asm("cvt.rna.tf32.f32 %0, %1;" : "=f"(r) : "f"(x));
    return r;
}
__device__ __forceinline__ void mma_tf32(float c[4],
                                         unsigned a0, unsigned a1, unsigned a2, unsigned a3,
                                         unsigned b0, unsigned b1) {
    asm volatile(
        "mma.sync.aligned.m16n8k8.row.col.f32.tf32.tf32.f32 "
        "{%0,%1,%2,%3},{%4,%5,%6,%7},{%8,%9},{%0,%1,%2,%3};"
        : "+f"(c[0]), "+f"(c[1]), "+f"(c[2]), "+f"(c[3])
        : "r"(a0), "r"(a1), "r"(a2), "r"(a3), "r"(b0), "r"(b1));
}

// ============================================================================
// 1) GroupNorm: one block per (batch, group). 32 groups, 8 ch/group, 32768 el.
// ============================================================================
__global__ __launch_bounds__(256) void gn_kernel(const float* __restrict__ x,
                                                 const float* __restrict__ w,
                                                 const float* __restrict__ bias) {
    const int b = blockIdx.x >> 5;
    const int g = blockIdx.x & 31;
    const size_t base = ((size_t)b * Cn + g * 8) * Tn;
    const float4* xp = (const float4*)(x + base);
    float4* op = (float4*)(g_xn + base);
    const int N4 = 8 * Tn / 4;  // 8192 float4s

    float s = 0.f, s2 = 0.f;
    for (int i = threadIdx.x; i < N4; i += 256) {
        float4 v = xp[i];
        s  += v.x + v.y + v.z + v.w;
        s2 += v.x*v.x + v.y*v.y + v.z*v.z + v.w*v.w;
    }
    __shared__ float rs[256], rs2[256];
    rs[threadIdx.x] = s; rs2[threadIdx.x] = s2;
    __syncthreads();
    for (int off = 128; off > 0; off >>= 1) {
        if (threadIdx.x < off) {
            rs [threadIdx.x] += rs [threadIdx.x + off];
            rs2[threadIdx.x] += rs2[threadIdx.x + off];
        }
        __syncthreads();
    }
    const float inv  = 1.f / (8.f * Tn);
    const float mean = rs[0] * inv;
    const float var  = rs2[0] * inv - mean * mean;
    const float rstd = rsqrtf(var + 1e-5f);

    for (int i = threadIdx.x; i < N4; i += 256) {
        int c = g * 8 + (i >> 10);
        float wc = w[c] * rstd;
        float bc = bias[c] - mean * wc;
        float4 v = xp[i];
        v.x = v.x * wc + bc; v.y = v.y * wc + bc;
        v.z = v.z * wc + bc; v.w = v.w * wc + bc;
        op[i] = v;
    }
}

// ============================================================================
// 2/4) Tensor-core GEMM (tf32): out[b,m,n] = sum_k A[m,k] * Bmat[b,k,n], K=256
//   MODE 0: A=qkv_w  Bmat=g_xn   out=g_qkv  (+bias, scale q/k rows)
//   MODE 1: A=proj_w Bmat=g_attn out=d_out  (+bias, +residual x)
// Block 64m x 128n, K-slice 32. 8 warps = 4(m) x 2(n); warp = m16 x n64.
// ============================================================================
template<int MODE>
__global__ __launch_bounds__(256, 2) void gemm_tc(const float* __restrict__ A,
                                                  const float* __restrict__ bias,
                                                  const float* __restrict__ resid,
                                                  float* __restrict__ out_param) {
    __shared__ float a_s[64][36];    // [m][k]  (stride 36: conflict-free frags)
    __shared__ float b_s[32][132];   // [k][n]  (stride 132)
    const int K = 256;
    const int tid  = threadIdx.x;
    const int wid  = tid >> 5;
    const int lane = tid & 31;
    const int g    = lane >> 2;
    const int t4   = lane & 3;
    const int wm   = (wid >> 1) * 16;   // 0,16,32,48
    const int wn   = (wid & 1) * 64;    // 0,64
    const int m0 = blockIdx.y * 64, n0 = blockIdx.x * 128;
    const float* __restrict__ Bmat = (MODE == 0) ? g_xn : g_attn;
    float* __restrict__ outp       = (MODE == 0) ? g_qkv : out_param;
    const size_t bb = (size_t)blockIdx.z * K * Tn;

    float acc[8][4] = {};
    for (int k0 = 0; k0 < K; k0 += 32) {
        // A tile 64m x 32k  (512 float4 loads, 2 per thread)
        #pragma unroll
        for (int r = 0; r < 2; r++) {
            int i = tid + r * 256;
            int m = i >> 3, kq = (i & 7) * 4;
            float4 v = *(const float4*)(A + (size_t)(m0 + m) * K + k0 + kq);
            a_s[m][kq+0] = f2tf(v.x); a_s[m][kq+1] = f2tf(v.y);
            a_s[m][kq+2] = f2tf(v.z); a_s[m][kq+3] = f2tf(v.w);
        }
        // B tile 32k x 128n (1024 float4 loads, 4 per thread)
        #pragma unroll
        for (int r = 0; r < 4; r++) {
            int i = tid + r * 256;
            int k = i >> 5, nq = (i & 31) * 4;
            float4 v = *(const float4*)(Bmat + bb + (size_t)(k0 + k) * Tn + n0 + nq);
            b_s[k][nq+0] = f2tf(v.x); b_s[k][nq+1] = f2tf(v.y);
            b_s[k][nq+2] = f2tf(v.z); b_s[k][nq+3] = f2tf(v.w);
        }
        __syncthreads();
        #pragma unroll
        for (int kk = 0; kk < 32; kk += 8) {
            unsigned a0 = __float_as_uint(a_s[wm + g    ][kk + t4    ]);
            unsigned a1 = __float_as_uint(a_s[wm + g + 8][kk + t4    ]);
            unsigned a2 = __float_as_uint(a_s[wm + g    ][kk + t4 + 4]);
            unsigned a3 = __float_as_uint(a_s[wm + g + 8][kk + t4 + 4]);
            #pragma unroll
            for (int n = 0; n < 8; n++) {
                unsigned b0 = __float_as_uint(b_s[kk + t4    ][wn + n * 8 + g]);
                unsigned b1 = __float_as_uint(b_s[kk + t4 + 4][wn + n * 8 + g]);
                mma_tf32(acc[n], a0, a1, a2, a3, b0, b1);
            }
        }
        __syncthreads();
    }

    // ---- epilogue ----
    const int mrow0 = m0 + wm + g;
    const int mrow1 = mrow0 + 8;
    float bi0 = bias[mrow0], bi1 = bias[mrow1];
    float sc0 = 1.f, sc1 = 1.f;
    if (MODE == 0) {
        if ((mrow0 % 192) < 128) sc0 = SCALE_QK;
        if ((mrow1 % 192) < 128) sc1 = SCALE_QK;
    }
    const int Mout = (MODE == 0) ? 768 : Cn;
    const size_t o0 = ((size_t)blockIdx.z * Mout + mrow0) * Tn + n0 + wn;
    const size_t o1 = ((size_t)blockIdx.z * Mout + mrow1) * Tn + n0 + wn;
    const size_t r0 = ((size_t)blockIdx.z * Cn + mrow0) * Tn + n0 + wn;
    const size_t r1 = ((size_t)blockIdx.z * Cn + mrow1) * Tn + n0 + wn;
    #pragma unroll
    for (int n = 0; n < 8; n++) {
        int col = n * 8 + 2 * t4;
        float v00 = (acc[n][0] + bi0) * sc0;
        float v01 = (acc[n][1] + bi0) * sc0;
        float v10 = (acc[n][2] + bi1) * sc1;
        float v11 = (acc[n][3] + bi1) * sc1;
        if (MODE == 1) {
            v00 += resid[r0 + col]; v01 += resid[r0 + col + 1];
            v10 += resid[r1 + col]; v11 += resid[r1 + col + 1];
        }
        *(float2*)(outp + o0 + col) = make_float2(v00, v01);
        *(float2*)(outp + o1 + col) = make_float2(v10, v11);
    }
}

// ============================================================================
// 3) Flash attention on tensor cores (tf32 mma.sync) — unchanged from R2.
// ============================================================================
#define QPS 68
#define KSS 72
#define VSS 76

__global__ __launch_bounds__(256, 2) void attn_kernel() {
    extern __shared__ float sm[];
    float* qp_s = sm;                    // [128][QPS]  Q-stage / P / O-stage
    float* k_s  = sm + 128 * QPS;        // [64][KSS]
    float* v_s  = k_s + 64 * KSS;        // [64][VSS]

    const int tid  = threadIdx.x;
    const int wid  = tid >> 5;
    const int lane = tid & 31;
    const int g    = lane >> 2;
    const int t4   = lane & 3;
    const int tw   = wid * 16;

    const int t0 = blockIdx.x * 128;
    const int bh = blockIdx.y;
    const int b  = bh >> 2, h = bh & 3;
    const float* qg = g_qkv + ((size_t)b * 768 + h * 192) * Tn;
    const float* kg = qg + (size_t)64 * Tn;
    const float* vg = qg + (size_t)128 * Tn;
    float* ap = g_attn + ((size_t)b * Cn + h * 64) * Tn;

    for (int i = tid; i < 2048; i += 256) {
        int c = i >> 5, tj = (i & 31) * 4;
        float4 v = *(const float4*)(qg + (size_t)c * Tn + t0 + tj);
        qp_s[(tj + 0) * QPS + c] = f2tf(v.x);
        qp_s[(tj + 1) * QPS + c] = f2tf(v.y);
        qp_s[(tj + 2) * QPS + c] = f2tf(v.z);
        qp_s[(tj + 3) * QPS + c] = f2tf(v.w);
    }
    __syncthreads();

    unsigned qf[8][4];
    #pragma unroll
    for (int kk = 0; kk < 8; kk++) {
        qf[kk][0] = __float_as_uint(qp_s[(tw + g    ) * QPS + kk * 8 + t4    ]);
        qf[kk][1] = __float_as_uint(qp_s[(tw + g + 8) * QPS + kk * 8 + t4    ]);
        qf[kk][2] = __float_as_uint(qp_s[(tw + g    ) * QPS + kk * 8 + t4 + 4]);
        qf[kk][3] = __float_as_uint(qp_s[(tw + g + 8) * QPS + kk * 8 + t4 + 4]);
    }

    float acc_o[8][4];
    #pragma unroll
    for (int n = 0; n < 8; n++)
        #pragma unroll
        for (int r = 0; r < 4; r++) acc_o[n][r] = 0.f;
    float m0 = -1e30f, m1 = -1e30f, l0 = 0.f, l1 = 0.f;

    for (int s0 = 0; s0 < Tn; s0 += 64) {
        __syncthreads();
        for (int i = tid; i < 1024; i += 256) {
            int c = i >> 4, sj = (i & 15) * 4;
            float4 kv = *(const float4*)(kg + (size_t)c * Tn + s0 + sj);
            k_s[c * KSS + sj + 0] = f2tf(kv.x);
            k_s[c * KSS + sj + 1] = f2tf(kv.y);
            k_s[c * KSS + sj + 2] = f2tf(kv.z);
            k_s[c * KSS + sj + 3] = f2tf(kv.w);
            float4 vv = *(const float4*)(vg + (size_t)c * Tn + s0 + sj);
            v_s[c * VSS + sj + 0] = f2tf(vv.x);
            v_s[c * VSS + sj + 1] = f2tf(vv.y);
            v_s[c * VSS + sj + 2] = f2tf(vv.z);
            v_s[c * VSS + sj + 3] = f2tf(vv.w);
        }
        __syncthreads();

        float sacc[8][4];
        #pragma unroll
        for (int n = 0; n < 8; n++)
            #pragma unroll
            for (int r = 0; r < 4; r++) sacc[n][r] = 0.f;
        #pragma unroll
        for (int kk = 0; kk < 8; kk++) {
            #pragma unroll
            for (int n = 0; n < 8; n++) {
                unsigned bb0 = __float_as_uint(k_s[(kk * 8 + t4    ) * KSS + n * 8 + g]);
                unsigned bb1 = __float_as_uint(k_s[(kk * 8 + t4 + 4) * KSS + n * 8 + g]);
                mma_tf32(sacc[n], qf[kk][0], qf[kk][1], qf[kk][2], qf[kk][3], bb0, bb1);
            }
        }

        {
            float ml = -1e30f;
            #pragma unroll
            for (int n = 0; n < 8; n++) ml = fmaxf(ml, fmaxf(sacc[n][0], sacc[n][1]));
            ml = fmaxf(ml, __shfl_xor_sync(0xffffffffu, ml, 1));
            ml = fmaxf(ml, __shfl_xor_sync(0xffffffffu, ml, 2));
            float mn = fmaxf(m0, ml);
            float al = __expf(m0 - mn);
            float ps = 0.f;
            #pragma unroll
            for (int n = 0; n < 8; n++) {
                float p0 = __expf(sacc[n][0] - mn);
                float p1 = __expf(sacc[n][1] - mn);
                ps += p0 + p1;
                float2 pw = make_float2(f2tf(p0), f2tf(p1));
                *(float2*)&qp_s[(tw + g) * QPS + n * 8 + 2 * t4] = pw;
            }
            ps += __shfl_xor_sync(0xffffffffu, ps, 1);
            ps += __shfl_xor_sync(0xffffffffu, ps, 2);
            l0 = l0 * al + ps;  m0 = mn;
            #pragma unroll
            for (int n = 0; n < 8; n++) { acc_o[n][0] *= al; acc_o[n][1] *= al; }
        }
        {
            float ml = -1e30f;
            #pragma unroll
            for (int n = 0; n < 8; n++) ml = fmaxf(ml, fmaxf(sacc[n][2], sacc[n][3]));
            ml = fmaxf(ml, __shfl_xor_sync(0xffffffffu, ml, 1));
            ml = fmaxf(ml, __shfl_xor_sync(0xffffffffu, ml, 2));
            float mn = fmaxf(m1, ml);
            float al = __expf(m1 - mn);
            float ps = 0.f;
            #pragma unroll
            for (int n = 0; n < 8; n++) {
                float p0 = __expf(sacc[n][2] - mn);
                float p1 = __expf(sacc[n][3] - mn);
                ps += p0 + p1;
                float2 pw = make_float2(f2tf(p0), f2tf(p1));
                *(float2*)&qp_s[(tw + g + 8) * QPS + n * 8 + 2 * t4] = pw;
            }
            ps += __shfl_xor_sync(0xffffffffu, ps, 1);
            ps += __shfl_xor_sync(0xffffffffu, ps, 2);
            l1 = l1 * al + ps;  m1 = mn;
            #pragma unroll
            for (int n = 0; n < 8; n++) { acc_o[n][2] *= al; acc_o[n][3] *= al; }
        }
        __syncthreads();

        #pragma unroll
        for (int kk = 0; kk < 8; kk++) {
            unsigned a0 = __float_as_uint(qp_s[(tw + g    ) * QPS + kk * 8 + t4    ]);
            unsigned a1 = __float_as_uint(qp_s[(tw + g + 8) * QPS + kk * 8 + t4    ]);
            unsigned a2 = __float_as_uint(qp_s[(tw + g    ) * QPS + kk * 8 + t4 + 4]);
            unsigned a3 = __float_as_uint(qp_s[(tw + g + 8) * QPS + kk * 8 + t4 + 4]);
            #pragma unroll
            for (int n = 0; n < 8; n++) {
                unsigned bb0 = __float_as_uint(v_s[(n * 8 + g) * VSS + kk * 8 + t4    ]);
                unsigned bb1 = __float_as_uint(v_s[(n * 8 + g) * VSS + kk * 8 + t4 + 4]);
                mma_tf32(acc_o[n], a0, a1, a2, a3, bb0, bb1);
            }
        }
    }

    __syncthreads();
    {
        float rl0 = 1.f / l0, rl1 = 1.f / l1;
        #pragma unroll
        for (int n = 0; n < 8; n++) {
            *(float2*)&qp_s[(tw + g    ) * QPS + n * 8 + 2 * t4] =
                make_float2(acc_o[n][0] * rl0, acc_o[n][1] * rl0);
            *(float2*)&qp_s[(tw + g + 8) * QPS + n * 8 + 2 * t4] =
                make_float2(acc_o[n][2] * rl1, acc_o[n][3] * rl1);
        }
    }
    __syncthreads();
    for (int i = tid; i < 2048; i += 256) {
        int c = i >> 5, tj = (i & 31) * 4;
        float4 o4;
        o4.x = qp_s[(tj + 0) * QPS + c];
        o4.y = qp_s[(tj + 1) * QPS + c];
        o4.z = qp_s[(tj + 2) * QPS + c];
        o4.w = qp_s[(tj + 3) * QPS + c];
        *(float4*)(ap + (size_t)c * Tn + t0 + tj) = o4;
    }
}

// ============================================================================
extern "C" void kernel_launch(void* const* d_in, const int* in_sizes, int n_in,
                              void* d_out, int out_size) {
    const float* x     = (const float*)d_in[0];
    const float* nw    = (const float*)d_in[1];
    const float* nb    = (const float*)d_in[2];
    const float* qkvw  = (const float*)d_in[3];
    const float* qkvb  = (const float*)d_in[4];
    const float* projw = (const float*)d_in[5];
    const float* projb = (const float*)d_in[6];
    float* out = (float*)d_out;

    const int ATTN_SMEM = (128 * QPS + 64 * KSS + 64 * VSS) * sizeof(float); // 72704
    cudaFuncSetAttribute(attn_kernel, cudaFuncAttributeMaxDynamicSharedMemorySize,
                         ATTN_SMEM);

    gn_kernel<<<Bn * 32, 256>>>(x, nw, nb);
    gemm_tc<0><<<dim3(Tn / 128, 768 / 64, Bn), 256>>>(qkvw, qkvb, nullptr, nullptr);
    attn_kernel<<<dim3(Tn / 128, Bn * 4), 256, ATTN_SMEM>>>();
    gemm_tc<1><<<dim3(Tn / 128, Cn / 64, Bn), 256>>>(projw, projb, x, out);
}

// round 4
// speedup vs baseline: 5.7721x; 1.1984x over previous
#include <cuda_runtime.h>
#include <cuda_bf16.h>
#include <math.h>

#define Tn 4096
#define Cn 256
#define Bn 2
#define SCALE_QK 0.35355339059327373f   // 64^-0.25

// ---- scratch (__device__ globals: allocation-free) ----
__device__ float g_xn  [Bn * Cn  * Tn];     // group-normed x        [B,256,T]
__device__ float g_qkv [Bn * 768 * Tn];     // v lives here          [B,768,T]
__device__ float g_qT  [Bn * 4 * Tn * 64];  // q transposed [b,h,t,c] (scaled)
__device__ float g_kT  [Bn * 4 * Tn * 64];  // k transposed [b,h,s,c] (scaled)
__device__ float g_attn[Bn * Cn  * Tn];     // attention output 'a'  [B,256,T]

// ---- helpers ----
__device__ __forceinline__ float f2tf(float x) {
    float r;
    asm("cvt.rna.tf32.f32 %0, %1;" : "=f"(r) : "f"(x));
    return r;
}
__device__ __forceinline__ unsigned pack_bf2(float a, float b) {
    __nv_bfloat162 h = __floats2bfloat162_rn(a, b);
    return *(unsigned*)&h;
}
__device__ __forceinline__ void mma_tf32(float c[4],
                                         unsigned a0, unsigned a1, unsigned a2, unsigned a3,
                                         unsigned b0, unsigned b1) {
    asm volatile(
        "mma.sync.aligned.m16n8k8.row.col.f32.tf32.tf32.f32 "
        "{%0,%1,%2,%3},{%4,%5,%6,%7},{%8,%9},{%0,%1,%2,%3};"
        : "+f"(c[0]), "+f"(c[1]), "+f"(c[2]), "+f"(c[3])
        : "r"(a0), "r"(a1), "r"(a2), "r"(a3), "r"(b0), "r"(b1));
}
__device__ __forceinline__ void mma_bf16(float c[4],
                                         unsigned a0, unsigned a1, unsigned a2, unsigned a3,
                                         unsigned b0, unsigned b1) {
    asm volatile(
        "mma.sync.aligned.m16n8k16.row.col.f32.bf16.bf16.f32 "
        "{%0,%1,%2,%3},{%4,%5,%6,%7},{%8,%9},{%0,%1,%2,%3};"
        : "+f"(c[0]), "+f"(c[1]), "+f"(c[2]), "+f"(c[3])
        : "r"(a0), "r"(a1), "r"(a2), "r"(a3), "r"(b0), "r"(b1));
}

// ============================================================================
// 1) GroupNorm (unchanged)
// ============================================================================
__global__ __launch_bounds__(256) void gn_kernel(const float* __restrict__ x,
                                                 const float* __restrict__ w,
                                                 const float* __restrict__ bias) {
    const int b = blockIdx.x >> 5;
    const int g = blockIdx.x & 31;
    const size_t base = ((size_t)b * Cn + g * 8) * Tn;
    const float4* xp = (const float4*)(x + base);
    float4* op = (float4*)(g_xn + base);
    const int N4 = 8 * Tn / 4;

    float s = 0.f, s2 = 0.f;
    for (int i = threadIdx.x; i < N4; i += 256) {
        float4 v = xp[i];
        s  += v.x + v.y + v.z + v.w;
        s2 += v.x*v.x + v.y*v.y + v.z*v.z + v.w*v.w;
    }
    __shared__ float rs[256], rs2[256];
    rs[threadIdx.x] = s; rs2[threadIdx.x] = s2;
    __syncthreads();
    for (int off = 128; off > 0; off >>= 1) {
        if (threadIdx.x < off) {
            rs [threadIdx.x] += rs [threadIdx.x + off];
            rs2[threadIdx.x] += rs2[threadIdx.x + off];
        }
        __syncthreads();
    }
    const float inv  = 1.f / (8.f * Tn);
    const float mean = rs[0] * inv;
    const float var  = rs2[0] * inv - mean * mean;
    const float rstd = rsqrtf(var + 1e-5f);

    for (int i = threadIdx.x; i < N4; i += 256) {
        int c = g * 8 + (i >> 10);
        float wc = w[c] * rstd;
        float bc = bias[c] - mean * wc;
        float4 v = xp[i];
        v.x = v.x * wc + bc; v.y = v.y * wc + bc;
        v.z = v.z * wc + bc; v.w = v.w * wc + bc;
        op[i] = v;
    }
}

// ============================================================================
// 2/4) Tensor-core GEMM (tf32), K=256. Block 64m x 128n, 8 warps (4m x 2n).
//   MODE 0: qkv. q/k class blocks scatter-write TRANSPOSED to g_qT/g_kT
//           (pre-scaled); v class writes to g_qkv as [c][t].
//   MODE 1: proj + bias + residual -> d_out.
// ============================================================================
template<int MODE>
__global__ __launch_bounds__(256, 2) void gemm_tc(const float* __restrict__ A,
                                                  const float* __restrict__ bias,
                                                  const float* __restrict__ resid,
                                                  float* __restrict__ out_param) {
    __shared__ float a_s[64][36];
    __shared__ float b_s[32][132];
    const int K = 256;
    const int tid  = threadIdx.x;
    const int wid  = tid >> 5;
    const int lane = tid & 31;
    const int g    = lane >> 2;
    const int t4   = lane & 3;
    const int wm   = (wid >> 1) * 16;
    const int wn   = (wid & 1) * 64;
    const int m0 = blockIdx.y * 64, n0 = blockIdx.x * 128;
    const float* __restrict__ Bmat = (MODE == 0) ? g_xn : g_attn;
    const size_t bb = (size_t)blockIdx.z * K * Tn;

    float acc[8][4] = {};
    for (int k0 = 0; k0 < K; k0 += 32) {
        #pragma unroll
        for (int r = 0; r < 2; r++) {
            int i = tid + r * 256;
            int m = i >> 3, kq = (i & 7) * 4;
            float4 v = *(const float4*)(A + (size_t)(m0 + m) * K + k0 + kq);
            a_s[m][kq+0] = f2tf(v.x); a_s[m][kq+1] = f2tf(v.y);
            a_s[m][kq+2] = f2tf(v.z); a_s[m][kq+3] = f2tf(v.w);
        }
        #pragma unroll
        for (int r = 0; r < 4; r++) {
            int i = tid + r * 256;
            int k = i >> 5, nq = (i & 31) * 4;
            float4 v = *(const float4*)(Bmat + bb + (size_t)(k0 + k) * Tn + n0 + nq);
            b_s[k][nq+0] = f2tf(v.x); b_s[k][nq+1] = f2tf(v.y);
            b_s[k][nq+2] = f2tf(v.z); b_s[k][nq+3] = f2tf(v.w);
        }
        __syncthreads();
        #pragma unroll
        for (int kk = 0; kk < 32; kk += 8) {
            unsigned a0 = __float_as_uint(a_s[wm + g    ][kk + t4    ]);
            unsigned a1 = __float_as_uint(a_s[wm + g + 8][kk + t4    ]);
            unsigned a2 = __float_as_uint(a_s[wm + g    ][kk + t4 + 4]);
            unsigned a3 = __float_as_uint(a_s[wm + g + 8][kk + t4 + 4]);
            #pragma unroll
            for (int n = 0; n < 8; n++) {
                unsigned b0 = __float_as_uint(b_s[kk + t4    ][wn + n * 8 + g]);
                unsigned b1 = __float_as_uint(b_s[kk + t4 + 4][wn + n * 8 + g]);
                mma_tf32(acc[n], a0, a1, a2, a3, b0, b1);
            }
        }
        __syncthreads();
    }

    // ---- epilogue ----
    const int mrow0 = m0 + wm + g;
    const int mrow1 = mrow0 + 8;
    float bi0 = bias[mrow0], bi1 = bias[mrow1];
    const int cls = (MODE == 0) ? ((m0 >> 6) % 3) : 2;   // 0=q,1=k,2=v/other
    float sc = (MODE == 0 && cls != 2) ? SCALE_QK : 1.f;

    if (MODE == 0 && cls != 2) {
        // transposed scatter: dst[b,h][t][c]
        const int hh  = mrow0 / 192;
        const int of0 = mrow0 % 192 - (cls == 1 ? 64 : 0);
        const int of1 = of0 + 8;
        float* dst = (cls == 0 ? g_qT : g_kT)
                   + ((size_t)(blockIdx.z * 4 + hh) * Tn + n0 + wn) * 64;
        #pragma unroll
        for (int n = 0; n < 8; n++) {
            int col = n * 8 + 2 * t4;
            dst[(size_t)(col    ) * 64 + of0] = (acc[n][0] + bi0) * sc;
            dst[(size_t)(col + 1) * 64 + of0] = (acc[n][1] + bi0) * sc;
            dst[(size_t)(col    ) * 64 + of1] = (acc[n][2] + bi1) * sc;
            dst[(size_t)(col + 1) * 64 + of1] = (acc[n][3] + bi1) * sc;
        }
    } else {
        float* __restrict__ outp = (MODE == 0) ? g_qkv : out_param;
        const int Mout = (MODE == 0) ? 768 : Cn;
        const size_t o0 = ((size_t)blockIdx.z * Mout + mrow0) * Tn + n0 + wn;
        const size_t o1 = ((size_t)blockIdx.z * Mout + mrow1) * Tn + n0 + wn;
        const size_t r0 = ((size_t)blockIdx.z * Cn + mrow0) * Tn + n0 + wn;
        const size_t r1 = ((size_t)blockIdx.z * Cn + mrow1) * Tn + n0 + wn;
        #pragma unroll
        for (int n = 0; n < 8; n++) {
            int col = n * 8 + 2 * t4;
            float v00 = acc[n][0] + bi0;
            float v01 = acc[n][1] + bi0;
            float v10 = acc[n][2] + bi1;
            float v11 = acc[n][3] + bi1;
            if (MODE == 1) {
                v00 += resid[r0 + col]; v01 += resid[r0 + col + 1];
                v10 += resid[r1 + col]; v11 += resid[r1 + col + 1];
            }
            *(float2*)(outp + o0 + col) = make_float2(v00, v01);
            *(float2*)(outp + o1 + col) = make_float2(v10, v11);
        }
    }
}

// ============================================================================
// 3) Flash attention, bf16 m16n8k16, fp32 softmax/accum.
//    smem (u32 stride 36 everywhere -> bank pattern 4g+t4, conflict-free):
//      union buf: Q-stage/P [128][36] u32  |  O-stage [128][68] f32
//      k_s [64][36] u32 ([s][c/2]),  v_s [64][36] u32 ([c][s/2])
// ============================================================================
#define OPS 68
#define UNION_F (128 * OPS)          // 8704 floats
#define KV_F    (64 * 36)            // 2304 floats (as u32 region)

__global__ __launch_bounds__(256, 2) void attn_kernel() {
    extern __shared__ float sm[];
    unsigned* qp_u = (unsigned*)sm;               // Q-stage / P  [128][36]
    float*    o_s  = sm;                          // O-stage      [128][68]
    unsigned* k_u  = (unsigned*)(sm + UNION_F);   // [64][36]
    unsigned* v_u  = (unsigned*)(sm + UNION_F + KV_F);

    const int tid  = threadIdx.x;
    const int wid  = tid >> 5;
    const int lane = tid & 31;
    const int g    = lane >> 2;
    const int t4   = lane & 3;
    const int tw   = wid * 16;

    const int t0 = blockIdx.x * 128;
    const int bh = blockIdx.y;                    // b*4 + h
    const int b  = bh >> 2, h = bh & 3;
    const float* qT = g_qT + ((size_t)bh * Tn + t0) * 64;
    const float* kT = g_kT + (size_t)bh * Tn * 64;
    const float* vg = g_qkv + ((size_t)b * 768 + h * 192 + 128) * Tn;
    float* ap = g_attn + ((size_t)b * Cn + h * 64) * Tn;

    // ---- stage Q [t][c/2] packed bf16x2 ----
    for (int i = tid; i < 2048; i += 256) {
        int t = i >> 4, cq = (i & 15) * 4;
        float4 v = *(const float4*)(qT + (size_t)t * 64 + cq);
        *(uint2*)&qp_u[t * 36 + cq / 2] =
            make_uint2(pack_bf2(v.x, v.y), pack_bf2(v.z, v.w));
    }
    __syncthreads();

    // ---- hoist Q fragments ----
    unsigned qf[4][4];
    #pragma unroll
    for (int kk = 0; kk < 4; kk++) {
        qf[kk][0] = qp_u[(tw + g    ) * 36 + kk * 8 + t4    ];
        qf[kk][1] = qp_u[(tw + g + 8) * 36 + kk * 8 + t4    ];
        qf[kk][2] = qp_u[(tw + g    ) * 36 + kk * 8 + t4 + 4];
        qf[kk][3] = qp_u[(tw + g + 8) * 36 + kk * 8 + t4 + 4];
    }

    float acc_o[8][4];
    #pragma unroll
    for (int n = 0; n < 8; n++)
        #pragma unroll
        for (int r = 0; r < 4; r++) acc_o[n][r] = 0.f;
    float m0 = -1e30f, m1 = -1e30f, l0 = 0.f, l1 = 0.f;

    for (int s0 = 0; s0 < Tn; s0 += 64) {
        __syncthreads();
        // K: [s][c] rows contiguous -> [s][c/2]
        for (int i = tid; i < 1024; i += 256) {
            int t = i >> 4, cq = (i & 15) * 4;
            float4 v = *(const float4*)(kT + (size_t)(s0 + t) * 64 + cq);
            *(uint2*)&k_u[t * 36 + cq / 2] =
                make_uint2(pack_bf2(v.x, v.y), pack_bf2(v.z, v.w));
        }
        // V: [c][s] -> [c][s/2]
        for (int i = tid; i < 1024; i += 256) {
            int c = i >> 4, sq = (i & 15) * 4;
            float4 v = *(const float4*)(vg + (size_t)c * Tn + s0 + sq);
            *(uint2*)&v_u[c * 36 + sq / 2] =
                make_uint2(pack_bf2(v.x, v.y), pack_bf2(v.z, v.w));
        }
        __syncthreads();

        // ---- S = Q K^T ----
        float sacc[8][4];
        #pragma unroll
        for (int n = 0; n < 8; n++)
            #pragma unroll
            for (int r = 0; r < 4; r++) sacc[n][r] = 0.f;
        #pragma unroll
        for (int kk = 0; kk < 4; kk++) {
            #pragma unroll
            for (int n = 0; n < 8; n++) {
                unsigned b0 = k_u[(n * 8 + g) * 36 + kk * 8 + t4    ];
                unsigned b1 = k_u[(n * 8 + g) * 36 + kk * 8 + t4 + 4];
                mma_bf16(sacc[n], qf[kk][0], qf[kk][1], qf[kk][2], qf[kk][3], b0, b1);
            }
        }

        // ---- online softmax ----
        {
            float ml = -1e30f;
            #pragma unroll
            for (int n = 0; n < 8; n++) ml = fmaxf(ml, fmaxf(sacc[n][0], sacc[n][1]));
            ml = fmaxf(ml, __shfl_xor_sync(0xffffffffu, ml, 1));
            ml = fmaxf(ml, __shfl_xor_sync(0xffffffffu, ml, 2));
            float mn = fmaxf(m0, ml);
            float al = __expf(m0 - mn);
            float ps = 0.f;
            #pragma unroll
            for (int n = 0; n < 8; n++) {
                float p0 = __expf(sacc[n][0] - mn);
                float p1 = __expf(sacc[n][1] - mn);
                ps += p0 + p1;
                qp_u[(tw + g) * 36 + n * 4 + t4] = pack_bf2(p0, p1);
            }
            ps += __shfl_xor_sync(0xffffffffu, ps, 1);
            ps += __shfl_xor_sync(0xffffffffu, ps, 2);
            l0 = l0 * al + ps;  m0 = mn;
            #pragma unroll
            for (int n = 0; n < 8; n++) { acc_o[n][0] *= al; acc_o[n][1] *= al; }
        }
        {
            float ml = -1e30f;
            #pragma unroll
            for (int n = 0; n < 8; n++) ml = fmaxf(ml, fmaxf(sacc[n][2], sacc[n][3]));
            ml = fmaxf(ml, __shfl_xor_sync(0xffffffffu, ml, 1));
            ml = fmaxf(ml, __shfl_xor_sync(0xffffffffu, ml, 2));
            float mn = fmaxf(m1, ml);
            float al = __expf(m1 - mn);
            float ps = 0.f;
            #pragma unroll
            for (int n = 0; n < 8; n++) {
                float p0 = __expf(sacc[n][2] - mn);
                float p1 = __expf(sacc[n][3] - mn);
                ps += p0 + p1;
                qp_u[(tw + g + 8) * 36 + n * 4 + t4] = pack_bf2(p0, p1);
            }
            ps += __shfl_xor_sync(0xffffffffu, ps, 1);
            ps += __shfl_xor_sync(0xffffffffu, ps, 2);
            l1 = l1 * al + ps;  m1 = mn;
            #pragma unroll
            for (int n = 0; n < 8; n++) { acc_o[n][2] *= al; acc_o[n][3] *= al; }
        }
        __syncthreads();

        // ---- O += P V^T ----
        #pragma unroll
        for (int kk = 0; kk < 4; kk++) {
            unsigned a0 = qp_u[(tw + g    ) * 36 + kk * 8 + t4    ];
            unsigned a1 = qp_u[(tw + g + 8) * 36 + kk * 8 + t4    ];
            unsigned a2 = qp_u[(tw + g    ) * 36 + kk * 8 + t4 + 4];
            unsigned a3 = qp_u[(tw + g + 8) * 36 + kk * 8 + t4 + 4];
            #pragma unroll
            for (int n = 0; n < 8; n++) {
                unsigned b0 = v_u[(n * 8 + g) * 36 + kk * 8 + t4    ];
                unsigned b1 = v_u[(n * 8 + g) * 36 + kk * 8 + t4 + 4];
                mma_bf16(acc_o[n], a0, a1, a2, a3, b0, b1);
            }
        }
    }

    // ---- normalize, stage O [t][c] fp32, coalesced writeback [c][t] ----
    __syncthreads();
    {
        float rl0 = 1.f / l0, rl1 = 1.f / l1;
        #pragma unroll
        for (int n = 0; n < 8; n++) {
            *(float2*)&o_s[(tw + g    ) * OPS + n * 8 + 2 * t4] =
                make_float2(acc_o[n][0] * rl0, acc_o[n][1] * rl0);
            *(float2*)&o_s[(tw + g + 8) * OPS + n * 8 + 2 * t4] =
                make_float2(acc_o[n][2] * rl1, acc_o[n][3] * rl1);
        }
    }
    __syncthreads();
    for (int i = tid; i < 2048; i += 256) {
        int c = i >> 5, tj = (i & 31) * 4;
        float4 o4;
        o4.x = o_s[(tj + 0) * OPS + c];
        o4.y = o_s[(tj + 1) * OPS + c];
        o4.z = o_s[(tj + 2) * OPS + c];
        o4.w = o_s[(tj + 3) * OPS + c];
        *(float4*)(ap + (size_t)c * Tn + t0 + tj) = o4;
    }
}

// ============================================================================
extern "C" void kernel_launch(void* const* d_in, const int* in_sizes, int n_in,
                              void* d_out, int out_size) {
    const float* x     = (const float*)d_in[0];
    const float* nw    = (const float*)d_in[1];
    const float* nb    = (const float*)d_in[2];
    const float* qkvw  = (const float*)d_in[3];
    const float* qkvb  = (const float*)d_in[4];
    const float* projw = (const float*)d_in[5];
    const float* projb = (const float*)d_in[6];
    float* out = (float*)d_out;

    const int ATTN_SMEM = (UNION_F + 2 * KV_F) * sizeof(float);  // 53248 B
    cudaFuncSetAttribute(attn_kernel, cudaFuncAttributeMaxDynamicSharedMemorySize,
                         ATTN_SMEM);

    gn_kernel<<<Bn * 32, 256>>>(x, nw, nb);
    gemm_tc<0><<<dim3(Tn / 128, 768 / 64, Bn), 256>>>(qkvw, qkvb, nullptr, nullptr);
    attn_kernel<<<dim3(Tn / 128, Bn * 4), 256, ATTN_SMEM>>>();
    gemm_tc<1><<<dim3(Tn / 128, Cn / 64, Bn), 256>>>(projw, projb, x, out);
}

// round 6
// speedup vs baseline: 9.5702x; 1.6580x over previous
#include <cuda_runtime.h>
#include <cuda_bf16.h>
#include <cstdint>
#include <math.h>

#define Tn 4096
#define Cn 256
#define Bn 2
#define SCALE_QK 0.35355339059327373f   // 64^-0.25

// ---- scratch (__device__ globals: allocation-free) ----
__device__ float         g_xn  [Bn * Cn * Tn];      // group-normed x [B,256,T]
__device__ float         g_attn[Bn * Cn * Tn];      // attention out  [B,256,T]
__device__ __nv_bfloat16 g_qb  [Bn * 4 * Tn * 64];  // q [bh][t][c] bf16 scaled
__device__ __nv_bfloat16 g_kb  [Bn * 4 * Tn * 64];  // k [bh][s][c] bf16 scaled
__device__ __nv_bfloat16 g_vb  [Bn * 4 * 64 * Tn];  // v [bh][c][t] bf16

// ---- helpers ----
__device__ __forceinline__ float f2tf(float x) {
    float r; asm("cvt.rna.tf32.f32 %0, %1;" : "=f"(r) : "f"(x)); return r;
}
__device__ __forceinline__ unsigned pack_bf2(float a, float b) {
    __nv_bfloat162 h = __floats2bfloat162_rn(a, b);
    return *(unsigned*)&h;
}
__device__ __forceinline__ void mma_tf32(float c[4],
                                         unsigned a0, unsigned a1, unsigned a2, unsigned a3,
                                         unsigned b0, unsigned b1) {
    asm volatile(
        "mma.sync.aligned.m16n8k8.row.col.f32.tf32.tf32.f32 "
        "{%0,%1,%2,%3},{%4,%5,%6,%7},{%8,%9},{%0,%1,%2,%3};"
        : "+f"(c[0]), "+f"(c[1]), "+f"(c[2]), "+f"(c[3])
        : "r"(a0), "r"(a1), "r"(a2), "r"(a3), "r"(b0), "r"(b1));
}
__device__ __forceinline__ void mma_bf16(float c[4],
                                         unsigned a0, unsigned a1, unsigned a2, unsigned a3,
                                         unsigned b0, unsigned b1) {
    asm volatile(
        "mma.sync.aligned.m16n8k16.row.col.f32.bf16.bf16.f32 "
        "{%0,%1,%2,%3},{%4,%5,%6,%7},{%8,%9},{%0,%1,%2,%3};"
        : "+f"(c[0]), "+f"(c[1]), "+f"(c[2]), "+f"(c[3])
        : "r"(a0), "r"(a1), "r"(a2), "r"(a3), "r"(b0), "r"(b1));
}

// ============================================================================
// 1) GroupNorm (unchanged)
// ============================================================================
__global__ __launch_bounds__(256) void gn_kernel(const float* __restrict__ x,
                                                 const float* __restrict__ w,
                                                 const float* __restrict__ bias) {
    const int b = blockIdx.x >> 5;
    const int g = blockIdx.x & 31;
    const size_t base = ((size_t)b * Cn + g * 8) * Tn;
    const float4* xp = (const float4*)(x + base);
    float4* op = (float4*)(g_xn + base);
    const int N4 = 8 * Tn / 4;

    float s = 0.f, s2 = 0.f;
    for (int i = threadIdx.x; i < N4; i += 256) {
        float4 v = xp[i];
        s  += v.x + v.y + v.z + v.w;
        s2 += v.x*v.x + v.y*v.y + v.z*v.z + v.w*v.w;
    }
    __shared__ float rs[256], rs2[256];
    rs[threadIdx.x] = s; rs2[threadIdx.x] = s2;
    __syncthreads();
    for (int off = 128; off > 0; off >>= 1) {
        if (threadIdx.x < off) {
            rs [threadIdx.x] += rs [threadIdx.x + off];
            rs2[threadIdx.x] += rs2[threadIdx.x + off];
        }
        __syncthreads();
    }
    const float inv  = 1.f / (8.f * Tn);
    const float mean = rs[0] * inv;
    const float var  = rs2[0] * inv - mean * mean;
    const float rstd = rsqrtf(var + 1e-5f);

    for (int i = threadIdx.x; i < N4; i += 256) {
        int c = g * 8 + (i >> 10);
        float wc = w[c] * rstd;
        float bc = bias[c] - mean * wc;
        float4 v = xp[i];
        v.x = v.x * wc + bc; v.y = v.y * wc + bc;
        v.z = v.z * wc + bc; v.w = v.w * wc + bc;
        op[i] = v;
    }
}

// ============================================================================
// 2/4) Tensor-core GEMM (tf32 warp-mma), K=256. Block 64m x 128n, 8 warps.
//   MODE 0: qkv. q/k -> g_qb/g_kb bf16 [bh][t][c] (scaled); v -> g_vb [bh][c][t]
//   MODE 1: proj + bias + residual -> d_out (fp32).
// ============================================================================
template<int MODE>
__global__ __launch_bounds__(256, 2) void gemm_tc(const float* __restrict__ A,
                                                  const float* __restrict__ bias,
                                                  const float* __restrict__ resid,
                                                  float* __restrict__ out_param) {
    __shared__ float a_s[64][36];
    __shared__ float b_s[32][132];
    const int K = 256;
    const int tid  = threadIdx.x;
    const int wid  = tid >> 5;
    const int lane = tid & 31;
    const int g    = lane >> 2;
    const int t4   = lane & 3;
    const int wm   = (wid >> 1) * 16;
    const int wn   = (wid & 1) * 64;
    const int m0 = blockIdx.y * 64, n0 = blockIdx.x * 128;
    const float* __restrict__ Bmat = (MODE == 0) ? g_xn : g_attn;
    const size_t bb = (size_t)blockIdx.z * K * Tn;

    float acc[8][4] = {};
    for (int k0 = 0; k0 < K; k0 += 32) {
        #pragma unroll
        for (int r = 0; r < 2; r++) {
            int i = tid + r * 256;
            int m = i >> 3, kq = (i & 7) * 4;
            float4 v = *(const float4*)(A + (size_t)(m0 + m) * K + k0 + kq);
            a_s[m][kq+0] = f2tf(v.x); a_s[m][kq+1] = f2tf(v.y);
            a_s[m][kq+2] = f2tf(v.z); a_s[m][kq+3] = f2tf(v.w);
        }
        #pragma unroll
        for (int r = 0; r < 4; r++) {
            int i = tid + r * 256;
            int k = i >> 5, nq = (i & 31) * 4;
            float4 v = *(const float4*)(Bmat + bb + (size_t)(k0 + k) * Tn + n0 + nq);
            b_s[k][nq+0] = f2tf(v.x); b_s[k][nq+1] = f2tf(v.y);
            b_s[k][nq+2] = f2tf(v.z); b_s[k][nq+3] = f2tf(v.w);
        }
        __syncthreads();
        #pragma unroll
        for (int kk = 0; kk < 32; kk += 8) {
            unsigned a0 = __float_as_uint(a_s[wm + g    ][kk + t4    ]);
            unsigned a1 = __float_as_uint(a_s[wm + g + 8][kk + t4    ]);
            unsigned a2 = __float_as_uint(a_s[wm + g    ][kk + t4 + 4]);
            unsigned a3 = __float_as_uint(a_s[wm + g + 8][kk + t4 + 4]);
            #pragma unroll
            for (int n = 0; n < 8; n++) {
                unsigned b0 = __float_as_uint(b_s[kk + t4    ][wn + n * 8 + g]);
                unsigned b1 = __float_as_uint(b_s[kk + t4 + 4][wn + n * 8 + g]);
                mma_tf32(acc[n], a0, a1, a2, a3, b0, b1);
            }
        }
        __syncthreads();
    }

    const int mrow0 = m0 + wm + g;
    const int mrow1 = mrow0 + 8;
    float bi0 = bias[mrow0], bi1 = bias[mrow1];

    if (MODE == 0) {
        const int cls = (m0 % 192) / 64;        // 0=q, 1=k, 2=v
        const int hh  = mrow0 / 192;
        const int bh  = blockIdx.z * 4 + hh;
        if (cls != 2) {
            const int of0 = mrow0 % 192 - cls * 64;
            const int of1 = of0 + 8;
            __nv_bfloat16* dst = (cls == 0 ? g_qb : g_kb)
                               + ((size_t)bh * Tn + n0 + wn) * 64;
            #pragma unroll
            for (int n = 0; n < 8; n++) {
                int col = n * 8 + 2 * t4;
                dst[(size_t)(col    ) * 64 + of0] = __float2bfloat16((acc[n][0] + bi0) * SCALE_QK);
                dst[(size_t)(col + 1) * 64 + of0] = __float2bfloat16((acc[n][1] + bi0) * SCALE_QK);
                dst[(size_t)(col    ) * 64 + of1] = __float2bfloat16((acc[n][2] + bi1) * SCALE_QK);
                dst[(size_t)(col + 1) * 64 + of1] = __float2bfloat16((acc[n][3] + bi1) * SCALE_QK);
            }
        } else {
            const int c0 = mrow0 % 192 - 128;
            unsigned* d0 = (unsigned*)(g_vb + ((size_t)bh * 64 + c0    ) * Tn + n0 + wn);
            unsigned* d1 = (unsigned*)(g_vb + ((size_t)bh * 64 + c0 + 8) * Tn + n0 + wn);
            #pragma unroll
            for (int n = 0; n < 8; n++) {
                int col = n * 8 + 2 * t4;
                d0[col / 2] = pack_bf2(acc[n][0] + bi0, acc[n][1] + bi0);
                d1[col / 2] = pack_bf2(acc[n][2] + bi1, acc[n][3] + bi1);
            }
        }
    } else {
        const size_t o0 = ((size_t)blockIdx.z * Cn + mrow0) * Tn + n0 + wn;
        const size_t o1 = ((size_t)blockIdx.z * Cn + mrow1) * Tn + n0 + wn;
        #pragma unroll
        for (int n = 0; n < 8; n++) {
            int col = n * 8 + 2 * t4;
            *(float2*)(out_param + o0 + col) = make_float2(
                acc[n][0] + bi0 + resid[o0 + col], acc[n][1] + bi0 + resid[o0 + col + 1]);
            *(float2*)(out_param + o1 + col) = make_float2(
                acc[n][2] + bi1 + resid[o1 + col], acc[n][3] + bi1 + resid[o1 + col + 1]);
        }
    }
}

// ============================================================================
// 3) Flash attention, bf16 m16n8k16, fixed-shift softmax p = exp(s - 8)
//    (shift-invariant => exact softmax; no running max, no rescale).
//    P stays in registers (S-frag layout == PV A-frag layout). Double-buffered
//    K/V smem, 1 sync/iter. Q tile 128 t-rows, KV tile 64, 64 iters.
//    smem u32 stride 36 (bank = 4g + t4 pattern, conflict-free).
//    Layout: K0[2304] K1[2304] V0[2304] V1[2304] u32 = 36864 B.
//    Q-stage (prologue) and O-stage (epilogue) alias the same region.
// ============================================================================
__global__ __launch_bounds__(256, 2) void attn_kernel() {
    extern __shared__ unsigned su[];
    const int tid  = threadIdx.x;
    const int wid  = tid >> 5;
    const int lane = tid & 31;
    const int g    = lane >> 2;
    const int t4   = lane & 3;
    const int tw   = wid * 16;

    const int t0 = blockIdx.x * 128;
    const int bh = blockIdx.y;
    const __nv_bfloat16* qb = g_qb + ((size_t)bh * Tn + t0) * 64;
    const char* kb = (const char*)(g_kb + (size_t)bh * Tn * 64);
    const char* vb = (const char*)(g_vb + (size_t)bh * 64 * Tn);
    float* ap = g_attn + ((size_t)(bh >> 2) * Cn + (bh & 3) * 64) * Tn;

    // ---- prologue: stage Q [t][c/2] u32 stride 36, hoist fragments ----
    #pragma unroll
    for (int r = 0; r < 4; r++) {
        int ch = tid + r * 256;                 // 1024 chunks of 16B
        int row = ch >> 3, q = ch & 7;
        uint4 v = *(const uint4*)((const char*)qb + ch * 16);
        *(uint4*)&su[row * 36 + q * 4] = v;
    }
    __syncthreads();
    unsigned qf[4][4];
    #pragma unroll
    for (int kk = 0; kk < 4; kk++) {
        qf[kk][0] = su[(tw + g    ) * 36 + kk * 8 + t4    ];
        qf[kk][1] = su[(tw + g + 8) * 36 + kk * 8 + t4    ];
        qf[kk][2] = su[(tw + g    ) * 36 + kk * 8 + t4 + 4];
        qf[kk][3] = su[(tw + g + 8) * 36 + kk * 8 + t4 + 4];
    }
    __syncthreads();

    // ---- stage tile 0 into buffers 0 ----
    #pragma unroll
    for (int r = 0; r < 2; r++) {
        int ch = tid + r * 256;                 // 512 chunks of 16B (8KB)
        int row = ch >> 3, q = ch & 7;
        uint4 kv = *(const uint4*)(kb + ch * 16);
        *(uint4*)&su[row * 36 + q * 4] = kv;
        uint4 vv = *(const uint4*)(vb + (size_t)row * (Tn * 2) + q * 16);
        *(uint4*)&su[4608 + row * 36 + q * 4] = vv;   // V: row==c here
    }
    __syncthreads();

    float acc_o[8][4];
    #pragma unroll
    for (int n = 0; n < 8; n++)
        #pragma unroll
        for (int r = 0; r < 4; r++) acc_o[n][r] = 0.f;
    float l0 = 0.f, l1 = 0.f;

    for (int i = 0; i < 64; i++) {
        const int cur = i & 1, nxt = cur ^ 1;
        const unsigned* ku = su + cur * 2304;
        const unsigned* vu = su + 4608 + cur * 2304;

        // prefetch next tile (global -> regs)
        uint4 pk[2], pv[2];
        if (i < 63) {
            const char* kg = kb + (size_t)(i + 1) * 8192;
            #pragma unroll
            for (int r = 0; r < 2; r++) {
                int ch = tid + r * 256;
                int row = ch >> 3, q = ch & 7;
                pk[r] = *(const uint4*)(kg + ch * 16);
                pv[r] = *(const uint4*)(vb + (size_t)row * (Tn * 2)
                                        + (size_t)(i + 1) * 128 + q * 16);
            }
        }

        // ---- S = Q K^T ----
        float sacc[8][4];
        #pragma unroll
        for (int n = 0; n < 8; n++)
            #pragma unroll
            for (int r = 0; r < 4; r++) sacc[n][r] = 0.f;
        #pragma unroll
        for (int kk = 0; kk < 4; kk++) {
            #pragma unroll
            for (int n = 0; n < 8; n++) {
                unsigned b0 = ku[(n * 8 + g) * 36 + kk * 8 + t4    ];
                unsigned b1 = ku[(n * 8 + g) * 36 + kk * 8 + t4 + 4];
                mma_bf16(sacc[n], qf[kk][0], qf[kk][1], qf[kk][2], qf[kk][3], b0, b1);
            }
        }

        // ---- p = exp(s - 8); accumulate l; pack P fragments in-register ----
        float p[8][4];
        #pragma unroll
        for (int n = 0; n < 8; n++) {
            p[n][0] = __expf(sacc[n][0] - 8.f);
            p[n][1] = __expf(sacc[n][1] - 8.f);
            p[n][2] = __expf(sacc[n][2] - 8.f);
            p[n][3] = __expf(sacc[n][3] - 8.f);
            l0 += p[n][0] + p[n][1];
            l1 += p[n][2] + p[n][3];
        }

        // ---- O += P V^T (P fragments straight from registers) ----
        #pragma unroll
        for (int kk = 0; kk < 4; kk++) {
            unsigned a0 = pack_bf2(p[2*kk  ][0], p[2*kk  ][1]);
            unsigned a1 = pack_bf2(p[2*kk  ][2], p[2*kk  ][3]);
            unsigned a2 = pack_bf2(p[2*kk+1][0], p[2*kk+1][1]);
            unsigned a3 = pack_bf2(p[2*kk+1][2], p[2*kk+1][3]);
            #pragma unroll
            for (int n = 0; n < 8; n++) {
                unsigned b0 = vu[(n * 8 + g) * 36 + kk * 8 + t4    ];
                unsigned b1 = vu[(n * 8 + g) * 36 + kk * 8 + t4 + 4];
                mma_bf16(acc_o[n], a0, a1, a2, a3, b0, b1);
            }
        }

        // store prefetched tile into other buffer
        if (i < 63) {
            unsigned* kd = su + nxt * 2304;
            unsigned* vd = su + 4608 + nxt * 2304;
            #pragma unroll
            for (int r = 0; r < 2; r++) {
                int ch = tid + r * 256;
                int row = ch >> 3, q = ch & 7;
                *(uint4*)&kd[row * 36 + q * 4] = pk[r];
                *(uint4*)&vd[row * 36 + q * 4] = pv[r];
            }
        }
        __syncthreads();
    }

    // ---- finalize l (sum across the 4 threads of each row quad) ----
    l0 += __shfl_xor_sync(0xffffffffu, l0, 1);
    l0 += __shfl_xor_sync(0xffffffffu, l0, 2);
    l1 += __shfl_xor_sync(0xffffffffu, l1, 1);
    l1 += __shfl_xor_sync(0xffffffffu, l1, 2);
    const float rl0 = 1.f / l0, rl1 = 1.f / l1;

    // ---- stage O as [c][t] (stride 132: conflict-free), coalesced writeback
    float* o_sm = (float*)su;
    #pragma unroll
    for (int n = 0; n < 8; n++) {
        int c = n * 8 + 2 * t4;
        o_sm[(c    ) * 132 + tw + g    ] = acc_o[n][0] * rl0;
        o_sm[(c + 1) * 132 + tw + g    ] = acc_o[n][1] * rl0;
        o_sm[(c    ) * 132 + tw + g + 8] = acc_o[n][2] * rl1;
        o_sm[(c + 1) * 132 + tw + g + 8] = acc_o[n][3] * rl1;
    }
    __syncthreads();
    for (int idx = tid; idx < 2048; idx += 256) {
        int c = idx >> 5, tj = (idx & 31) * 4;
        float4 o4;
        o4.x = o_sm[c * 132 + tj];     o4.y = o_sm[c * 132 + tj + 1];
        o4.z = o_sm[c * 132 + tj + 2]; o4.w = o_sm[c * 132 + tj + 3];
        *(float4*)(ap + (size_t)c * Tn + t0 + tj) = o4;
    }
}

// ============================================================================
extern "C" void kernel_launch(void* const* d_in, const int* in_sizes, int n_in,
                              void* d_out, int out_size) {
    const float* x     = (const float*)d_in[0];
    const float* nw    = (const float*)d_in[1];
    const float* nb    = (const float*)d_in[2];
    const float* qkvw  = (const float*)d_in[3];
    const float* qkvb  = (const float*)d_in[4];
    const float* projw = (const float*)d_in[5];
    const float* projb = (const float*)d_in[6];
    float* out = (float*)d_out;

    const int ATTN_SMEM = 4 * 2304 * 4;   // 36864 B
    cudaFuncSetAttribute(attn_kernel, cudaFuncAttributeMaxDynamicSharedMemorySize,
                         ATTN_SMEM);

    gn_kernel<<<Bn * 32, 256>>>(x, nw, nb);
    gemm_tc<0><<<dim3(Tn / 128, 768 / 64, Bn), 256>>>(qkvw, qkvb, nullptr, nullptr);
    attn_kernel<<<dim3(Tn / 128, Bn * 4), 256, ATTN_SMEM>>>();
    gemm_tc<1><<<dim3(Tn / 128, Cn / 64, Bn), 256>>>(projw, projb, x, out);
}

// round 8
// speedup vs baseline: 10.1918x; 1.0650x over previous
#include <cuda_runtime.h>
#include <cuda_bf16.h>
#include <cuda_fp16.h>
#include <cstdint>
#include <math.h>

#define Tn 4096
#define Cn 256
#define Bn 2
#define SCALE_QK 0.35355339059327373f   // 64^-0.25
#define LOG2E    1.4426950408889634f
// exp(s-2) = 2^(s*LOG2E - 2*LOG2E); 2*LOG2E = 2.8853900817779268
#define EXSHIFT  2.8853900817779268f

// ---- scratch (__device__ globals: allocation-free) ----
__device__ float         g_attn [Bn * Cn * Tn];     // attention out  [B,256,T]
__device__ float2        g_stats[Bn * 32];          // per (b,group): mean, rstd
__device__ __nv_bfloat16 g_qb   [Bn * 4 * Tn * 64]; // q [bh][t][c] bf16 scaled
__device__ __nv_bfloat16 g_kb   [Bn * 4 * Tn * 64]; // k [bh][s][c] bf16 scaled
__device__ __half        g_vh   [Bn * 4 * 64 * Tn]; // v [bh][c][t] fp16

// ---- helpers ----
__device__ __forceinline__ unsigned pack_bf2(float a, float b) {
    __nv_bfloat162 h = __floats2bfloat162_rn(a, b);
    return *(unsigned*)&h;
}
__device__ __forceinline__ unsigned pack_h2(float a, float b) {
    __half2 h = __floats2half2_rn(a, b);
    return *(unsigned*)&h;
}
__device__ __forceinline__ unsigned cvt_f16x2(float hi, float lo) {
    unsigned d;
    asm("cvt.rn.f16x2.f32 %0, %1, %2;" : "=r"(d) : "f"(hi), "f"(lo));
    return d;
}
__device__ __forceinline__ unsigned ex2_f16x2(unsigned a) {
    unsigned d;
    asm("ex2.approx.f16x2 %0, %1;" : "=r"(d) : "r"(a));
    return d;
}
__device__ __forceinline__ void mma_bf16(float c[4],
                                         unsigned a0, unsigned a1, unsigned a2, unsigned a3,
                                         unsigned b0, unsigned b1) {
    asm volatile(
        "mma.sync.aligned.m16n8k16.row.col.f32.bf16.bf16.f32 "
        "{%0,%1,%2,%3},{%4,%5,%6,%7},{%8,%9},{%0,%1,%2,%3};"
        : "+f"(c[0]), "+f"(c[1]), "+f"(c[2]), "+f"(c[3])
        : "r"(a0), "r"(a1), "r"(a2), "r"(a3), "r"(b0), "r"(b1));
}
__device__ __forceinline__ void mma_f16(float c[4],
                                        unsigned a0, unsigned a1, unsigned a2, unsigned a3,
                                        unsigned b0, unsigned b1) {
    asm volatile(
        "mma.sync.aligned.m16n8k16.row.col.f32.f16.f16.f32 "
        "{%0,%1,%2,%3},{%4,%5,%6,%7},{%8,%9},{%0,%1,%2,%3};"
        : "+f"(c[0]), "+f"(c[1]), "+f"(c[2]), "+f"(c[3])
        : "r"(a0), "r"(a1), "r"(a2), "r"(a3), "r"(b0), "r"(b1));
}

// ============================================================================
// 1) GroupNorm stats only: grid 64 (b,g), 512 threads. Writes (mean, rstd).
// ============================================================================
__global__ __launch_bounds__(512) void gn_stats_kernel(const float* __restrict__ x) {
    const int b = blockIdx.x >> 5;
    const int g = blockIdx.x & 31;
    const size_t base = ((size_t)b * Cn + g * 8) * Tn;
    const float4* xp = (const float4*)(x + base);
    const int N4 = 8 * Tn / 4;  // 8192

    float s = 0.f, s2 = 0.f;
    for (int i = threadIdx.x; i < N4; i += 512) {
        float4 v = xp[i];
        s  += v.x + v.y + v.z + v.w;
        s2 += v.x*v.x + v.y*v.y + v.z*v.z + v.w*v.w;
    }
    __shared__ float rs[512], rs2[512];
    rs[threadIdx.x] = s; rs2[threadIdx.x] = s2;
    __syncthreads();
    for (int off = 256; off > 0; off >>= 1) {
        if (threadIdx.x < off) {
            rs [threadIdx.x] += rs [threadIdx.x + off];
            rs2[threadIdx.x] += rs2[threadIdx.x + off];
        }
        __syncthreads();
    }
    if (threadIdx.x == 0) {
        const float inv  = 1.f / (8.f * Tn);
        const float mean = rs[0] * inv;
        const float var  = rs2[0] * inv - mean * mean;
        g_stats[blockIdx.x] = make_float2(mean, rsqrtf(var + 1e-5f));
    }
}

// ============================================================================
// 2/4) bf16 tensor-core GEMM, K=256. Block 64m x 128n, 8 warps (4m x 2n).
//   MODE 0: A=qkv_w, B = groupnorm(x) applied on the fly during staging
//           (Bsrc = x from harness). q/k -> g_qb/g_kb bf16 [bh][t][c] scaled;
//           v -> g_vh fp16 [bh][c][t].
//   MODE 1: A=proj_w, B = g_attn (device symbol, resolved in DEVICE code);
//           out = proj + bias + residual (fp32).
// ============================================================================
template<int MODE>
__global__ __launch_bounds__(256, 2) void gemm_bf(const float* __restrict__ A,
                                                  const float* __restrict__ bias,
                                                  const float* __restrict__ Bsrc,
                                                  const float* __restrict__ nw,
                                                  const float* __restrict__ nb,
                                                  const float* __restrict__ resid,
                                                  float* __restrict__ out_param) {
    __shared__ unsigned as_u[64 * 20];
    __shared__ unsigned bs_u[128 * 20];
    const int K = 256;
    const int tid  = threadIdx.x;
    const int wid  = tid >> 5;
    const int lane = tid & 31;
    const int g    = lane >> 2;
    const int t4   = lane & 3;
    const int wm   = (wid >> 1) * 16;
    const int wn   = (wid & 1) * 64;
    const int m0 = blockIdx.y * 64, n0 = blockIdx.x * 128;
    // device-side symbol resolution (NEVER pass __device__ globals from host!)
    const float* __restrict__ Bmat = (MODE == 0) ? Bsrc : g_attn;
    const size_t bb = (size_t)blockIdx.z * K * Tn;

    float acc[8][4] = {};
    for (int k0 = 0; k0 < K; k0 += 32) {
        // ---- A tile 64m x 32k -> as_u[m][k/2] (1 item/thread) ----
        {
            int m = tid >> 2, kq = (tid & 3) * 8;
            const float* ap = A + (size_t)(m0 + m) * K + k0 + kq;
            float4 v0 = *(const float4*)ap;
            float4 v1 = *(const float4*)(ap + 4);
            uint4 pk;
            pk.x = pack_bf2(v0.x, v0.y); pk.y = pack_bf2(v0.z, v0.w);
            pk.z = pack_bf2(v1.x, v1.y); pk.w = pack_bf2(v1.z, v1.w);
            *(uint4*)&as_u[m * 20 + kq / 2] = pk;
        }
        // ---- B tile 32k x 128n -> bs_u[n][k/2] (transpose-pack, 2 items/thr)
        #pragma unroll
        for (int r = 0; r < 2; r++) {
            int idx = tid + r * 256;        // 512 items
            int kp = idx & 15, nq = idx >> 4;
            int c0 = k0 + 2 * kp;
            const float* rp = Bmat + bb + (size_t)c0 * Tn + n0 + nq * 4;
            float4 va = *(const float4*)rp;
            float4 vb = *(const float4*)(rp + Tn);
            float wc0 = 1.f, bc0 = 0.f, wc1 = 1.f, bc1 = 0.f;
            if (MODE == 0) {
                float2 st = g_stats[(blockIdx.z << 5) + (c0 >> 3)];
                wc0 = nw[c0] * st.y;     bc0 = nb[c0] - st.x * wc0;
                wc1 = nw[c0 + 1] * st.y; bc1 = nb[c0 + 1] - st.x * wc1;
            }
            int nbase = (nq * 4) * 20 + kp;
            bs_u[nbase     ] = pack_bf2(va.x * wc0 + bc0, vb.x * wc1 + bc1);
            bs_u[nbase + 20] = pack_bf2(va.y * wc0 + bc0, vb.y * wc1 + bc1);
            bs_u[nbase + 40] = pack_bf2(va.z * wc0 + bc0, vb.z * wc1 + bc1);
            bs_u[nbase + 60] = pack_bf2(va.w * wc0 + bc0, vb.w * wc1 + bc1);
        }
        __syncthreads();
        #pragma unroll
        for (int kk = 0; kk < 2; kk++) {
            unsigned a0 = as_u[(wm + g    ) * 20 + kk * 8 + t4    ];
            unsigned a1 = as_u[(wm + g + 8) * 20 + kk * 8 + t4    ];
            unsigned a2 = as_u[(wm + g    ) * 20 + kk * 8 + t4 + 4];
            unsigned a3 = as_u[(wm + g + 8) * 20 + kk * 8 + t4 + 4];
            #pragma unroll
            for (int n = 0; n < 8; n++) {
                unsigned b0 = bs_u[(wn + n * 8 + g) * 20 + kk * 8 + t4    ];
                unsigned b1 = bs_u[(wn + n * 8 + g) * 20 + kk * 8 + t4 + 4];
                mma_bf16(acc[n], a0, a1, a2, a3, b0, b1);
            }
        }
        __syncthreads();
    }

    const int mrow0 = m0 + wm + g;
    const int mrow1 = mrow0 + 8;
    float bi0 = bias[mrow0], bi1 = bias[mrow1];

    if (MODE == 0) {
        const int cls = (m0 % 192) / 64;        // 0=q, 1=k, 2=v
        const int hh  = mrow0 / 192;
        const int bh  = blockIdx.z * 4 + hh;
        if (cls != 2) {
            const int of0 = mrow0 % 192 - cls * 64;
            const int of1 = of0 + 8;
            __nv_bfloat16* dst = (cls == 0 ? g_qb : g_kb)
                               + ((size_t)bh * Tn + n0 + wn) * 64;
            #pragma unroll
            for (int n = 0; n < 8; n++) {
                int col = n * 8 + 2 * t4;
                dst[(size_t)(col    ) * 64 + of0] = __float2bfloat16((acc[n][0] + bi0) * SCALE_QK);
                dst[(size_t)(col + 1) * 64 + of0] = __float2bfloat16((acc[n][1] + bi0) * SCALE_QK);
                dst[(size_t)(col    ) * 64 + of1] = __float2bfloat16((acc[n][2] + bi1) * SCALE_QK);
                dst[(size_t)(col + 1) * 64 + of1] = __float2bfloat16((acc[n][3] + bi1) * SCALE_QK);
            }
        } else {
            const int c0 = mrow0 % 192 - 128;
            unsigned* d0 = (unsigned*)(g_vh + ((size_t)bh * 64 + c0    ) * Tn + n0 + wn);
            unsigned* d1 = (unsigned*)(g_vh + ((size_t)bh * 64 + c0 + 8) * Tn + n0 + wn);
            #pragma unroll
            for (int n = 0; n < 8; n++) {
                int col = n * 8 + 2 * t4;
                d0[col / 2] = pack_h2(acc[n][0] + bi0, acc[n][1] + bi0);
                d1[col / 2] = pack_h2(acc[n][2] + bi1, acc[n][3] + bi1);
            }
        }
    } else {
        const size_t o0 = ((size_t)blockIdx.z * Cn + mrow0) * Tn + n0 + wn;
        const size_t o1 = ((size_t)blockIdx.z * Cn + mrow1) * Tn + n0 + wn;
        #pragma unroll
        for (int n = 0; n < 8; n++) {
            int col = n * 8 + 2 * t4;
            *(float2*)(out_param + o0 + col) = make_float2(
                acc[n][0] + bi0 + resid[o0 + col], acc[n][1] + bi0 + resid[o0 + col + 1]);
            *(float2*)(out_param + o1 + col) = make_float2(
                acc[n][2] + bi1 + resid[o1 + col], acc[n][3] + bi1 + resid[o1 + col + 1]);
        }
    }
}

// ============================================================================
// 3) Flash attention. S: bf16 mma. P: fp16 via ex2.approx.f16x2, shift 2
//    (p = exp(s-2), all values in fp16 normal range for |s| <= ~10).
//    PV: fp16 mma, V fp16 with a ones-row block (n-subtile 8) so the MMA
//    accumulates l = row-sums of P.
//    smem u32: K0[2304] K1[2304] | V0[2592] V1[2592]  (V rows 64..71: row 64 =
//    fp16 ones, rows 65-71 = 0). Stride 36 u32, conflict-free.
// ============================================================================
#define KBUF 2304
#define VOFF 4608
#define VBUF 2592
#define SMU  (VOFF + 2 * VBUF)    // 9792 u32 = 39168 B

__global__ __launch_bounds__(256, 2) void attn_kernel() {
    extern __shared__ unsigned su[];
    const int tid  = threadIdx.x;
    const int wid  = tid >> 5;
    const int lane = tid & 31;
    const int g    = lane >> 2;
    const int t4   = lane & 3;
    const int tw   = wid * 16;

    const int t0 = blockIdx.x * 128;
    const int bh = blockIdx.y;
    const __nv_bfloat16* qb = g_qb + ((size_t)bh * Tn + t0) * 64;
    const char* kb = (const char*)(g_kb + (size_t)bh * Tn * 64);
    const char* vb = (const char*)(g_vh + (size_t)bh * 64 * Tn);
    float* ap = g_attn + ((size_t)(bh >> 2) * Cn + (bh & 3) * 64) * Tn;

    // ---- prologue: stage Q [t][c/2] stride 36, hoist fragments ----
    #pragma unroll
    for (int r = 0; r < 4; r++) {
        int ch = tid + r * 256;
        int row = ch >> 3, q = ch & 7;
        uint4 v = *(const uint4*)((const char*)qb + ch * 16);
        *(uint4*)&su[row * 36 + q * 4] = v;
    }
    __syncthreads();
    unsigned qf[4][4];
    #pragma unroll
    for (int kk = 0; kk < 4; kk++) {
        qf[kk][0] = su[(tw + g    ) * 36 + kk * 8 + t4    ];
        qf[kk][1] = su[(tw + g + 8) * 36 + kk * 8 + t4    ];
        qf[kk][2] = su[(tw + g    ) * 36 + kk * 8 + t4 + 4];
        qf[kk][3] = su[(tw + g + 8) * 36 + kk * 8 + t4 + 4];
    }
    __syncthreads();

    // ---- ones/zero rows 64-71 of both V buffers + stage tile 0 ----
    {
        int row = 64 + (tid >> 5), col = lane;
        unsigned val = (row == 64) ? 0x3C003C00u : 0u;   // fp16 {1,1} : {0,0}
        su[VOFF        + row * 36 + col] = val;
        su[VOFF + VBUF + row * 36 + col] = val;
    }
    #pragma unroll
    for (int r = 0; r < 2; r++) {
        int ch = tid + r * 256;
        int row = ch >> 3, q = ch & 7;
        uint4 kv = *(const uint4*)(kb + ch * 16);
        *(uint4*)&su[row * 36 + q * 4] = kv;
        uint4 vv = *(const uint4*)(vb + (size_t)row * (Tn * 2) + q * 16);
        *(uint4*)&su[VOFF + row * 36 + q * 4] = vv;
    }
    __syncthreads();

    float acc_o[8][4];
    #pragma unroll
    for (int n = 0; n < 8; n++)
        #pragma unroll
        for (int r = 0; r < 4; r++) acc_o[n][r] = 0.f;
    float acc_l[4] = {0.f, 0.f, 0.f, 0.f};

    for (int i = 0; i < 64; i++) {
        const int cur = i & 1, nxt = cur ^ 1;
        const unsigned* ku = su + cur * KBUF;
        const unsigned* vu = su + VOFF + cur * VBUF;

        // prefetch next tile (global -> regs)
        uint4 pk[2], pv[2];
        if (i < 63) {
            const char* kg = kb + (size_t)(i + 1) * 8192;
            #pragma unroll
            for (int r = 0; r < 2; r++) {
                int ch = tid + r * 256;
                int row = ch >> 3, q = ch & 7;
                pk[r] = *(const uint4*)(kg + ch * 16);
                pv[r] = *(const uint4*)(vb + (size_t)row * (Tn * 2)
                                        + (size_t)(i + 1) * 128 + q * 16);
            }
        }

        // ---- S = Q K^T (bf16) ----
        float sacc[8][4];
        #pragma unroll
        for (int n = 0; n < 8; n++)
            #pragma unroll
            for (int r = 0; r < 4; r++) sacc[n][r] = 0.f;
        #pragma unroll
        for (int kk = 0; kk < 4; kk++) {
            #pragma unroll
            for (int n = 0; n < 8; n++) {
                unsigned b0 = ku[(n * 8 + g) * 36 + kk * 8 + t4    ];
                unsigned b1 = ku[(n * 8 + g) * 36 + kk * 8 + t4 + 4];
                mma_bf16(sacc[n], qf[kk][0], qf[kk][1], qf[kk][2], qf[kk][3], b0, b1);
            }
        }

        // ---- p = exp(s-2) = 2^(s*log2e - 2*log2e), packed fp16x2 ----
        unsigned pf[8], pg[8];
        #pragma unroll
        for (int n = 0; n < 8; n++) {
            float t0f = fmaf(sacc[n][0], LOG2E, -EXSHIFT);
            float t1f = fmaf(sacc[n][1], LOG2E, -EXSHIFT);
            float t2f = fmaf(sacc[n][2], LOG2E, -EXSHIFT);
            float t3f = fmaf(sacc[n][3], LOG2E, -EXSHIFT);
            pf[n] = ex2_f16x2(cvt_f16x2(t1f, t0f));
            pg[n] = ex2_f16x2(cvt_f16x2(t3f, t2f));
        }

        // ---- O += P V^T; l accumulated by n-subtile 8 (ones row) ----
        #pragma unroll
        for (int kk = 0; kk < 4; kk++) {
            unsigned a0 = pf[2*kk], a1 = pg[2*kk], a2 = pf[2*kk+1], a3 = pg[2*kk+1];
            #pragma unroll
            for (int n = 0; n < 8; n++) {
                unsigned b0 = vu[(n * 8 + g) * 36 + kk * 8 + t4    ];
                unsigned b1 = vu[(n * 8 + g) * 36 + kk * 8 + t4 + 4];
                mma_f16(acc_o[n], a0, a1, a2, a3, b0, b1);
            }
            unsigned l0 = vu[(64 + g) * 36 + kk * 8 + t4    ];
            unsigned l1 = vu[(64 + g) * 36 + kk * 8 + t4 + 4];
            mma_f16(acc_l, a0, a1, a2, a3, l0, l1);
        }

        // store prefetched tile into other buffer
        if (i < 63) {
            unsigned* kd = su + nxt * KBUF;
            unsigned* vd = su + VOFF + nxt * VBUF;
            #pragma unroll
            for (int r = 0; r < 2; r++) {
                int ch = tid + r * 256;
                int row = ch >> 3, q = ch & 7;
                *(uint4*)&kd[row * 36 + q * 4] = pk[r];
                *(uint4*)&vd[row * 36 + q * 4] = pv[r];
            }
        }
        __syncthreads();
    }

    // ---- l lives in output column 0 => t4==0 lanes; broadcast within quad --
    const float l0 = __shfl_sync(0xffffffffu, acc_l[0], lane & ~3);
    const float l1 = __shfl_sync(0xffffffffu, acc_l[2], lane & ~3);
    const float rl0 = 1.f / l0, rl1 = 1.f / l1;

    // ---- stage O as [c][t] (stride 132), coalesced writeback ----
    float* o_sm = (float*)su;
    #pragma unroll
    for (int n = 0; n < 8; n++) {
        int c = n * 8 + 2 * t4;
        o_sm[(c    ) * 132 + tw + g    ] = acc_o[n][0] * rl0;
        o_sm[(c + 1) * 132 + tw + g    ] = acc_o[n][1] * rl0;
        o_sm[(c    ) * 132 + tw + g + 8] = acc_o[n][2] * rl1;
        o_sm[(c + 1) * 132 + tw + g + 8] = acc_o[n][3] * rl1;
    }
    __syncthreads();
    for (int idx = tid; idx < 2048; idx += 256) {
        int c = idx >> 5, tj = (idx & 31) * 4;
        float4 o4;
        o4.x = o_sm[c * 132 + tj];     o4.y = o_sm[c * 132 + tj + 1];
        o4.z = o_sm[c * 132 + tj + 2]; o4.w = o_sm[c * 132 + tj + 3];
        *(float4*)(ap + (size_t)c * Tn + t0 + tj) = o4;
    }
}

// ============================================================================
extern "C" void kernel_launch(void* const* d_in, const int* in_sizes, int n_in,
                              void* d_out, int out_size) {
    const float* x     = (const float*)d_in[0];
    const float* nw    = (const float*)d_in[1];
    const float* nb    = (const float*)d_in[2];
    const float* qkvw  = (const float*)d_in[3];
    const float* qkvb  = (const float*)d_in[4];
    const float* projw = (const float*)d_in[5];
    const float* projb = (const float*)d_in[6];
    float* out = (float*)d_out;

    const int ATTN_SMEM = SMU * 4;   // 39168 B
    cudaFuncSetAttribute(attn_kernel, cudaFuncAttributeMaxDynamicSharedMemorySize,
                         ATTN_SMEM);

    gn_stats_kernel<<<Bn * 32, 512>>>(x);
    gemm_bf<0><<<dim3(Tn / 128, 768 / 64, Bn), 256>>>(qkvw, qkvb, x, nw, nb,
                                                      nullptr, nullptr);
    attn_kernel<<<dim3(Tn / 128, Bn * 4), 256, ATTN_SMEM>>>();
    gemm_bf<1><<<dim3(Tn / 128, Cn / 64, Bn), 256>>>(projw, projb, nullptr, nullptr,
                                                     nullptr, x, out);
}

// round 9
// speedup vs baseline: 10.6532x; 1.0453x over previous
#include <cuda_runtime.h>
#include <cuda_bf16.h>
#include <cuda_fp16.h>
#include <cstdint>
#include <math.h>

#define Tn 4096
#define Cn 256
#define Bn 2
#define SCALE_QK 0.35355339059327373f   // 64^-0.25
#define LOG2E    1.4426950408889634f
// exp(s-2) = 2^(s*LOG2E - 2*LOG2E); 2*LOG2E = 2.8853900817779268
#define EXSHIFT  2.8853900817779268f

// ---- scratch (__device__ globals: allocation-free) ----
__device__ float         g_attn [Bn * Cn * Tn];     // attention out  [B,256,T]
__device__ float2        g_stats[Bn * 32];          // per (b,group): mean, rstd
__device__ __nv_bfloat16 g_qb   [Bn * 4 * Tn * 64]; // q [bh][t][c] bf16 scaled
__device__ __nv_bfloat16 g_kb   [Bn * 4 * Tn * 64]; // k [bh][s][c] bf16 scaled
__device__ __half        g_vh   [Bn * 4 * 64 * Tn]; // v [bh][c][t] fp16

// ---- helpers ----
__device__ __forceinline__ unsigned pack_bf2(float a, float b) {
    __nv_bfloat162 h = __floats2bfloat162_rn(a, b);
    return *(unsigned*)&h;
}
__device__ __forceinline__ unsigned pack_h2(float a, float b) {
    __half2 h = __floats2half2_rn(a, b);
    return *(unsigned*)&h;
}
__device__ __forceinline__ unsigned cvt_f16x2(float hi, float lo) {
    unsigned d;
    asm("cvt.rn.f16x2.f32 %0, %1, %2;" : "=r"(d) : "f"(hi), "f"(lo));
    return d;
}
__device__ __forceinline__ unsigned ex2_f16x2(unsigned a) {
    unsigned d;
    asm("ex2.approx.f16x2 %0, %1;" : "=r"(d) : "r"(a));
    return d;
}
__device__ __forceinline__ void mma_bf16(float c[4],
                                         unsigned a0, unsigned a1, unsigned a2, unsigned a3,
                                         unsigned b0, unsigned b1) {
    asm volatile(
        "mma.sync.aligned.m16n8k16.row.col.f32.bf16.bf16.f32 "
        "{%0,%1,%2,%3},{%4,%5,%6,%7},{%8,%9},{%0,%1,%2,%3};"
        : "+f"(c[0]), "+f"(c[1]), "+f"(c[2]), "+f"(c[3])
        : "r"(a0), "r"(a1), "r"(a2), "r"(a3), "r"(b0), "r"(b1));
}
__device__ __forceinline__ void mma_f16(float c[4],
                                        unsigned a0, unsigned a1, unsigned a2, unsigned a3,
                                        unsigned b0, unsigned b1) {
    asm volatile(
        "mma.sync.aligned.m16n8k16.row.col.f32.f16.f16.f32 "
        "{%0,%1,%2,%3},{%4,%5,%6,%7},{%8,%9},{%0,%1,%2,%3};"
        : "+f"(c[0]), "+f"(c[1]), "+f"(c[2]), "+f"(c[3])
        : "r"(a0), "r"(a1), "r"(a2), "r"(a3), "r"(b0), "r"(b1));
}

// ============================================================================
// 1) GroupNorm stats only: grid 64 (b,g), 512 threads. Writes (mean, rstd).
// ============================================================================
__global__ __launch_bounds__(512) void gn_stats_kernel(const float* __restrict__ x) {
    const int b = blockIdx.x >> 5;
    const int g = blockIdx.x & 31;
    const size_t base = ((size_t)b * Cn + g * 8) * Tn;
    const float4* xp = (const float4*)(x + base);
    const int N4 = 8 * Tn / 4;  // 8192

    float s = 0.f, s2 = 0.f;
    for (int i = threadIdx.x; i < N4; i += 512) {
        float4 v = xp[i];
        s  += v.x + v.y + v.z + v.w;
        s2 += v.x*v.x + v.y*v.y + v.z*v.z + v.w*v.w;
    }
    __shared__ float rs[512], rs2[512];
    rs[threadIdx.x] = s; rs2[threadIdx.x] = s2;
    __syncthreads();
    for (int off = 256; off > 0; off >>= 1) {
        if (threadIdx.x < off) {
            rs [threadIdx.x] += rs [threadIdx.x + off];
            rs2[threadIdx.x] += rs2[threadIdx.x + off];
        }
        __syncthreads();
    }
    if (threadIdx.x == 0) {
        const float inv  = 1.f / (8.f * Tn);
        const float mean = rs[0] * inv;
        const float var  = rs2[0] * inv - mean * mean;
        g_stats[blockIdx.x] = make_float2(mean, rsqrtf(var + 1e-5f));
    }
}

// ============================================================================
// 2/4) bf16 tensor-core GEMM, K=256, software-pipelined (reg prefetch).
//   Block 64m x 128n, 8 warps (4m x 2n), K-slice 32.
//   MODE 0: A=qkv_w, B = groupnorm(x) on the fly; q/k -> g_qb/g_kb bf16
//           [bh][t][c] scaled; v -> g_vh fp16 [bh][c][t].
//   MODE 1: A=proj_w, B = g_attn (device-side symbol); out = proj+bias+resid.
// ============================================================================
template<int MODE>
__global__ __launch_bounds__(256, 2) void gemm_bf(const float* __restrict__ A,
                                                  const float* __restrict__ bias,
                                                  const float* __restrict__ Bsrc,
                                                  const float* __restrict__ nw,
                                                  const float* __restrict__ nb,
                                                  const float* __restrict__ resid,
                                                  float* __restrict__ out_param) {
    __shared__ unsigned as_u[64 * 20];
    __shared__ unsigned bs_u[128 * 20];
    const int K = 256;
    const int tid  = threadIdx.x;
    const int wid  = tid >> 5;
    const int lane = tid & 31;
    const int g    = lane >> 2;
    const int t4   = lane & 3;
    const int wm   = (wid >> 1) * 16;
    const int wn   = (wid & 1) * 64;
    const int m0 = blockIdx.y * 64, n0 = blockIdx.x * 128;
    const float* __restrict__ Bmat = (MODE == 0) ? Bsrc : g_attn;
    const size_t bb = (size_t)blockIdx.z * K * Tn;

    const int m_a = tid >> 2, kq_a = (tid & 3) * 8;
    const int kp_b = tid & 15, nq_b = (tid >> 4) & 15;   // per r: idx = tid + r*256

    float4 pa0, pa1;
    float4 pb[2][2];
    // ---- prefetch slice 0 ----
    {
        const float* apt = A + (size_t)(m0 + m_a) * K + kq_a;
        pa0 = *(const float4*)apt; pa1 = *(const float4*)(apt + 4);
        #pragma unroll
        for (int r = 0; r < 2; r++) {
            int idx = tid + r * 256;
            int kp = idx & 15, nq = idx >> 4;
            const float* rp = Bmat + bb + (size_t)(2 * kp) * Tn + n0 + nq * 4;
            pb[r][0] = *(const float4*)rp;
            pb[r][1] = *(const float4*)(rp + Tn);
        }
    }

    float acc[8][4] = {};
    for (int k0 = 0; k0 < K; k0 += 32) {
        // ---- store prefetched slice k0 into smem ----
        {
            uint4 pk4;
            pk4.x = pack_bf2(pa0.x, pa0.y); pk4.y = pack_bf2(pa0.z, pa0.w);
            pk4.z = pack_bf2(pa1.x, pa1.y); pk4.w = pack_bf2(pa1.z, pa1.w);
            *(uint4*)&as_u[m_a * 20 + kq_a / 2] = pk4;
            #pragma unroll
            for (int r = 0; r < 2; r++) {
                int idx = tid + r * 256;
                int kp = idx & 15, nq = idx >> 4;
                int c0 = k0 + 2 * kp;
                float wc0 = 1.f, bc0 = 0.f, wc1 = 1.f, bc1 = 0.f;
                if (MODE == 0) {
                    float2 st = g_stats[(blockIdx.z << 5) + (c0 >> 3)];
                    wc0 = nw[c0] * st.y;     bc0 = nb[c0] - st.x * wc0;
                    wc1 = nw[c0 + 1] * st.y; bc1 = nb[c0 + 1] - st.x * wc1;
                }
                float4 va = pb[r][0], vb4 = pb[r][1];
                int nbase = (nq * 4) * 20 + kp;
                bs_u[nbase     ] = pack_bf2(va.x * wc0 + bc0, vb4.x * wc1 + bc1);
                bs_u[nbase + 20] = pack_bf2(va.y * wc0 + bc0, vb4.y * wc1 + bc1);
                bs_u[nbase + 40] = pack_bf2(va.z * wc0 + bc0, vb4.z * wc1 + bc1);
                bs_u[nbase + 60] = pack_bf2(va.w * wc0 + bc0, vb4.w * wc1 + bc1);
            }
        }
        __syncthreads();
        // ---- issue prefetch for next slice (overlaps the MMAs below) ----
        if (k0 + 32 < K) {
            const float* apt = A + (size_t)(m0 + m_a) * K + k0 + 32 + kq_a;
            pa0 = *(const float4*)apt; pa1 = *(const float4*)(apt + 4);
            #pragma unroll
            for (int r = 0; r < 2; r++) {
                int idx = tid + r * 256;
                int kp = idx & 15, nq = idx >> 4;
                const float* rp = Bmat + bb + (size_t)(k0 + 32 + 2 * kp) * Tn + n0 + nq * 4;
                pb[r][0] = *(const float4*)rp;
                pb[r][1] = *(const float4*)(rp + Tn);
            }
        }
        // ---- MMAs on current slice ----
        #pragma unroll
        for (int kk = 0; kk < 2; kk++) {
            unsigned a0 = as_u[(wm + g    ) * 20 + kk * 8 + t4    ];
            unsigned a1 = as_u[(wm + g + 8) * 20 + kk * 8 + t4    ];
            unsigned a2 = as_u[(wm + g    ) * 20 + kk * 8 + t4 + 4];
            unsigned a3 = as_u[(wm + g + 8) * 20 + kk * 8 + t4 + 4];
            #pragma unroll
            for (int n = 0; n < 8; n++) {
                unsigned b0 = bs_u[(wn + n * 8 + g) * 20 + kk * 8 + t4    ];
                unsigned b1 = bs_u[(wn + n * 8 + g) * 20 + kk * 8 + t4 + 4];
                mma_bf16(acc[n], a0, a1, a2, a3, b0, b1);
            }
        }
        __syncthreads();
    }

    const int mrow0 = m0 + wm + g;
    const int mrow1 = mrow0 + 8;
    float bi0 = bias[mrow0], bi1 = bias[mrow1];

    if (MODE == 0) {
        const int cls = (m0 % 192) / 64;        // 0=q, 1=k, 2=v
        const int hh  = mrow0 / 192;
        const int bh  = blockIdx.z * 4 + hh;
        if (cls != 2) {
            const int of0 = mrow0 % 192 - cls * 64;
            const int of1 = of0 + 8;
            __nv_bfloat16* dst = (cls == 0 ? g_qb : g_kb)
                               + ((size_t)bh * Tn + n0 + wn) * 64;
            #pragma unroll
            for (int n = 0; n < 8; n++) {
                int col = n * 8 + 2 * t4;
                dst[(size_t)(col    ) * 64 + of0] = __float2bfloat16((acc[n][0] + bi0) * SCALE_QK);
                dst[(size_t)(col + 1) * 64 + of0] = __float2bfloat16((acc[n][1] + bi0) * SCALE_QK);
                dst[(size_t)(col    ) * 64 + of1] = __float2bfloat16((acc[n][2] + bi1) * SCALE_QK);
                dst[(size_t)(col + 1) * 64 + of1] = __float2bfloat16((acc[n][3] + bi1) * SCALE_QK);
            }
        } else {
            const int c0 = mrow0 % 192 - 128;
            unsigned* d0 = (unsigned*)(g_vh + ((size_t)bh * 64 + c0    ) * Tn + n0 + wn);
            unsigned* d1 = (unsigned*)(g_vh + ((size_t)bh * 64 + c0 + 8) * Tn + n0 + wn);
            #pragma unroll
            for (int n = 0; n < 8; n++) {
                int col = n * 8 + 2 * t4;
                d0[col / 2] = pack_h2(acc[n][0] + bi0, acc[n][1] + bi0);
                d1[col / 2] = pack_h2(acc[n][2] + bi1, acc[n][3] + bi1);
            }
        }
    } else {
        const size_t o0 = ((size_t)blockIdx.z * Cn + mrow0) * Tn + n0 + wn;
        const size_t o1 = ((size_t)blockIdx.z * Cn + mrow1) * Tn + n0 + wn;
        #pragma unroll
        for (int n = 0; n < 8; n++) {
            int col = n * 8 + 2 * t4;
            *(float2*)(out_param + o0 + col) = make_float2(
                acc[n][0] + bi0 + resid[o0 + col], acc[n][1] + bi0 + resid[o0 + col + 1]);
            *(float2*)(out_param + o1 + col) = make_float2(
                acc[n][2] + bi1 + resid[o1 + col], acc[n][3] + bi1 + resid[o1 + col + 1]);
        }
    }
}

// ============================================================================
// 3) Flash attention, m32-per-warp: 128 threads / 4 warps, each warp owns 32
//    t-rows => every K/V b-fragment feeds 2 MMAs (halved smem traffic).
//    S: bf16 mma. P: fp16 via ex2.approx.f16x2 (p = exp(s-2), exact softmax).
//    PV: fp16 mma; V carries a ones-row block (n-subtile 8) so the MMA
//    accumulates l. Double-buffered K/V, 1 sync/iter.
//    smem u32: K0[2304] K1[2304] | V0[2592] V1[2592], stride 36, conflict-free.
// ============================================================================
#define KBUF 2304
#define VOFF 4608
#define VBUF 2592
#define SMU  (VOFF + 2 * VBUF)    // 9792 u32 = 39168 B

__global__ __launch_bounds__(128, 2) void attn_kernel() {
    extern __shared__ unsigned su[];
    const int tid  = threadIdx.x;
    const int wid  = tid >> 5;
    const int lane = tid & 31;
    const int g    = lane >> 2;
    const int t4   = lane & 3;
    const int tw   = wid * 32;

    const int t0 = blockIdx.x * 128;
    const int bh = blockIdx.y;
    const __nv_bfloat16* qb = g_qb + ((size_t)bh * Tn + t0) * 64;
    const char* kb = (const char*)(g_kb + (size_t)bh * Tn * 64);
    const char* vb = (const char*)(g_vh + (size_t)bh * 64 * Tn);
    float* ap = g_attn + ((size_t)(bh >> 2) * Cn + (bh & 3) * 64) * Tn;

    // ---- prologue: stage Q [t][c/2] stride 36, hoist fragments ----
    #pragma unroll
    for (int r = 0; r < 8; r++) {
        int ch = tid + r * 128;
        int row = ch >> 3, q = ch & 7;
        uint4 v = *(const uint4*)((const char*)qb + ch * 16);
        *(uint4*)&su[row * 36 + q * 4] = v;
    }
    __syncthreads();
    unsigned qf0[4][4], qf1[4][4];
    #pragma unroll
    for (int kk = 0; kk < 4; kk++) {
        qf0[kk][0] = su[(tw + g     ) * 36 + kk * 8 + t4    ];
        qf0[kk][1] = su[(tw + g +  8) * 36 + kk * 8 + t4    ];
        qf0[kk][2] = su[(tw + g     ) * 36 + kk * 8 + t4 + 4];
        qf0[kk][3] = su[(tw + g +  8) * 36 + kk * 8 + t4 + 4];
        qf1[kk][0] = su[(tw + g + 16) * 36 + kk * 8 + t4    ];
        qf1[kk][1] = su[(tw + g + 24) * 36 + kk * 8 + t4    ];
        qf1[kk][2] = su[(tw + g + 16) * 36 + kk * 8 + t4 + 4];
        qf1[kk][3] = su[(tw + g + 24) * 36 + kk * 8 + t4 + 4];
    }
    __syncthreads();

    // ---- ones/zero rows 64-71 of both V buffers + stage tile 0 ----
    for (int idx = tid; idx < 256; idx += 128) {
        int row = 64 + (idx >> 5), col = idx & 31;
        unsigned val = (row == 64) ? 0x3C003C00u : 0u;   // fp16 {1,1} : {0,0}
        su[VOFF        + row * 36 + col] = val;
        su[VOFF + VBUF + row * 36 + col] = val;
    }
    #pragma unroll
    for (int r = 0; r < 4; r++) {
        int ch = tid + r * 128;
        int row = ch >> 3, q = ch & 7;
        uint4 kv = *(const uint4*)(kb + ch * 16);
        *(uint4*)&su[row * 36 + q * 4] = kv;
        uint4 vv = *(const uint4*)(vb + (size_t)row * (Tn * 2) + q * 16);
        *(uint4*)&su[VOFF + row * 36 + q * 4] = vv;
    }
    __syncthreads();

    float acc_o[16][4];
    #pragma unroll
    for (int n = 0; n < 16; n++)
        #pragma unroll
        for (int r = 0; r < 4; r++) acc_o[n][r] = 0.f;
    float acc_l0[4] = {0.f, 0.f, 0.f, 0.f};
    float acc_l1[4] = {0.f, 0.f, 0.f, 0.f};

    for (int i = 0; i < 64; i++) {
        const int cur = i & 1, nxt = cur ^ 1;
        const unsigned* ku = su + cur * KBUF;
        const unsigned* vu = su + VOFF + cur * VBUF;

        // prefetch next tile (global -> regs)
        uint4 pk[4], pv[4];
        if (i < 63) {
            const char* kg = kb + (size_t)(i + 1) * 8192;
            #pragma unroll
            for (int r = 0; r < 4; r++) {
                int ch = tid + r * 128;
                int row = ch >> 3, q = ch & 7;
                pk[r] = *(const uint4*)(kg + ch * 16);
                pv[r] = *(const uint4*)(vb + (size_t)row * (Tn * 2)
                                        + (size_t)(i + 1) * 128 + q * 16);
            }
        }

        // ---- S = Q K^T (bf16), two m-tiles per warp ----
        float sacc[16][4];
        #pragma unroll
        for (int n = 0; n < 16; n++)
            #pragma unroll
            for (int r = 0; r < 4; r++) sacc[n][r] = 0.f;
        #pragma unroll
        for (int kk = 0; kk < 4; kk++) {
            #pragma unroll
            for (int n = 0; n < 8; n++) {
                unsigned b0 = ku[(n * 8 + g) * 36 + kk * 8 + t4    ];
                unsigned b1 = ku[(n * 8 + g) * 36 + kk * 8 + t4 + 4];
                mma_bf16(sacc[2*n    ], qf0[kk][0], qf0[kk][1], qf0[kk][2], qf0[kk][3], b0, b1);
                mma_bf16(sacc[2*n + 1], qf1[kk][0], qf1[kk][1], qf1[kk][2], qf1[kk][3], b0, b1);
            }
        }

        // ---- p = exp(s-2), packed fp16x2 ----
        unsigned pf0[8], pg0[8], pf1[8], pg1[8];
        #pragma unroll
        for (int n = 0; n < 8; n++) {
            {
                float u0 = fmaf(sacc[2*n][0], LOG2E, -EXSHIFT);
                float u1 = fmaf(sacc[2*n][1], LOG2E, -EXSHIFT);
                float u2 = fmaf(sacc[2*n][2], LOG2E, -EXSHIFT);
                float u3 = fmaf(sacc[2*n][3], LOG2E, -EXSHIFT);
                pf0[n] = ex2_f16x2(cvt_f16x2(u1, u0));
                pg0[n] = ex2_f16x2(cvt_f16x2(u3, u2));
            }
            {
                float u0 = fmaf(sacc[2*n+1][0], LOG2E, -EXSHIFT);
                float u1 = fmaf(sacc[2*n+1][1], LOG2E, -EXSHIFT);
                float u2 = fmaf(sacc[2*n+1][2], LOG2E, -EXSHIFT);
                float u3 = fmaf(sacc[2*n+1][3], LOG2E, -EXSHIFT);
                pf1[n] = ex2_f16x2(cvt_f16x2(u1, u0));
                pg1[n] = ex2_f16x2(cvt_f16x2(u3, u2));
            }
        }

        // ---- O += P V^T; l via ones-row block ----
        #pragma unroll
        for (int kk = 0; kk < 4; kk++) {
            unsigned a00 = pf0[2*kk], a01 = pg0[2*kk], a02 = pf0[2*kk+1], a03 = pg0[2*kk+1];
            unsigned a10 = pf1[2*kk], a11 = pg1[2*kk], a12 = pf1[2*kk+1], a13 = pg1[2*kk+1];
            #pragma unroll
            for (int n = 0; n < 8; n++) {
                unsigned b0 = vu[(n * 8 + g) * 36 + kk * 8 + t4    ];
                unsigned b1 = vu[(n * 8 + g) * 36 + kk * 8 + t4 + 4];
                mma_f16(acc_o[2*n    ], a00, a01, a02, a03, b0, b1);
                mma_f16(acc_o[2*n + 1], a10, a11, a12, a13, b0, b1);
            }
            unsigned l0 = vu[(64 + g) * 36 + kk * 8 + t4    ];
            unsigned l1 = vu[(64 + g) * 36 + kk * 8 + t4 + 4];
            mma_f16(acc_l0, a00, a01, a02, a03, l0, l1);
            mma_f16(acc_l1, a10, a11, a12, a13, l0, l1);
        }

        // store prefetched tile into other buffer
        if (i < 63) {
            unsigned* kd = su + nxt * KBUF;
            unsigned* vd = su + VOFF + nxt * VBUF;
            #pragma unroll
            for (int r = 0; r < 4; r++) {
                int ch = tid + r * 128;
                int row = ch >> 3, q = ch & 7;
                *(uint4*)&kd[row * 36 + q * 4] = pk[r];
                *(uint4*)&vd[row * 36 + q * 4] = pv[r];
            }
        }
        __syncthreads();
    }

    // ---- l lives in output column 0 => t4==0 lanes; broadcast within quad --
    const float rl0 = 1.f / __shfl_sync(0xffffffffu, acc_l0[0], lane & ~3);
    const float rl1 = 1.f / __shfl_sync(0xffffffffu, acc_l0[2], lane & ~3);
    const float rl2 = 1.f / __shfl_sync(0xffffffffu, acc_l1[0], lane & ~3);
    const float rl3 = 1.f / __shfl_sync(0xffffffffu, acc_l1[2], lane & ~3);

    // ---- stage O as [c][t] (stride 132), coalesced writeback ----
    float* o_sm = (float*)su;
    #pragma unroll
    for (int n = 0; n < 8; n++) {
        int c = n * 8 + 2 * t4;
        o_sm[(c    ) * 132 + tw + g     ] = acc_o[2*n  ][0] * rl0;
        o_sm[(c + 1) * 132 + tw + g     ] = acc_o[2*n  ][1] * rl0;
        o_sm[(c    ) * 132 + tw + g +  8] = acc_o[2*n  ][2] * rl1;
        o_sm[(c + 1) * 132 + tw + g +  8] = acc_o[2*n  ][3] * rl1;
        o_sm[(c    ) * 132 + tw + g + 16] = acc_o[2*n+1][0] * rl2;
        o_sm[(c + 1) * 132 + tw + g + 16] = acc_o[2*n+1][1] * rl2;
        o_sm[(c    ) * 132 + tw + g + 24] = acc_o[2*n+1][2] * rl3;
        o_sm[(c + 1) * 132 + tw + g + 24] = acc_o[2*n+1][3] * rl3;
    }
    __syncthreads();
    for (int idx = tid; idx < 2048; idx += 128) {
        int c = idx >> 5, tj = (idx & 31) * 4;
        float4 o4 = *(float4*)&o_sm[c * 132 + tj];
        *(float4*)(ap + (size_t)c * Tn + t0 + tj) = o4;
    }
}

// ============================================================================
extern "C" void kernel_launch(void* const* d_in, const int* in_sizes, int n_in,
                              void* d_out, int out_size) {
    const float* x     = (const float*)d_in[0];
    const float* nw    = (const float*)d_in[1];
    const float* nb    = (const float*)d_in[2];
    const float* qkvw  = (const float*)d_in[3];
    const float* qkvb  = (const float*)d_in[4];
    const float* projw = (const float*)d_in[5];
    const float* projb = (const float*)d_in[6];
    float* out = (float*)d_out;

    const int ATTN_SMEM = SMU * 4;   // 39168 B
    cudaFuncSetAttribute(attn_kernel, cudaFuncAttributeMaxDynamicSharedMemorySize,
                         ATTN_SMEM);

    gn_stats_kernel<<<Bn * 32, 512>>>(x);
    gemm_bf<0><<<dim3(Tn / 128, 768 / 64, Bn), 256>>>(qkvw, qkvb, x, nw, nb,
                                                      nullptr, nullptr);
    attn_kernel<<<dim3(Tn / 128, Bn * 4), 128, ATTN_SMEM>>>();
    gemm_bf<1><<<dim3(Tn / 128, Cn / 64, Bn), 256>>>(projw, projb, nullptr, nullptr,
                                                     nullptr, x, out);
}

// round 10
// speedup vs baseline: 11.5377x; 1.0830x over previous
#include <cuda_runtime.h>
#include <cuda_bf16.h>
#include <cuda_fp16.h>
#include <cstdint>
#include <math.h>

#define Tn 4096
#define Cn 256
#define Bn 2
#define SCALE_QK 0.35355339059327373f   // 64^-0.25
#define LOG2E    1.4426950408889634f
// exp(s-2) = 2^(s*LOG2E - 2*LOG2E); 2*LOG2E = 2.8853900817779268
#define EXSHIFT  2.8853900817779268f

// ---- scratch (__device__ globals: allocation-free) ----
__device__ float         g_attn [Bn * Cn * Tn];     // attention out  [B,256,T]
__device__ float2        g_stats[Bn * 32];          // per (b,group): mean, rstd
__device__ __nv_bfloat16 g_qb   [Bn * 4 * Tn * 64]; // q [bh][t][c] bf16 scaled
__device__ __nv_bfloat16 g_kb   [Bn * 4 * Tn * 64]; // k [bh][s][c] bf16 scaled
__device__ __half        g_vh   [Bn * 4 * 64 * Tn]; // v [bh][c][t] fp16

// ---- helpers ----
__device__ __forceinline__ unsigned pack_bf2(float a, float b) {
    __nv_bfloat162 h = __floats2bfloat162_rn(a, b);
    return *(unsigned*)&h;
}
__device__ __forceinline__ unsigned pack_h2(float a, float b) {
    __half2 h = __floats2half2_rn(a, b);
    return *(unsigned*)&h;
}
__device__ __forceinline__ unsigned cvt_f16x2(float hi, float lo) {
    unsigned d;
    asm("cvt.rn.f16x2.f32 %0, %1, %2;" : "=r"(d) : "f"(hi), "f"(lo));
    return d;
}
__device__ __forceinline__ unsigned ex2_f16x2(unsigned a) {
    unsigned d;
    asm("ex2.approx.f16x2 %0, %1;" : "=r"(d) : "r"(a));
    return d;
}
__device__ __forceinline__ void mma_bf16(float c[4],
                                         unsigned a0, unsigned a1, unsigned a2, unsigned a3,
                                         unsigned b0, unsigned b1) {
    asm volatile(
        "mma.sync.aligned.m16n8k16.row.col.f32.bf16.bf16.f32 "
        "{%0,%1,%2,%3},{%4,%5,%6,%7},{%8,%9},{%0,%1,%2,%3};"
        : "+f"(c[0]), "+f"(c[1]), "+f"(c[2]), "+f"(c[3])
        : "r"(a0), "r"(a1), "r"(a2), "r"(a3), "r"(b0), "r"(b1));
}
__device__ __forceinline__ void mma_f16(float c[4],
                                        unsigned a0, unsigned a1, unsigned a2, unsigned a3,
                                        unsigned b0, unsigned b1) {
    asm volatile(
        "mma.sync.aligned.m16n8k16.row.col.f32.f16.f16.f32 "
        "{%0,%1,%2,%3},{%4,%5,%6,%7},{%8,%9},{%0,%1,%2,%3};"
        : "+f"(c[0]), "+f"(c[1]), "+f"(c[2]), "+f"(c[3])
        : "r"(a0), "r"(a1), "r"(a2), "r"(a3), "r"(b0), "r"(b1));
}

// ============================================================================
// 1) GroupNorm stats only: grid 64 (b,g), 512 threads. Writes (mean, rstd).
// ============================================================================
__global__ __launch_bounds__(512) void gn_stats_kernel(const float* __restrict__ x) {
    const int b = blockIdx.x >> 5;
    const int g = blockIdx.x & 31;
    const size_t base = ((size_t)b * Cn + g * 8) * Tn;
    const float4* xp = (const float4*)(x + base);
    const int N4 = 8 * Tn / 4;  // 8192

    float s = 0.f, s2 = 0.f;
    for (int i = threadIdx.x; i < N4; i += 512) {
        float4 v = xp[i];
        s  += v.x + v.y + v.z + v.w;
        s2 += v.x*v.x + v.y*v.y + v.z*v.z + v.w*v.w;
    }
    __shared__ float rs[512], rs2[512];
    rs[threadIdx.x] = s; rs2[threadIdx.x] = s2;
    __syncthreads();
    for (int off = 256; off > 0; off >>= 1) {
        if (threadIdx.x < off) {
            rs [threadIdx.x] += rs [threadIdx.x + off];
            rs2[threadIdx.x] += rs2[threadIdx.x + off];
        }
        __syncthreads();
    }
    if (threadIdx.x == 0) {
        const float inv  = 1.f / (8.f * Tn);
        const float mean = rs[0] * inv;
        const float var  = rs2[0] * inv - mean * mean;
        g_stats[blockIdx.x] = make_float2(mean, rsqrtf(var + 1e-5f));
    }
}

// ============================================================================
// 2/4) bf16 tensor-core GEMM, K=256, software-pipelined, COALESCED B staging:
//   thread -> (k-pair, 2 n-cols): warp reads two contiguous 256B spans.
//   Block 64m x 128n, 8 warps (4m x 2n), K-slice 32.
//   MODE 0: A=qkv_w, B = groupnorm(x) on the fly; q/k -> g_qb/g_kb bf16
//           [bh][t][c] scaled; v -> g_vh fp16 [bh][c][t].
//   MODE 1: A=proj_w, B = g_attn (device-side symbol); out = proj+bias+resid.
// ============================================================================
template<int MODE>
__global__ __launch_bounds__(256, 2) void gemm_bf(const float* __restrict__ A,
                                                  const float* __restrict__ bias,
                                                  const float* __restrict__ Bsrc,
                                                  const float* __restrict__ nw,
                                                  const float* __restrict__ nb,
                                                  const float* __restrict__ resid,
                                                  float* __restrict__ out_param) {
    __shared__ unsigned as_u[64 * 20];
    __shared__ unsigned bs_u[128 * 20];
    const int K = 256;
    const int tid  = threadIdx.x;
    const int wid  = tid >> 5;
    const int lane = tid & 31;
    const int g    = lane >> 2;
    const int t4   = lane & 3;
    const int wm   = (wid >> 1) * 16;
    const int wn   = (wid & 1) * 64;
    const int m0 = blockIdx.y * 64, n0 = blockIdx.x * 128;
    const float* __restrict__ Bmat = (MODE == 0) ? Bsrc : g_attn;
    const size_t bb = (size_t)blockIdx.z * K * Tn;

    const int m_a = tid >> 2, kq_a = (tid & 3) * 8;

    float4 pa0, pa1;
    float2 pbA[4], pbB[4];   // rows k and k+1, 2 n-cols each, 4 passes
    // ---- prefetch slice 0 ----
    {
        const float* apt = A + (size_t)(m0 + m_a) * K + kq_a;
        pa0 = *(const float4*)apt; pa1 = *(const float4*)(apt + 4);
        #pragma unroll
        for (int r = 0; r < 4; r++) {
            int idx = tid + r * 256;            // [0,1024)
            int kp = idx >> 6;                  // 0..15 (k-pair)
            int nn = (idx & 63) * 2;            // 0..126
            const float* rp = Bmat + bb + (size_t)(2 * kp) * Tn + n0 + nn;
            pbA[r] = *(const float2*)rp;
            pbB[r] = *(const float2*)(rp + Tn);
        }
    }

    float acc[8][4] = {};
    for (int k0 = 0; k0 < K; k0 += 32) {
        // ---- store prefetched slice k0 into smem ----
        {
            uint4 pk4;
            pk4.x = pack_bf2(pa0.x, pa0.y); pk4.y = pack_bf2(pa0.z, pa0.w);
            pk4.z = pack_bf2(pa1.x, pa1.y); pk4.w = pack_bf2(pa1.z, pa1.w);
            *(uint4*)&as_u[m_a * 20 + kq_a / 2] = pk4;
            #pragma unroll
            for (int r = 0; r < 4; r++) {
                int idx = tid + r * 256;
                int kp = idx >> 6;
                int nn = (idx & 63) * 2;
                int c0 = k0 + 2 * kp;
                float wc0 = 1.f, bc0 = 0.f, wc1 = 1.f, bc1 = 0.f;
                if (MODE == 0) {
                    float2 st = g_stats[(blockIdx.z << 5) + (c0 >> 3)];
                    wc0 = nw[c0] * st.y;     bc0 = nb[c0] - st.x * wc0;
                    wc1 = nw[c0 + 1] * st.y; bc1 = nb[c0 + 1] - st.x * wc1;
                }
                bs_u[(nn    ) * 20 + kp] =
                    pack_bf2(pbA[r].x * wc0 + bc0, pbB[r].x * wc1 + bc1);
                bs_u[(nn + 1) * 20 + kp] =
                    pack_bf2(pbA[r].y * wc0 + bc0, pbB[r].y * wc1 + bc1);
            }
        }
        __syncthreads();
        // ---- issue prefetch for next slice (overlaps the MMAs below) ----
        if (k0 + 32 < K) {
            const float* apt = A + (size_t)(m0 + m_a) * K + k0 + 32 + kq_a;
            pa0 = *(const float4*)apt; pa1 = *(const float4*)(apt + 4);
            #pragma unroll
            for (int r = 0; r < 4; r++) {
                int idx = tid + r * 256;
                int kp = idx >> 6;
                int nn = (idx & 63) * 2;
                const float* rp = Bmat + bb + (size_t)(k0 + 32 + 2 * kp) * Tn + n0 + nn;
                pbA[r] = *(const float2*)rp;
                pbB[r] = *(const float2*)(rp + Tn);
            }
        }
        // ---- MMAs on current slice ----
        #pragma unroll
        for (int kk = 0; kk < 2; kk++) {
            unsigned a0 = as_u[(wm + g    ) * 20 + kk * 8 + t4    ];
            unsigned a1 = as_u[(wm + g + 8) * 20 + kk * 8 + t4    ];
            unsigned a2 = as_u[(wm + g    ) * 20 + kk * 8 + t4 + 4];
            unsigned a3 = as_u[(wm + g + 8) * 20 + kk * 8 + t4 + 4];
            #pragma unroll
            for (int n = 0; n < 8; n++) {
                unsigned b0 = bs_u[(wn + n * 8 + g) * 20 + kk * 8 + t4    ];
                unsigned b1 = bs_u[(wn + n * 8 + g) * 20 + kk * 8 + t4 + 4];
                mma_bf16(acc[n], a0, a1, a2, a3, b0, b1);
            }
        }
        __syncthreads();
    }

    const int mrow0 = m0 + wm + g;
    const int mrow1 = mrow0 + 8;
    float bi0 = bias[mrow0], bi1 = bias[mrow1];

    if (MODE == 0) {
        const int cls = (m0 % 192) / 64;        // 0=q, 1=k, 2=v
        const int hh  = mrow0 / 192;
        const int bh  = blockIdx.z * 4 + hh;
        if (cls != 2) {
            const int of0 = mrow0 % 192 - cls * 64;
            const int of1 = of0 + 8;
            __nv_bfloat16* dst = (cls == 0 ? g_qb : g_kb)
                               + ((size_t)bh * Tn + n0 + wn) * 64;
            #pragma unroll
            for (int n = 0; n < 8; n++) {
                int col = n * 8 + 2 * t4;
                dst[(size_t)(col    ) * 64 + of0] = __float2bfloat16((acc[n][0] + bi0) * SCALE_QK);
                dst[(size_t)(col + 1) * 64 + of0] = __float2bfloat16((acc[n][1] + bi0) * SCALE_QK);
                dst[(size_t)(col    ) * 64 + of1] = __float2bfloat16((acc[n][2] + bi1) * SCALE_QK);
                dst[(size_t)(col + 1) * 64 + of1] = __float2bfloat16((acc[n][3] + bi1) * SCALE_QK);
            }
        } else {
            const int c0 = mrow0 % 192 - 128;
            unsigned* d0 = (unsigned*)(g_vh + ((size_t)bh * 64 + c0    ) * Tn + n0 + wn);
            unsigned* d1 = (unsigned*)(g_vh + ((size_t)bh * 64 + c0 + 8) * Tn + n0 + wn);
            #pragma unroll
            for (int n = 0; n < 8; n++) {
                int col = n * 8 + 2 * t4;
                d0[col / 2] = pack_h2(acc[n][0] + bi0, acc[n][1] + bi0);
                d1[col / 2] = pack_h2(acc[n][2] + bi1, acc[n][3] + bi1);
            }
        }
    } else {
        const size_t o0 = ((size_t)blockIdx.z * Cn + mrow0) * Tn + n0 + wn;
        const size_t o1 = ((size_t)blockIdx.z * Cn + mrow1) * Tn + n0 + wn;
        #pragma unroll
        for (int n = 0; n < 8; n++) {
            int col = n * 8 + 2 * t4;
            *(float2*)(out_param + o0 + col) = make_float2(
                acc[n][0] + bi0 + resid[o0 + col], acc[n][1] + bi0 + resid[o0 + col + 1]);
            *(float2*)(out_param + o1 + col) = make_float2(
                acc[n][2] + bi1 + resid[o1 + col], acc[n][3] + bi1 + resid[o1 + col + 1]);
        }
    }
}

// ============================================================================
// 3) Flash attention, m32-per-warp (unchanged from R9): 128 threads / 4 warps,
//    each warp owns 32 t-rows. S: bf16 mma. P: fp16 via ex2.approx.f16x2
//    (p = exp(s-2), exact softmax). PV: fp16 mma; V carries a ones-row block
//    so the MMA accumulates l. Double-buffered K/V, 1 sync/iter.
// ============================================================================
#define KBUF 2304
#define VOFF 4608
#define VBUF 2592
#define SMU  (VOFF + 2 * VBUF)    // 9792 u32 = 39168 B

__global__ __launch_bounds__(128, 2) void attn_kernel() {
    extern __shared__ unsigned su[];
    const int tid  = threadIdx.x;
    const int wid  = tid >> 5;
    const int lane = tid & 31;
    const int g    = lane >> 2;
    const int t4   = lane & 3;
    const int tw   = wid * 32;

    const int t0 = blockIdx.x * 128;
    const int bh = blockIdx.y;
    const __nv_bfloat16* qb = g_qb + ((size_t)bh * Tn + t0) * 64;
    const char* kb = (const char*)(g_kb + (size_t)bh * Tn * 64);
    const char* vb = (const char*)(g_vh + (size_t)bh * 64 * Tn);
    float* ap = g_attn + ((size_t)(bh >> 2) * Cn + (bh & 3) * 64) * Tn;

    // ---- prologue: stage Q [t][c/2] stride 36, hoist fragments ----
    #pragma unroll
    for (int r = 0; r < 8; r++) {
        int ch = tid + r * 128;
        int row = ch >> 3, q = ch & 7;
        uint4 v = *(const uint4*)((const char*)qb + ch * 16);
        *(uint4*)&su[row * 36 + q * 4] = v;
    }
    __syncthreads();
    unsigned qf0[4][4], qf1[4][4];
    #pragma unroll
    for (int kk = 0; kk < 4; kk++) {
        qf0[kk][0] = su[(tw + g     ) * 36 + kk * 8 + t4    ];
        qf0[kk][1] = su[(tw + g +  8) * 36 + kk * 8 + t4    ];
        qf0[kk][2] = su[(tw + g     ) * 36 + kk * 8 + t4 + 4];
        qf0[kk][3] = su[(tw + g +  8) * 36 + kk * 8 + t4 + 4];
        qf1[kk][0] = su[(tw + g + 16) * 36 + kk * 8 + t4    ];
        qf1[kk][1] = su[(tw + g + 24) * 36 + kk * 8 + t4    ];
        qf1[kk][2] = su[(tw + g + 16) * 36 + kk * 8 + t4 + 4];
        qf1[kk][3] = su[(tw + g + 24) * 36 + kk * 8 + t4 + 4];
    }
    __syncthreads();

    // ---- ones/zero rows 64-71 of both V buffers + stage tile 0 ----
    for (int idx = tid; idx < 256; idx += 128) {
        int row = 64 + (idx >> 5), col = idx & 31;
        unsigned val = (row == 64) ? 0x3C003C00u : 0u;   // fp16 {1,1} : {0,0}
        su[VOFF        + row * 36 + col] = val;
        su[VOFF + VBUF + row * 36 + col] = val;
    }
    #pragma unroll
    for (int r = 0; r < 4; r++) {
        int ch = tid + r * 128;
        int row = ch >> 3, q = ch & 7;
        uint4 kv = *(const uint4*)(kb + ch * 16);
        *(uint4*)&su[row * 36 + q * 4] = kv;
        uint4 vv = *(const uint4*)(vb + (size_t)row * (Tn * 2) + q * 16);
        *(uint4*)&su[VOFF + row * 36 + q * 4] = vv;
    }
    __syncthreads();

    float acc_o[16][4];
    #pragma unroll
    for (int n = 0; n < 16; n++)
        #pragma unroll
        for (int r = 0; r < 4; r++) acc_o[n][r] = 0.f;
    float acc_l0[4] = {0.f, 0.f, 0.f, 0.f};
    float acc_l1[4] = {0.f, 0.f, 0.f, 0.f};

    for (int i = 0; i < 64; i++) {
        const int cur = i & 1, nxt = cur ^ 1;
        const unsigned* ku = su + cur * KBUF;
        const unsigned* vu = su + VOFF + cur * VBUF;

        // prefetch next tile (global -> regs)
        uint4 pk[4], pv[4];
        if (i < 63) {
            const char* kg = kb + (size_t)(i + 1) * 8192;
            #pragma unroll
            for (int r = 0; r < 4; r++) {
                int ch = tid + r * 128;
                int row = ch >> 3, q = ch & 7;
                pk[r] = *(const uint4*)(kg + ch * 16);
                pv[r] = *(const uint4*)(vb + (size_t)row * (Tn * 2)
                                        + (size_t)(i + 1) * 128 + q * 16);
            }
        }

        // ---- S = Q K^T (bf16), two m-tiles per warp ----
        float sacc[16][4];
        #pragma unroll
        for (int n = 0; n < 16; n++)
            #pragma unroll
            for (int r = 0; r < 4; r++) sacc[n][r] = 0.f;
        #pragma unroll
        for (int kk = 0; kk < 4; kk++) {
            #pragma unroll
            for (int n = 0; n < 8; n++) {
                unsigned b0 = ku[(n * 8 + g) * 36 + kk * 8 + t4    ];
                unsigned b1 = ku[(n * 8 + g) * 36 + kk * 8 + t4 + 4];
                mma_bf16(sacc[2*n    ], qf0[kk][0], qf0[kk][1], qf0[kk][2], qf0[kk][3], b0, b1);
                mma_bf16(sacc[2*n + 1], qf1[kk][0], qf1[kk][1], qf1[kk][2], qf1[kk][3], b0, b1);
            }
        }

        // ---- p = exp(s-2), packed fp16x2 ----
        unsigned pf0[8], pg0[8], pf1[8], pg1[8];
        #pragma unroll
        for (int n = 0; n < 8; n++) {
            {
                float u0 = fmaf(sacc[2*n][0], LOG2E, -EXSHIFT);
                float u1 = fmaf(sacc[2*n][1], LOG2E, -EXSHIFT);
                float u2 = fmaf(sacc[2*n][2], LOG2E, -EXSHIFT);
                float u3 = fmaf(sacc[2*n][3], LOG2E, -EXSHIFT);
                pf0[n] = ex2_f16x2(cvt_f16x2(u1, u0));
                pg0[n] = ex2_f16x2(cvt_f16x2(u3, u2));
            }
            {
                float u0 = fmaf(sacc[2*n+1][0], LOG2E, -EXSHIFT);
                float u1 = fmaf(sacc[2*n+1][1], LOG2E, -EXSHIFT);
                float u2 = fmaf(sacc[2*n+1][2], LOG2E, -EXSHIFT);
                float u3 = fmaf(sacc[2*n+1][3], LOG2E, -EXSHIFT);
                pf1[n] = ex2_f16x2(cvt_f16x2(u1, u0));
                pg1[n] = ex2_f16x2(cvt_f16x2(u3, u2));
            }
        }

        // ---- O += P V^T; l via ones-row block ----
        #pragma unroll
        for (int kk = 0; kk < 4; kk++) {
            unsigned a00 = pf0[2*kk], a01 = pg0[2*kk], a02 = pf0[2*kk+1], a03 = pg0[2*kk+1];
            unsigned a10 = pf1[2*kk], a11 = pg1[2*kk], a12 = pf1[2*kk+1], a13 = pg1[2*kk+1];
            #pragma unroll
            for (int n = 0; n < 8; n++) {
                unsigned b0 = vu[(n * 8 + g) * 36 + kk * 8 + t4    ];
                unsigned b1 = vu[(n * 8 + g) * 36 + kk * 8 + t4 + 4];
                mma_f16(acc_o[2*n    ], a00, a01, a02, a03, b0, b1);
                mma_f16(acc_o[2*n + 1], a10, a11, a12, a13, b0, b1);
            }
            unsigned l0 = vu[(64 + g) * 36 + kk * 8 + t4    ];
            unsigned l1 = vu[(64 + g) * 36 + kk * 8 + t4 + 4];
            mma_f16(acc_l0, a00, a01, a02, a03, l0, l1);
            mma_f16(acc_l1, a10, a11, a12, a13, l0, l1);
        }

        // store prefetched tile into other buffer
        if (i < 63) {
            unsigned* kd = su + nxt * KBUF;
            unsigned* vd = su + VOFF + nxt * VBUF;
            #pragma unroll
            for (int r = 0; r < 4; r++) {
                int ch = tid + r * 128;
                int row = ch >> 3, q = ch & 7;
                *(uint4*)&kd[row * 36 + q * 4] = pk[r];
                *(uint4*)&vd[row * 36 + q * 4] = pv[r];
            }
        }
        __syncthreads();
    }

    // ---- l lives in output column 0 => t4==0 lanes; broadcast within quad --
    const float rl0 = 1.f / __shfl_sync(0xffffffffu, acc_l0[0], lane & ~3);
    const float rl1 = 1.f / __shfl_sync(0xffffffffu, acc_l0[2], lane & ~3);
    const float rl2 = 1.f / __shfl_sync(0xffffffffu, acc_l1[0], lane & ~3);
    const float rl3 = 1.f / __shfl_sync(0xffffffffu, acc_l1[2], lane & ~3);

    // ---- stage O as [c][t] (stride 132), coalesced writeback ----
    float* o_sm = (float*)su;
    #pragma unroll
    for (int n = 0; n < 8; n++) {
        int c = n * 8 + 2 * t4;
        o_sm[(c    ) * 132 + tw + g     ] = acc_o[2*n  ][0] * rl0;
        o_sm[(c + 1) * 132 + tw + g     ] = acc_o[2*n  ][1] * rl0;
        o_sm[(c    ) * 132 + tw + g +  8] = acc_o[2*n  ][2] * rl1;
        o_sm[(c + 1) * 132 + tw + g +  8] = acc_o[2*n  ][3] * rl1;
        o_sm[(c    ) * 132 + tw + g + 16] = acc_o[2*n+1][0] * rl2;
        o_sm[(c + 1) * 132 + tw + g + 16] = acc_o[2*n+1][1] * rl2;
        o_sm[(c    ) * 132 + tw + g + 24] = acc_o[2*n+1][2] * rl3;
        o_sm[(c + 1) * 132 + tw + g + 24] = acc_o[2*n+1][3] * rl3;
    }
    __syncthreads();
    for (int idx = tid; idx < 2048; idx += 128) {
        int c = idx >> 5, tj = (idx & 31) * 4;
        float4 o4 = *(float4*)&o_sm[c * 132 + tj];
        *(float4*)(ap + (size_t)c * Tn + t0 + tj) = o4;
    }
}

// ============================================================================
extern "C" void kernel_launch(void* const* d_in, const int* in_sizes, int n_in,
                              void* d_out, int out_size) {
    const float* x     = (const float*)d_in[0];
    const float* nw    = (const float*)d_in[1];
    const float* nb    = (const float*)d_in[2];
    const float* qkvw  = (const float*)d_in[3];
    const float* qkvb  = (const float*)d_in[4];
    const float* projw = (const float*)d_in[5];
    const float* projb = (const float*)d_in[6];
    float* out = (float*)d_out;

    const int ATTN_SMEM = SMU * 4;   // 39168 B
    cudaFuncSetAttribute(attn_kernel, cudaFuncAttributeMaxDynamicSharedMemorySize,
                         ATTN_SMEM);

    gn_stats_kernel<<<Bn * 32, 512>>>(x);
    gemm_bf<0><<<dim3(Tn / 128, 768 / 64, Bn), 256>>>(qkvw, qkvb, x, nw, nb,
                                                      nullptr, nullptr);
    attn_kernel<<<dim3(Tn / 128, Bn * 4), 128, ATTN_SMEM>>>();
    gemm_bf<1><<<dim3(Tn / 128, Cn / 64, Bn), 256>>>(projw, projb, nullptr, nullptr,
                                                     nullptr, x, out);
}

// round 11
// speedup vs baseline: 11.8138x; 1.0239x over previous
#include <cuda_runtime.h>
#include <cuda_bf16.h>
#include <cuda_fp16.h>
#include <cstdint>
#include <math.h>

#define Tn 4096
#define Cn 256
#define Bn 2
#define SCALE_QK 0.35355339059327373f   // 64^-0.25
#define LOG2E    1.4426950408889634f
// exp(s-2) = 2^(s*LOG2E - 2*LOG2E); 2*LOG2E = 2.8853900817779268
#define EXSHIFT  2.8853900817779268f

// ---- scratch (__device__ globals: allocation-free) ----
__device__ float         g_attn [Bn * Cn * Tn];     // attention out  [B,256,T]
__device__ float2        g_stats[Bn * 32];          // per (b,group): mean, rstd
__device__ __nv_bfloat16 g_qb   [Bn * 4 * Tn * 64]; // q [bh][t][c] bf16 scaled
__device__ __nv_bfloat16 g_kb   [Bn * 4 * Tn * 64]; // k [bh][s][c] bf16 scaled
__device__ __half        g_vh   [Bn * 4 * 64 * Tn]; // v [bh][c][t] fp16

// ---- helpers ----
__device__ __forceinline__ unsigned pack_bf2(float a, float b) {
    __nv_bfloat162 h = __floats2bfloat162_rn(a, b);
    return *(unsigned*)&h;
}
__device__ __forceinline__ unsigned pack_h2(float a, float b) {
    __half2 h = __floats2half2_rn(a, b);
    return *(unsigned*)&h;
}
__device__ __forceinline__ unsigned cvt_f16x2(float hi, float lo) {
    unsigned d;
    asm("cvt.rn.f16x2.f32 %0, %1, %2;" : "=r"(d) : "f"(hi), "f"(lo));
    return d;
}
__device__ __forceinline__ unsigned ex2_f16x2(unsigned a) {
    unsigned d;
    asm("ex2.approx.f16x2 %0, %1;" : "=r"(d) : "r"(a));
    return d;
}
__device__ __forceinline__ void mma_bf16(float c[4],
                                         unsigned a0, unsigned a1, unsigned a2, unsigned a3,
                                         unsigned b0, unsigned b1) {
    asm volatile(
        "mma.sync.aligned.m16n8k16.row.col.f32.bf16.bf16.f32 "
        "{%0,%1,%2,%3},{%4,%5,%6,%7},{%8,%9},{%0,%1,%2,%3};"
        : "+f"(c[0]), "+f"(c[1]), "+f"(c[2]), "+f"(c[3])
        : "r"(a0), "r"(a1), "r"(a2), "r"(a3), "r"(b0), "r"(b1));
}
__device__ __forceinline__ void mma_f16(float c[4],
                                        unsigned a0, unsigned a1, unsigned a2, unsigned a3,
                                        unsigned b0, unsigned b1) {
    asm volatile(
        "mma.sync.aligned.m16n8k16.row.col.f32.f16.f16.f32 "
        "{%0,%1,%2,%3},{%4,%5,%6,%7},{%8,%9},{%0,%1,%2,%3};"
        : "+f"(c[0]), "+f"(c[1]), "+f"(c[2]), "+f"(c[3])
        : "r"(a0), "r"(a1), "r"(a2), "r"(a3), "r"(b0), "r"(b1));
}

// ============================================================================
// 1) GroupNorm stats only: grid 64 (b,g), 512 threads. Writes (mean, rstd).
// ============================================================================
__global__ __launch_bounds__(512) void gn_stats_kernel(const float* __restrict__ x) {
    const int b = blockIdx.x >> 5;
    const int g = blockIdx.x & 31;
    const size_t base = ((size_t)b * Cn + g * 8) * Tn;
    const float4* xp = (const float4*)(x + base);
    const int N4 = 8 * Tn / 4;  // 8192

    float s = 0.f, s2 = 0.f;
    for (int i = threadIdx.x; i < N4; i += 512) {
        float4 v = xp[i];
        s  += v.x + v.y + v.z + v.w;
        s2 += v.x*v.x + v.y*v.y + v.z*v.z + v.w*v.w;
    }
    __shared__ float rs[512], rs2[512];
    rs[threadIdx.x] = s; rs2[threadIdx.x] = s2;
    __syncthreads();
    for (int off = 256; off > 0; off >>= 1) {
        if (threadIdx.x < off) {
            rs [threadIdx.x] += rs [threadIdx.x + off];
            rs2[threadIdx.x] += rs2[threadIdx.x + off];
        }
        __syncthreads();
    }
    if (threadIdx.x == 0) {
        const float inv  = 1.f / (8.f * Tn);
        const float mean = rs[0] * inv;
        const float var  = rs2[0] * inv - mean * mean;
        g_stats[blockIdx.x] = make_float2(mean, rsqrtf(var + 1e-5f));
    }
}

// ============================================================================
// 2/4) bf16 tensor-core GEMM, K=256, PING-PONG double-buffered smem
//   (1 sync/slice: MMAs on buf cur overlap LDG+STS of buf nxt).
//   Block 64m x 128n, 8 warps (4m x 2n), K-slice 32.
//   MODE 0: A=qkv_w, B = groupnorm(x) on the fly; epilogues stage through
//           smem and write fully coalesced rows:
//           q/k -> g_qb/g_kb bf16 [bh][t][c] scaled; v -> g_vh fp16 [bh][c][t].
//   MODE 1: A=proj_w, B = g_attn; out = proj + bias + residual (fp32).
//   smem: 2 x (as 1280 + bs 2560) u32 = 7680 u32; epilogue staging aliases it.
// ============================================================================
template<int MODE>
__global__ __launch_bounds__(256, 2) void gemm_bf(const float* __restrict__ A,
                                                  const float* __restrict__ bias,
                                                  const float* __restrict__ Bsrc,
                                                  const float* __restrict__ nw,
                                                  const float* __restrict__ nb,
                                                  const float* __restrict__ resid,
                                                  float* __restrict__ out_param) {
    __shared__ unsigned smem_all[7680];
    const int K = 256;
    const int tid  = threadIdx.x;
    const int wid  = tid >> 5;
    const int lane = tid & 31;
    const int g    = lane >> 2;
    const int t4   = lane & 3;
    const int wm   = (wid >> 1) * 16;
    const int wn   = (wid & 1) * 64;
    const int m0 = blockIdx.y * 64, n0 = blockIdx.x * 128;
    const float* __restrict__ Bmat = (MODE == 0) ? Bsrc : g_attn;
    const size_t bb = (size_t)blockIdx.z * K * Tn;

    const int m_a = tid >> 2, kq_a = (tid & 3) * 8;

    float4 pa0, pa1;
    float2 pbA[4], pbB[4];

    // ---- prologue: load + stage slice 0 into buf 0 ----
    {
        const float* apt = A + (size_t)(m0 + m_a) * K + kq_a;
        pa0 = *(const float4*)apt; pa1 = *(const float4*)(apt + 4);
        #pragma unroll
        for (int r = 0; r < 4; r++) {
            int idx = tid + r * 256;
            int kp = idx >> 6, nn = (idx & 63) * 2;
            const float* rp = Bmat + bb + (size_t)(2 * kp) * Tn + n0 + nn;
            pbA[r] = *(const float2*)rp;
            pbB[r] = *(const float2*)(rp + Tn);
        }
        unsigned* asn = smem_all;
        unsigned* bsn = smem_all + 1280;
        uint4 pk4;
        pk4.x = pack_bf2(pa0.x, pa0.y); pk4.y = pack_bf2(pa0.z, pa0.w);
        pk4.z = pack_bf2(pa1.x, pa1.y); pk4.w = pack_bf2(pa1.z, pa1.w);
        *(uint4*)&asn[m_a * 20 + kq_a / 2] = pk4;
        #pragma unroll
        for (int r = 0; r < 4; r++) {
            int idx = tid + r * 256;
            int kp = idx >> 6, nn = (idx & 63) * 2;
            int c0 = 2 * kp;
            float wc0 = 1.f, bc0 = 0.f, wc1 = 1.f, bc1 = 0.f;
            if (MODE == 0) {
                float2 st = g_stats[(blockIdx.z << 5) + (c0 >> 3)];
                wc0 = nw[c0] * st.y;     bc0 = nb[c0] - st.x * wc0;
                wc1 = nw[c0 + 1] * st.y; bc1 = nb[c0 + 1] - st.x * wc1;
            }
            bsn[(nn    ) * 20 + kp] = pack_bf2(pbA[r].x * wc0 + bc0, pbB[r].x * wc1 + bc1);
            bsn[(nn + 1) * 20 + kp] = pack_bf2(pbA[r].y * wc0 + bc0, pbB[r].y * wc1 + bc1);
        }
    }
    __syncthreads();

    float acc[8][4] = {};
    #pragma unroll
    for (int s = 0; s < 8; s++) {
        unsigned* asb = smem_all + (s & 1) * 3840;
        unsigned* bsb = asb + 1280;
        const int k1 = (s + 1) * 32;
        // ---- issue LDG for slice s+1 ----
        if (s < 7) {
            const float* apt = A + (size_t)(m0 + m_a) * K + k1 + kq_a;
            pa0 = *(const float4*)apt; pa1 = *(const float4*)(apt + 4);
            #pragma unroll
            for (int r = 0; r < 4; r++) {
                int idx = tid + r * 256;
                int kp = idx >> 6, nn = (idx & 63) * 2;
                const float* rp = Bmat + bb + (size_t)(k1 + 2 * kp) * Tn + n0 + nn;
                pbA[r] = *(const float2*)rp;
                pbB[r] = *(const float2*)(rp + Tn);
            }
        }
        // ---- MMAs on slice s (buf cur) ----
        #pragma unroll
        for (int kk = 0; kk < 2; kk++) {
            unsigned a0 = asb[(wm + g    ) * 20 + kk * 8 + t4    ];
            unsigned a1 = asb[(wm + g + 8) * 20 + kk * 8 + t4    ];
            unsigned a2 = asb[(wm + g    ) * 20 + kk * 8 + t4 + 4];
            unsigned a3 = asb[(wm + g + 8) * 20 + kk * 8 + t4 + 4];
            #pragma unroll
            for (int n = 0; n < 8; n++) {
                unsigned b0 = bsb[(wn + n * 8 + g) * 20 + kk * 8 + t4    ];
                unsigned b1 = bsb[(wn + n * 8 + g) * 20 + kk * 8 + t4 + 4];
                mma_bf16(acc[n], a0, a1, a2, a3, b0, b1);
            }
        }
        // ---- stage slice s+1 into buf nxt ----
        if (s < 7) {
            unsigned* asn = smem_all + ((s + 1) & 1) * 3840;
            unsigned* bsn = asn + 1280;
            uint4 pk4;
            pk4.x = pack_bf2(pa0.x, pa0.y); pk4.y = pack_bf2(pa0.z, pa0.w);
            pk4.z = pack_bf2(pa1.x, pa1.y); pk4.w = pack_bf2(pa1.z, pa1.w);
            *(uint4*)&asn[m_a * 20 + kq_a / 2] = pk4;
            #pragma unroll
            for (int r = 0; r < 4; r++) {
                int idx = tid + r * 256;
                int kp = idx >> 6, nn = (idx & 63) * 2;
                int c0 = k1 + 2 * kp;
                float wc0 = 1.f, bc0 = 0.f, wc1 = 1.f, bc1 = 0.f;
                if (MODE == 0) {
                    float2 st = g_stats[(blockIdx.z << 5) + (c0 >> 3)];
                    wc0 = nw[c0] * st.y;     bc0 = nb[c0] - st.x * wc0;
                    wc1 = nw[c0 + 1] * st.y; bc1 = nb[c0 + 1] - st.x * wc1;
                }
                bsn[(nn    ) * 20 + kp] = pack_bf2(pbA[r].x * wc0 + bc0, pbB[r].x * wc1 + bc1);
                bsn[(nn + 1) * 20 + kp] = pack_bf2(pbA[r].y * wc0 + bc0, pbB[r].y * wc1 + bc1);
            }
        }
        __syncthreads();
    }

    const int mrow0 = m0 + wm + g;
    const int mrow1 = mrow0 + 8;
    float bi0 = bias[mrow0], bi1 = bias[mrow1];

    if (MODE == 0) {
        const int cls = (m0 % 192) / 64;        // 0=q, 1=k, 2=v
        const int bh  = blockIdx.z * 4 + (m0 / 192);
        const int c0  = wm + g;
        if (cls != 2) {
            // stage [t][c] bf16 (row stride 80 bf16 = 160 B), coalesced out
            __nv_bfloat16* sm_bf = (__nv_bfloat16*)smem_all;
            #pragma unroll
            for (int n = 0; n < 8; n++) {
                int t = wn + n * 8 + 2 * t4;
                sm_bf[(t    ) * 80 + c0    ] = __float2bfloat16((acc[n][0] + bi0) * SCALE_QK);
                sm_bf[(t + 1) * 80 + c0    ] = __float2bfloat16((acc[n][1] + bi0) * SCALE_QK);
                sm_bf[(t    ) * 80 + c0 + 8] = __float2bfloat16((acc[n][2] + bi1) * SCALE_QK);
                sm_bf[(t + 1) * 80 + c0 + 8] = __float2bfloat16((acc[n][3] + bi1) * SCALE_QK);
            }
            __syncthreads();
            char* dstb = (char*)((cls == 0 ? g_qb : g_kb) + (size_t)bh * Tn * 64);
            #pragma unroll
            for (int r = 0; r < 4; r++) {
                int ch = tid + r * 256;
                int trow = ch >> 3, qc = ch & 7;
                uint4 v = *(uint4*)((char*)sm_bf + trow * 160 + qc * 16);
                *(uint4*)(dstb + (size_t)(n0 + trow) * 128 + qc * 16) = v;
            }
        } else {
            // stage [c][t/2] u32 (row stride 72 u32 = 288 B), coalesced out
            unsigned* sm_v = smem_all;
            #pragma unroll
            for (int n = 0; n < 8; n++) {
                int th = wn / 2 + n * 4 + t4;
                sm_v[(c0    ) * 72 + th] = pack_h2(acc[n][0] + bi0, acc[n][1] + bi0);
                sm_v[(c0 + 8) * 72 + th] = pack_h2(acc[n][2] + bi1, acc[n][3] + bi1);
            }
            __syncthreads();
            char* vbase = (char*)(g_vh + (size_t)bh * 64 * Tn);
            #pragma unroll
            for (int r = 0; r < 4; r++) {
                int ch = tid + r * 256;
                int row = ch >> 4, qc = ch & 15;
                uint4 v = *(uint4*)((char*)sm_v + row * 288 + qc * 16);
                *(uint4*)(vbase + (size_t)row * (Tn * 2) + (size_t)n0 * 2 + qc * 16) = v;
            }
        }
    } else {
        const size_t o0 = ((size_t)blockIdx.z * Cn + mrow0) * Tn + n0 + wn;
        const size_t o1 = ((size_t)blockIdx.z * Cn + mrow1) * Tn + n0 + wn;
        #pragma unroll
        for (int n = 0; n < 8; n++) {
            int col = n * 8 + 2 * t4;
            *(float2*)(out_param + o0 + col) = make_float2(
                acc[n][0] + bi0 + resid[o0 + col], acc[n][1] + bi0 + resid[o0 + col + 1]);
            *(float2*)(out_param + o1 + col) = make_float2(
                acc[n][2] + bi1 + resid[o1 + col], acc[n][3] + bi1 + resid[o1 + col + 1]);
        }
    }
}

// ============================================================================
// 3) Flash attention, m32-per-warp (unchanged): 128 threads / 4 warps,
//    each warp owns 32 t-rows. S: bf16 mma. P: fp16 via ex2.approx.f16x2
//    (p = exp(s-2), exact softmax). PV: fp16 mma; V carries a ones-row block
//    so the MMA accumulates l. Double-buffered K/V, 1 sync/iter.
// ============================================================================
#define KBUF 2304
#define VOFF 4608
#define VBUF 2592
#define SMU  (VOFF + 2 * VBUF)    // 9792 u32 = 39168 B

__global__ __launch_bounds__(128, 2) void attn_kernel() {
    extern __shared__ unsigned su[];
    const int tid  = threadIdx.x;
    const int wid  = tid >> 5;
    const int lane = tid & 31;
    const int g    = lane >> 2;
    const int t4   = lane & 3;
    const int tw   = wid * 32;

    const int t0 = blockIdx.x * 128;
    const int bh = blockIdx.y;
    const __nv_bfloat16* qb = g_qb + ((size_t)bh * Tn + t0) * 64;
    const char* kb = (const char*)(g_kb + (size_t)bh * Tn * 64);
    const char* vb = (const char*)(g_vh + (size_t)bh * 64 * Tn);
    float* ap = g_attn + ((size_t)(bh >> 2) * Cn + (bh & 3) * 64) * Tn;

    // ---- prologue: stage Q [t][c/2] stride 36, hoist fragments ----
    #pragma unroll
    for (int r = 0; r < 8; r++) {
        int ch = tid + r * 128;
        int row = ch >> 3, q = ch & 7;
        uint4 v = *(const uint4*)((const char*)qb + ch * 16);
        *(uint4*)&su[row * 36 + q * 4] = v;
    }
    __syncthreads();
    unsigned qf0[4][4], qf1[4][4];
    #pragma unroll
    for (int kk = 0; kk < 4; kk++) {
        qf0[kk][0] = su[(tw + g     ) * 36 + kk * 8 + t4    ];
        qf0[kk][1] = su[(tw + g +  8) * 36 + kk * 8 + t4    ];
        qf0[kk][2] = su[(tw + g     ) * 36 + kk * 8 + t4 + 4];
        qf0[kk][3] = su[(tw + g +  8) * 36 + kk * 8 + t4 + 4];
        qf1[kk][0] = su[(tw + g + 16) * 36 + kk * 8 + t4    ];
        qf1[kk][1] = su[(tw + g + 24) * 36 + kk * 8 + t4    ];
        qf1[kk][2] = su[(tw + g + 16) * 36 + kk * 8 + t4 + 4];
        qf1[kk][3] = su[(tw + g + 24) * 36 + kk * 8 + t4 + 4];
    }
    __syncthreads();

    // ---- ones/zero rows 64-71 of both V buffers + stage tile 0 ----
    for (int idx = tid; idx < 256; idx += 128) {
        int row = 64 + (idx >> 5), col = idx & 31;
        unsigned val = (row == 64) ? 0x3C003C00u : 0u;   // fp16 {1,1} : {0,0}
        su[VOFF        + row * 36 + col] = val;
        su[VOFF + VBUF + row * 36 + col] = val;
    }
    #pragma unroll
    for (int r = 0; r < 4; r++) {
        int ch = tid + r * 128;
        int row = ch >> 3, q = ch & 7;
        uint4 kv = *(const uint4*)(kb + ch * 16);
        *(uint4*)&su[row * 36 + q * 4] = kv;
        uint4 vv = *(const uint4*)(vb + (size_t)row * (Tn * 2) + q * 16);
        *(uint4*)&su[VOFF + row * 36 + q * 4] = vv;
    }
    __syncthreads();

    float acc_o[16][4];
    #pragma unroll
    for (int n = 0; n < 16; n++)
        #pragma unroll
        for (int r = 0; r < 4; r++) acc_o[n][r] = 0.f;
    float acc_l0[4] = {0.f, 0.f, 0.f, 0.f};
    float acc_l1[4] = {0.f, 0.f, 0.f, 0.f};

    for (int i = 0; i < 64; i++) {
        const int cur = i & 1, nxt = cur ^ 1;
        const unsigned* ku = su + cur * KBUF;
        const unsigned* vu = su + VOFF + cur * VBUF;

        // prefetch next tile (global -> regs)
        uint4 pk[4], pv[4];
        if (i < 63) {
            const char* kg = kb + (size_t)(i + 1) * 8192;
            #pragma unroll
            for (int r = 0; r < 4; r++) {
                int ch = tid + r * 128;
                int row = ch >> 3, q = ch & 7;
                pk[r] = *(const uint4*)(kg + ch * 16);
                pv[r] = *(const uint4*)(vb + (size_t)row * (Tn * 2)
                                        + (size_t)(i + 1) * 128 + q * 16);
            }
        }

        // ---- S = Q K^T (bf16), two m-tiles per warp ----
        float sacc[16][4];
        #pragma unroll
        for (int n = 0; n < 16; n++)
            #pragma unroll
            for (int r = 0; r < 4; r++) sacc[n][r] = 0.f;
        #pragma unroll
        for (int kk = 0; kk < 4; kk++) {
            #pragma unroll
            for (int n = 0; n < 8; n++) {
                unsigned b0 = ku[(n * 8 + g) * 36 + kk * 8 + t4    ];
                unsigned b1 = ku[(n * 8 + g) * 36 + kk * 8 + t4 + 4];
                mma_bf16(sacc[2*n    ], qf0[kk][0], qf0[kk][1], qf0[kk][2], qf0[kk][3], b0, b1);
                mma_bf16(sacc[2*n + 1], qf1[kk][0], qf1[kk][1], qf1[kk][2], qf1[kk][3], b0, b1);
            }
        }

        // ---- p = exp(s-2), packed fp16x2 ----
        unsigned pf0[8], pg0[8], pf1[8], pg1[8];
        #pragma unroll
        for (int n = 0; n < 8; n++) {
            {
                float u0 = fmaf(sacc[2*n][0], LOG2E, -EXSHIFT);
                float u1 = fmaf(sacc[2*n][1], LOG2E, -EXSHIFT);
                float u2 = fmaf(sacc[2*n][2], LOG2E, -EXSHIFT);
                float u3 = fmaf(sacc[2*n][3], LOG2E, -EXSHIFT);
                pf0[n] = ex2_f16x2(cvt_f16x2(u1, u0));
                pg0[n] = ex2_f16x2(cvt_f16x2(u3, u2));
            }
            {
                float u0 = fmaf(sacc[2*n+1][0], LOG2E, -EXSHIFT);
                float u1 = fmaf(sacc[2*n+1][1], LOG2E, -EXSHIFT);
                float u2 = fmaf(sacc[2*n+1][2], LOG2E, -EXSHIFT);
                float u3 = fmaf(sacc[2*n+1][3], LOG2E, -EXSHIFT);
                pf1[n] = ex2_f16x2(cvt_f16x2(u1, u0));
                pg1[n] = ex2_f16x2(cvt_f16x2(u3, u2));
            }
        }

        // ---- O += P V^T; l via ones-row block ----
        #pragma unroll
        for (int kk = 0; kk < 4; kk++) {
            unsigned a00 = pf0[2*kk], a01 = pg0[2*kk], a02 = pf0[2*kk+1], a03 = pg0[2*kk+1];
            unsigned a10 = pf1[2*kk], a11 = pg1[2*kk], a12 = pf1[2*kk+1], a13 = pg1[2*kk+1];
            #pragma unroll
            for (int n = 0; n < 8; n++) {
                unsigned b0 = vu[(n * 8 + g) * 36 + kk * 8 + t4    ];
                unsigned b1 = vu[(n * 8 + g) * 36 + kk * 8 + t4 + 4];
                mma_f16(acc_o[2*n    ], a00, a01, a02, a03, b0, b1);
                mma_f16(acc_o[2*n + 1], a10, a11, a12, a13, b0, b1);
            }
            unsigned l0 = vu[(64 + g) * 36 + kk * 8 + t4    ];
            unsigned l1 = vu[(64 + g) * 36 + kk * 8 + t4 + 4];
            mma_f16(acc_l0, a00, a01, a02, a03, l0, l1);
            mma_f16(acc_l1, a10, a11, a12, a13, l0, l1);
        }

        // store prefetched tile into other buffer
        if (i < 63) {
            unsigned* kd = su + nxt * KBUF;
            unsigned* vd = su + VOFF + nxt * VBUF;
            #pragma unroll
            for (int r = 0; r < 4; r++) {
                int ch = tid + r * 128;
                int row = ch >> 3, q = ch & 7;
                *(uint4*)&kd[row * 36 + q * 4] = pk[r];
                *(uint4*)&vd[row * 36 + q * 4] = pv[r];
            }
        }
        __syncthreads();
    }

    // ---- l lives in output column 0 => t4==0 lanes; broadcast within quad --
    const float rl0 = 1.f / __shfl_sync(0xffffffffu, acc_l0[0], lane & ~3);
    const float rl1 = 1.f / __shfl_sync(0xffffffffu, acc_l0[2], lane & ~3);
    const float rl2 = 1.f / __shfl_sync(0xffffffffu, acc_l1[0], lane & ~3);
    const float rl3 = 1.f / __shfl_sync(0xffffffffu, acc_l1[2], lane & ~3);

    // ---- stage O as [c][t] (stride 132), coalesced writeback ----
    float* o_sm = (float*)su;
    #pragma unroll
    for (int n = 0; n < 8; n++) {
        int c = n * 8 + 2 * t4;
        o_sm[(c    ) * 132 + tw + g     ] = acc_o[2*n  ][0] * rl0;
        o_sm[(c + 1) * 132 + tw + g     ] = acc_o[2*n  ][1] * rl0;
        o_sm[(c    ) * 132 + tw + g +  8] = acc_o[2*n  ][2] * rl1;
        o_sm[(c + 1) * 132 + tw + g +  8] = acc_o[2*n  ][3] * rl1;
        o_sm[(c    ) * 132 + tw + g + 16] = acc_o[2*n+1][0] * rl2;
        o_sm[(c + 1) * 132 + tw + g + 16] = acc_o[2*n+1][1] * rl2;
        o_sm[(c    ) * 132 + tw + g + 24] = acc_o[2*n+1][2] * rl3;
        o_sm[(c + 1) * 132 + tw + g + 24] = acc_o[2*n+1][3] * rl3;
    }
    __syncthreads();
    for (int idx = tid; idx < 2048; idx += 128) {
        int c = idx >> 5, tj = (idx & 31) * 4;
        float4 o4 = *(float4*)&o_sm[c * 132 + tj];
        *(float4*)(ap + (size_t)c * Tn + t0 + tj) = o4;
    }
}

// ============================================================================
extern "C" void kernel_launch(void* const* d_in, const int* in_sizes, int n_in,
                              void* d_out, int out_size) {
    const float* x     = (const float*)d_in[0];
    const float* nw    = (const float*)d_in[1];
    const float* nb    = (const float*)d_in[2];
    const float* qkvw  = (const float*)d_in[3];
    const float* qkvb  = (const float*)d_in[4];
    const float* projw = (const float*)d_in[5];
    const float* projb = (const float*)d_in[6];
    float* out = (float*)d_out;

    const int ATTN_SMEM = SMU * 4;   // 39168 B
    cudaFuncSetAttribute(attn_kernel, cudaFuncAttributeMaxDynamicSharedMemorySize,
                         ATTN_SMEM);

    gn_stats_kernel<<<Bn * 32, 512>>>(x);
    gemm_bf<0><<<dim3(Tn / 128, 768 / 64, Bn), 256>>>(qkvw, qkvb, x, nw, nb,
                                                      nullptr, nullptr);
    attn_kernel<<<dim3(Tn / 128, Bn * 4), 128, ATTN_SMEM>>>();
    gemm_bf<1><<<dim3(Tn / 128, Cn / 64, Bn), 256>>>(projw, projb, nullptr, nullptr,
                                                     nullptr, x, out);
}

// round 12
// speedup vs baseline: 12.6191x; 1.0682x over previous
#include <cuda_runtime.h>
#include <cuda_bf16.h>
#include <cuda_fp16.h>
#include <cstdint>
#include <math.h>

#define Tn 4096
#define Cn 256
#define Bn 2
#define SCALE_QK 0.35355339059327373f   // 64^-0.25
#define LOG2E    1.4426950408889634f
// exp(s-2) = 2^(s*LOG2E - 2*LOG2E); 2*LOG2E = 2.8853900817779268
#define EXSHIFT  2.8853900817779268f

// ---- scratch (__device__ globals: allocation-free) ----
__device__ float         g_attn [Bn * Cn * Tn];     // attention out  [B,256,T]
__device__ float2        g_stats[Bn * 32];          // per (b,group): mean, rstd
__device__ __nv_bfloat16 g_qb   [Bn * 4 * Tn * 64]; // q [bh][t][c] bf16 scaled
__device__ __nv_bfloat16 g_kb   [Bn * 4 * Tn * 64]; // k [bh][s][c] bf16 scaled
__device__ __half        g_vh   [Bn * 4 * 64 * Tn]; // v [bh][c][t] fp16

// ---- helpers ----
__device__ __forceinline__ unsigned pack_bf2(float a, float b) {
    __nv_bfloat162 h = __floats2bfloat162_rn(a, b);
    return *(unsigned*)&h;
}
__device__ __forceinline__ unsigned pack_h2(float a, float b) {
    __half2 h = __floats2half2_rn(a, b);
    return *(unsigned*)&h;
}
__device__ __forceinline__ unsigned cvt_f16x2(float hi, float lo) {
    unsigned d;
    asm("cvt.rn.f16x2.f32 %0, %1, %2;" : "=r"(d) : "f"(hi), "f"(lo));
    return d;
}
__device__ __forceinline__ unsigned ex2_f16x2(unsigned a) {
    unsigned d;
    asm("ex2.approx.f16x2 %0, %1;" : "=r"(d) : "r"(a));
    return d;
}
__device__ __forceinline__ void mma_bf16(float c[4],
                                         unsigned a0, unsigned a1, unsigned a2, unsigned a3,
                                         unsigned b0, unsigned b1) {
    asm volatile(
        "mma.sync.aligned.m16n8k16.row.col.f32.bf16.bf16.f32 "
        "{%0,%1,%2,%3},{%4,%5,%6,%7},{%8,%9},{%0,%1,%2,%3};"
        : "+f"(c[0]), "+f"(c[1]), "+f"(c[2]), "+f"(c[3])
        : "r"(a0), "r"(a1), "r"(a2), "r"(a3), "r"(b0), "r"(b1));
}
__device__ __forceinline__ void mma_f16(float c[4],
                                        unsigned a0, unsigned a1, unsigned a2, unsigned a3,
                                        unsigned b0, unsigned b1) {
    asm volatile(
        "mma.sync.aligned.m16n8k16.row.col.f32.f16.f16.f32 "
        "{%0,%1,%2,%3},{%4,%5,%6,%7},{%8,%9},{%0,%1,%2,%3};"
        : "+f"(c[0]), "+f"(c[1]), "+f"(c[2]), "+f"(c[3])
        : "r"(a0), "r"(a1), "r"(a2), "r"(a3), "r"(b0), "r"(b1));
}

// ============================================================================
// 1) GroupNorm stats only: grid 64 (b,g), 512 threads. Writes (mean, rstd).
// ============================================================================
__global__ __launch_bounds__(512) void gn_stats_kernel(const float* __restrict__ x) {
    const int b = blockIdx.x >> 5;
    const int g = blockIdx.x & 31;
    const size_t base = ((size_t)b * Cn + g * 8) * Tn;
    const float4* xp = (const float4*)(x + base);
    const int N4 = 8 * Tn / 4;  // 8192

    float s = 0.f, s2 = 0.f;
    for (int i = threadIdx.x; i < N4; i += 512) {
        float4 v = xp[i];
        s  += v.x + v.y + v.z + v.w;
        s2 += v.x*v.x + v.y*v.y + v.z*v.z + v.w*v.w;
    }
    __shared__ float rs[512], rs2[512];
    rs[threadIdx.x] = s; rs2[threadIdx.x] = s2;
    __syncthreads();
    for (int off = 256; off > 0; off >>= 1) {
        if (threadIdx.x < off) {
            rs [threadIdx.x] += rs [threadIdx.x + off];
            rs2[threadIdx.x] += rs2[threadIdx.x + off];
        }
        __syncthreads();
    }
    if (threadIdx.x == 0) {
        const float inv  = 1.f / (8.f * Tn);
        const float mean = rs[0] * inv;
        const float var  = rs2[0] * inv - mean * mean;
        g_stats[blockIdx.x] = make_float2(mean, rsqrtf(var + 1e-5f));
    }
}

// ============================================================================
// 2/4) bf16 tensor-core GEMM, K=256, 128m x 128n block tiles, ping-pong smem.
//   8 warps (4m x 2n); warp = m32 x n64 (two m16 subtiles share B frags).
//   MODE 0: A=qkv_w, B = groupnorm(x) on the fly. Each block spans TWO 64-row
//           class bands (q/k/v); each band staged in its own smem half and
//           written coalesced: q/k -> [bh][t][c] bf16 scaled; v -> [bh][c][t] fp16.
//   MODE 1: A=proj_w, B=g_attn; out = proj + bias + residual (fp32).
//   smem: 2 x (A 2560 + B 2560) u32 = 10240 u32 = 40KB; epilogue aliases it.
// ============================================================================
template<int MODE>
__global__ __launch_bounds__(256) void gemm_bf(const float* __restrict__ A,
                                               const float* __restrict__ bias,
                                               const float* __restrict__ Bsrc,
                                               const float* __restrict__ nw,
                                               const float* __restrict__ nb,
                                               const float* __restrict__ resid,
                                               float* __restrict__ out_param) {
    __shared__ unsigned smem_all[10240];
    const int K = 256;
    const int tid  = threadIdx.x;
    const int wid  = tid >> 5;
    const int lane = tid & 31;
    const int g    = lane >> 2;
    const int t4   = lane & 3;
    const int wm   = (wid >> 1) * 32;   // 0,32,64,96
    const int wn   = (wid & 1) * 64;
    const int m0 = blockIdx.y * 128, n0 = blockIdx.x * 128;
    const float* __restrict__ Bmat = (MODE == 0) ? Bsrc : g_attn;
    const size_t bb = (size_t)blockIdx.z * K * Tn;

    const int m_a = tid >> 2, kq_a = (tid & 3) * 8;

    float4 pa[4];
    float2 pbA[4], pbB[4];

    // ---- prologue: load + stage slice 0 into buf 0 ----
    {
        const float* apt0 = A + (size_t)(m0 + m_a) * K + kq_a;
        const float* apt1 = A + (size_t)(m0 + m_a + 64) * K + kq_a;
        pa[0] = *(const float4*)apt0; pa[1] = *(const float4*)(apt0 + 4);
        pa[2] = *(const float4*)apt1; pa[3] = *(const float4*)(apt1 + 4);
        #pragma unroll
        for (int r = 0; r < 4; r++) {
            int idx = tid + r * 256;
            int kp = idx >> 6, nn = (idx & 63) * 2;
            const float* rp = Bmat + bb + (size_t)(2 * kp) * Tn + n0 + nn;
            pbA[r] = *(const float2*)rp;
            pbB[r] = *(const float2*)(rp + Tn);
        }
        unsigned* asn = smem_all;
        unsigned* bsn = smem_all + 2560;
        uint4 q0, q1;
        q0.x = pack_bf2(pa[0].x, pa[0].y); q0.y = pack_bf2(pa[0].z, pa[0].w);
        q0.z = pack_bf2(pa[1].x, pa[1].y); q0.w = pack_bf2(pa[1].z, pa[1].w);
        q1.x = pack_bf2(pa[2].x, pa[2].y); q1.y = pack_bf2(pa[2].z, pa[2].w);
        q1.z = pack_bf2(pa[3].x, pa[3].y); q1.w = pack_bf2(pa[3].z, pa[3].w);
        *(uint4*)&asn[(m_a     ) * 20 + kq_a / 2] = q0;
        *(uint4*)&asn[(m_a + 64) * 20 + kq_a / 2] = q1;
        #pragma unroll
        for (int r = 0; r < 4; r++) {
            int idx = tid + r * 256;
            int kp = idx >> 6, nn = (idx & 63) * 2;
            int c0 = 2 * kp;
            float wc0 = 1.f, bc0 = 0.f, wc1 = 1.f, bc1 = 0.f;
            if (MODE == 0) {
                float2 st = g_stats[(blockIdx.z << 5) + (c0 >> 3)];
                wc0 = nw[c0] * st.y;     bc0 = nb[c0] - st.x * wc0;
                wc1 = nw[c0 + 1] * st.y; bc1 = nb[c0 + 1] - st.x * wc1;
            }
            bsn[(nn    ) * 20 + kp] = pack_bf2(pbA[r].x * wc0 + bc0, pbB[r].x * wc1 + bc1);
            bsn[(nn + 1) * 20 + kp] = pack_bf2(pbA[r].y * wc0 + bc0, pbB[r].y * wc1 + bc1);
        }
    }
    __syncthreads();

    float acc[2][8][4] = {};
    #pragma unroll
    for (int s = 0; s < 8; s++) {
        unsigned* asb = smem_all + (s & 1) * 5120;
        unsigned* bsb = asb + 2560;
        const int k1 = (s + 1) * 32;
        // ---- issue LDG for slice s+1 ----
        if (s < 7) {
            const float* apt0 = A + (size_t)(m0 + m_a) * K + k1 + kq_a;
            const float* apt1 = A + (size_t)(m0 + m_a + 64) * K + k1 + kq_a;
            pa[0] = *(const float4*)apt0; pa[1] = *(const float4*)(apt0 + 4);
            pa[2] = *(const float4*)apt1; pa[3] = *(const float4*)(apt1 + 4);
            #pragma unroll
            for (int r = 0; r < 4; r++) {
                int idx = tid + r * 256;
                int kp = idx >> 6, nn = (idx & 63) * 2;
                const float* rp = Bmat + bb + (size_t)(k1 + 2 * kp) * Tn + n0 + nn;
                pbA[r] = *(const float2*)rp;
                pbB[r] = *(const float2*)(rp + Tn);
            }
        }
        // ---- MMAs on slice s ----
        #pragma unroll
        for (int kk = 0; kk < 2; kk++) {
            unsigned a00 = asb[(wm + g     ) * 20 + kk * 8 + t4    ];
            unsigned a01 = asb[(wm + g +  8) * 20 + kk * 8 + t4    ];
            unsigned a02 = asb[(wm + g     ) * 20 + kk * 8 + t4 + 4];
            unsigned a03 = asb[(wm + g +  8) * 20 + kk * 8 + t4 + 4];
            unsigned a10 = asb[(wm + g + 16) * 20 + kk * 8 + t4    ];
            unsigned a11 = asb[(wm + g + 24) * 20 + kk * 8 + t4    ];
            unsigned a12 = asb[(wm + g + 16) * 20 + kk * 8 + t4 + 4];
            unsigned a13 = asb[(wm + g + 24) * 20 + kk * 8 + t4 + 4];
            #pragma unroll
            for (int n = 0; n < 8; n++) {
                unsigned b0 = bsb[(wn + n * 8 + g) * 20 + kk * 8 + t4    ];
                unsigned b1 = bsb[(wn + n * 8 + g) * 20 + kk * 8 + t4 + 4];
                mma_bf16(acc[0][n], a00, a01, a02, a03, b0, b1);
                mma_bf16(acc[1][n], a10, a11, a12, a13, b0, b1);
            }
        }
        // ---- stage slice s+1 into buf nxt ----
        if (s < 7) {
            unsigned* asn = smem_all + ((s + 1) & 1) * 5120;
            unsigned* bsn = asn + 2560;
            uint4 q0, q1;
            q0.x = pack_bf2(pa[0].x, pa[0].y); q0.y = pack_bf2(pa[0].z, pa[0].w);
            q0.z = pack_bf2(pa[1].x, pa[1].y); q0.w = pack_bf2(pa[1].z, pa[1].w);
            q1.x = pack_bf2(pa[2].x, pa[2].y); q1.y = pack_bf2(pa[2].z, pa[2].w);
            q1.z = pack_bf2(pa[3].x, pa[3].y); q1.w = pack_bf2(pa[3].z, pa[3].w);
            *(uint4*)&asn[(m_a     ) * 20 + kq_a / 2] = q0;
            *(uint4*)&asn[(m_a + 64) * 20 + kq_a / 2] = q1;
            #pragma unroll
            for (int r = 0; r < 4; r++) {
                int idx = tid + r * 256;
                int kp = idx >> 6, nn = (idx & 63) * 2;
                int c0 = k1 + 2 * kp;
                float wc0 = 1.f, bc0 = 0.f, wc1 = 1.f, bc1 = 0.f;
                if (MODE == 0) {
                    float2 st = g_stats[(blockIdx.z << 5) + (c0 >> 3)];
                    wc0 = nw[c0] * st.y;     bc0 = nb[c0] - st.x * wc0;
                    wc1 = nw[c0 + 1] * st.y; bc1 = nb[c0 + 1] - st.x * wc1;
                }
                bsn[(nn    ) * 20 + kp] = pack_bf2(pbA[r].x * wc0 + bc0, pbB[r].x * wc1 + bc1);
                bsn[(nn + 1) * 20 + kp] = pack_bf2(pbA[r].y * wc0 + bc0, pbB[r].y * wc1 + bc1);
            }
        }
        __syncthreads();
    }

    const float bi0 = bias[m0 + wm + g     ];
    const float bi1 = bias[m0 + wm + g +  8];
    const float bi2 = bias[m0 + wm + g + 16];
    const float bi3 = bias[m0 + wm + g + 24];

    if (MODE == 0) {
        // this warp's class band (64-row bands are class-uniform)
        const int rbw  = m0 + wm;
        const int cls  = (rbw % 192) / 64;      // 0=q 1=k 2=v
        const int band = wm >> 6;               // 0 or 1
        const int cb   = (wm & 63) + g;         // col within class (c dim)
        const float sc = (cls != 2) ? SCALE_QK : 1.f;
        if (cls != 2) {
            __nv_bfloat16* sb = (__nv_bfloat16*)(smem_all + band * 4608);
            #pragma unroll
            for (int n = 0; n < 8; n++) {
                int t = wn + n * 8 + 2 * t4;
                sb[(t    ) * 72 + cb     ] = __float2bfloat16((acc[0][n][0] + bi0) * sc);
                sb[(t + 1) * 72 + cb     ] = __float2bfloat16((acc[0][n][1] + bi0) * sc);
                sb[(t    ) * 72 + cb +  8] = __float2bfloat16((acc[0][n][2] + bi1) * sc);
                sb[(t + 1) * 72 + cb +  8] = __float2bfloat16((acc[0][n][3] + bi1) * sc);
                sb[(t    ) * 72 + cb + 16] = __float2bfloat16((acc[1][n][0] + bi2) * sc);
                sb[(t + 1) * 72 + cb + 16] = __float2bfloat16((acc[1][n][1] + bi2) * sc);
                sb[(t    ) * 72 + cb + 24] = __float2bfloat16((acc[1][n][2] + bi3) * sc);
                sb[(t + 1) * 72 + cb + 24] = __float2bfloat16((acc[1][n][3] + bi3) * sc);
            }
        } else {
            unsigned* sv = smem_all + band * 4608;
            #pragma unroll
            for (int n = 0; n < 8; n++) {
                int th = wn / 2 + n * 4 + t4;
                sv[(cb     ) * 72 + th] = pack_h2(acc[0][n][0] + bi0, acc[0][n][1] + bi0);
                sv[(cb +  8) * 72 + th] = pack_h2(acc[0][n][2] + bi1, acc[0][n][3] + bi1);
                sv[(cb + 16) * 72 + th] = pack_h2(acc[1][n][0] + bi2, acc[1][n][1] + bi2);
                sv[(cb + 24) * 72 + th] = pack_h2(acc[1][n][2] + bi3, acc[1][n][3] + bi3);
            }
        }
        __syncthreads();
        // coalesced writeback, both bands, all 256 threads
        #pragma unroll
        for (int bandi = 0; bandi < 2; bandi++) {
            const int rb   = m0 + bandi * 64;
            const int clsb = (rb % 192) / 64;
            const int bhb  = blockIdx.z * 4 + rb / 192;
            const char* srcb = (const char*)(smem_all + bandi * 4608);
            if (clsb != 2) {
                char* dstb = (char*)((clsb == 0 ? g_qb : g_kb) + (size_t)bhb * Tn * 64);
                #pragma unroll
                for (int r = 0; r < 4; r++) {
                    int ch = tid + r * 256;
                    int trow = ch >> 3, qc = ch & 7;
                    uint4 v = *(const uint4*)(srcb + trow * 144 + qc * 16);
                    *(uint4*)(dstb + (size_t)(n0 + trow) * 128 + qc * 16) = v;
                }
            } else {
                char* vbs = (char*)(g_vh + (size_t)bhb * 64 * Tn);
                #pragma unroll
                for (int r = 0; r < 4; r++) {
                    int ch = tid + r * 256;
                    int crow = ch >> 4, qc = ch & 15;
                    uint4 v = *(const uint4*)(srcb + crow * 288 + qc * 16);
                    *(uint4*)(vbs + (size_t)crow * (Tn * 2) + (size_t)n0 * 2 + qc * 16) = v;
                }
            }
        }
    } else {
        const float bis[4] = {bi0, bi1, bi2, bi3};
        #pragma unroll
        for (int mi = 0; mi < 2; mi++) {
            const int rA = m0 + wm + g + mi * 16;
            const size_t o0 = ((size_t)blockIdx.z * Cn + rA    ) * Tn + n0 + wn;
            const size_t o1 = ((size_t)blockIdx.z * Cn + rA + 8) * Tn + n0 + wn;
            const float ba = bis[mi * 2], bbv = bis[mi * 2 + 1];
            #pragma unroll
            for (int n = 0; n < 8; n++) {
                int col = n * 8 + 2 * t4;
                *(float2*)(out_param + o0 + col) = make_float2(
                    acc[mi][n][0] + ba  + resid[o0 + col],
                    acc[mi][n][1] + ba  + resid[o0 + col + 1]);
                *(float2*)(out_param + o1 + col) = make_float2(
                    acc[mi][n][2] + bbv + resid[o1 + col],
                    acc[mi][n][3] + bbv + resid[o1 + col + 1]);
            }
        }
    }
}

// ============================================================================
// 3) Flash attention, m32-per-warp (unchanged from R11).
// ============================================================================
#define KBUF 2304
#define VOFF 4608
#define VBUF 2592
#define SMU  (VOFF + 2 * VBUF)    // 9792 u32 = 39168 B

__global__ __launch_bounds__(128, 2) void attn_kernel() {
    extern __shared__ unsigned su[];
    const int tid  = threadIdx.x;
    const int wid  = tid >> 5;
    const int lane = tid & 31;
    const int g    = lane >> 2;
    const int t4   = lane & 3;
    const int tw   = wid * 32;

    const int t0 = blockIdx.x * 128;
    const int bh = blockIdx.y;
    const __nv_bfloat16* qb = g_qb + ((size_t)bh * Tn + t0) * 64;
    const char* kb = (const char*)(g_kb + (size_t)bh * Tn * 64);
    const char* vb = (const char*)(g_vh + (size_t)bh * 64 * Tn);
    float* ap = g_attn + ((size_t)(bh >> 2) * Cn + (bh & 3) * 64) * Tn;

    #pragma unroll
    for (int r = 0; r < 8; r++) {
        int ch = tid + r * 128;
        int row = ch >> 3, q = ch & 7;
        uint4 v = *(const uint4*)((const char*)qb + ch * 16);
        *(uint4*)&su[row * 36 + q * 4] = v;
    }
    __syncthreads();
    unsigned qf0[4][4], qf1[4][4];
    #pragma unroll
    for (int kk = 0; kk < 4; kk++) {
        qf0[kk][0] = su[(tw + g     ) * 36 + kk * 8 + t4    ];
        qf0[kk][1] = su[(tw + g +  8) * 36 + kk * 8 + t4    ];
        qf0[kk][2] = su[(tw + g     ) * 36 + kk * 8 + t4 + 4];
        qf0[kk][3] = su[(tw + g +  8) * 36 + kk * 8 + t4 + 4];
        qf1[kk][0] = su[(tw + g + 16) * 36 + kk * 8 + t4    ];
        qf1[kk][1] = su[(tw + g + 24) * 36 + kk * 8 + t4    ];
        qf1[kk][2] = su[(tw + g + 16) * 36 + kk * 8 + t4 + 4];
        qf1[kk][3] = su[(tw + g + 24) * 36 + kk * 8 + t4 + 4];
    }
    __syncthreads();

    for (int idx = tid; idx < 256; idx += 128) {
        int row = 64 + (idx >> 5), col = idx & 31;
        unsigned val = (row == 64) ? 0x3C003C00u : 0u;   // fp16 {1,1} : {0,0}
        su[VOFF        + row * 36 + col] = val;
        su[VOFF + VBUF + row * 36 + col] = val;
    }
    #pragma unroll
    for (int r = 0; r < 4; r++) {
        int ch = tid + r * 128;
        int row = ch >> 3, q = ch & 7;
        uint4 kv = *(const uint4*)(kb + ch * 16);
        *(uint4*)&su[row * 36 + q * 4] = kv;
        uint4 vv = *(const uint4*)(vb + (size_t)row * (Tn * 2) + q * 16);
        *(uint4*)&su[VOFF + row * 36 + q * 4] = vv;
    }
    __syncthreads();

    float acc_o[16][4];
    #pragma unroll
    for (int n = 0; n < 16; n++)
        #pragma unroll
        for (int r = 0; r < 4; r++) acc_o[n][r] = 0.f;
    float acc_l0[4] = {0.f, 0.f, 0.f, 0.f};
    float acc_l1[4] = {0.f, 0.f, 0.f, 0.f};

    for (int i = 0; i < 64; i++) {
        const int cur = i & 1, nxt = cur ^ 1;
        const unsigned* ku = su + cur * KBUF;
        const unsigned* vu = su + VOFF + cur * VBUF;

        uint4 pk[4], pv[4];
        if (i < 63) {
            const char* kg = kb + (size_t)(i + 1) * 8192;
            #pragma unroll
            for (int r = 0; r < 4; r++) {
                int ch = tid + r * 128;
                int row = ch >> 3, q = ch & 7;
                pk[r] = *(const uint4*)(kg + ch * 16);
                pv[r] = *(const uint4*)(vb + (size_t)row * (Tn * 2)
                                        + (size_t)(i + 1) * 128 + q * 16);
            }
        }

        float sacc[16][4];
        #pragma unroll
        for (int n = 0; n < 16; n++)
            #pragma unroll
            for (int r = 0; r < 4; r++) sacc[n][r] = 0.f;
        #pragma unroll
        for (int kk = 0; kk < 4; kk++) {
            #pragma unroll
            for (int n = 0; n < 8; n++) {
                unsigned b0 = ku[(n * 8 + g) * 36 + kk * 8 + t4    ];
                unsigned b1 = ku[(n * 8 + g) * 36 + kk * 8 + t4 + 4];
                mma_bf16(sacc[2*n    ], qf0[kk][0], qf0[kk][1], qf0[kk][2], qf0[kk][3], b0, b1);
                mma_bf16(sacc[2*n + 1], qf1[kk][0], qf1[kk][1], qf1[kk][2], qf1[kk][3], b0, b1);
            }
        }

        unsigned pf0[8], pg0[8], pf1[8], pg1[8];
        #pragma unroll
        for (int n = 0; n < 8; n++) {
            {
                float u0 = fmaf(sacc[2*n][0], LOG2E, -EXSHIFT);
                float u1 = fmaf(sacc[2*n][1], LOG2E, -EXSHIFT);
                float u2 = fmaf(sacc[2*n][2], LOG2E, -EXSHIFT);
                float u3 = fmaf(sacc[2*n][3], LOG2E, -EXSHIFT);
                pf0[n] = ex2_f16x2(cvt_f16x2(u1, u0));
                pg0[n] = ex2_f16x2(cvt_f16x2(u3, u2));
            }
            {
                float u0 = fmaf(sacc[2*n+1][0], LOG2E, -EXSHIFT);
                float u1 = fmaf(sacc[2*n+1][1], LOG2E, -EXSHIFT);
                float u2 = fmaf(sacc[2*n+1][2], LOG2E, -EXSHIFT);
                float u3 = fmaf(sacc[2*n+1][3], LOG2E, -EXSHIFT);
                pf1[n] = ex2_f16x2(cvt_f16x2(u1, u0));
                pg1[n] = ex2_f16x2(cvt_f16x2(u3, u2));
            }
        }

        #pragma unroll
        for (int kk = 0; kk < 4; kk++) {
            unsigned a00 = pf0[2*kk], a01 = pg0[2*kk], a02 = pf0[2*kk+1], a03 = pg0[2*kk+1];
            unsigned a10 = pf1[2*kk], a11 = pg1[2*kk], a12 = pf1[2*kk+1], a13 = pg1[2*kk+1];
            #pragma unroll
            for (int n = 0; n < 8; n++) {
                unsigned b0 = vu[(n * 8 + g) * 36 + kk * 8 + t4    ];
                unsigned b1 = vu[(n * 8 + g) * 36 + kk * 8 + t4 + 4];
                mma_f16(acc_o[2*n    ], a00, a01, a02, a03, b0, b1);
                mma_f16(acc_o[2*n + 1], a10, a11, a12, a13, b0, b1);
            }
            unsigned l0 = vu[(64 + g) * 36 + kk * 8 + t4    ];
            unsigned l1 = vu[(64 + g) * 36 + kk * 8 + t4 + 4];
            mma_f16(acc_l0, a00, a01, a02, a03, l0, l1);
            mma_f16(acc_l1, a10, a11, a12, a13, l0, l1);
        }

        if (i < 63) {
            unsigned* kd = su + nxt * KBUF;
            unsigned* vd = su + VOFF + nxt * VBUF;
            #pragma unroll
            for (int r = 0; r < 4; r++) {
                int ch = tid + r * 128;
                int row = ch >> 3, q = ch & 7;
                *(uint4*)&kd[row * 36 + q * 4] = pk[r];
                *(uint4*)&vd[row * 36 + q * 4] = pv[r];
            }
        }
        __syncthreads();
    }

    const float rl0 = 1.f / __shfl_sync(0xffffffffu, acc_l0[0], lane & ~3);
    const float rl1 = 1.f / __shfl_sync(0xffffffffu, acc_l0[2], lane & ~3);
    const float rl2 = 1.f / __shfl_sync(0xffffffffu, acc_l1[0], lane & ~3);
    const float rl3 = 1.f / __shfl_sync(0xffffffffu, acc_l1[2], lane & ~3);

    float* o_sm = (float*)su;
    #pragma unroll
    for (int n = 0; n < 8; n++) {
        int c = n * 8 + 2 * t4;
        o_sm[(c    ) * 132 + tw + g     ] = acc_o[2*n  ][0] * rl0;
        o_sm[(c + 1) * 132 + tw + g     ] = acc_o[2*n  ][1] * rl0;
        o_sm[(c    ) * 132 + tw + g +  8] = acc_o[2*n  ][2] * rl1;
        o_sm[(c + 1) * 132 + tw + g +  8] = acc_o[2*n  ][3] * rl1;
        o_sm[(c    ) * 132 + tw + g + 16] = acc_o[2*n+1][0] * rl2;
        o_sm[(c + 1) * 132 + tw + g + 16] = acc_o[2*n+1][1] * rl2;
        o_sm[(c    ) * 132 + tw + g + 24] = acc_o[2*n+1][2] * rl3;
        o_sm[(c + 1) * 132 + tw + g + 24] = acc_o[2*n+1][3] * rl3;
    }
    __syncthreads();
    for (int idx = tid; idx < 2048; idx += 128) {
        int c = idx >> 5, tj = (idx & 31) * 4;
        float4 o4 = *(float4*)&o_sm[c * 132 + tj];
        *(float4*)(ap + (size_t)c * Tn + t0 + tj) = o4;
    }
}

// ============================================================================
extern "C" void kernel_launch(void* const* d_in, const int* in_sizes, int n_in,
                              void* d_out, int out_size) {
    const float* x     = (const float*)d_in[0];
    const float* nw    = (const float*)d_in[1];
    const float* nb    = (const float*)d_in[2];
    const float* qkvw  = (const float*)d_in[3];
    const float* qkvb  = (const float*)d_in[4];
    const float* projw = (const float*)d_in[5];
    const float* projb = (const float*)d_in[6];
    float* out = (float*)d_out;

    const int ATTN_SMEM = SMU * 4;   // 39168 B
    cudaFuncSetAttribute(attn_kernel, cudaFuncAttributeMaxDynamicSharedMemorySize,
                         ATTN_SMEM);

    gn_stats_kernel<<<Bn * 32, 512>>>(x);
    gemm_bf<0><<<dim3(Tn / 128, 768 / 128, Bn), 256>>>(qkvw, qkvb, x, nw, nb,
                                                       nullptr, nullptr);
    attn_kernel<<<dim3(Tn / 128, Bn * 4), 128, ATTN_SMEM>>>();
    gemm_bf<1><<<dim3(Tn / 128, Cn / 128, Bn), 256>>>(projw, projb, nullptr, nullptr,
                                                      nullptr, x, out);
}

// round 13
// speedup vs baseline: 13.3164x; 1.0553x over previous
#include <cuda_runtime.h>
#include <cuda_bf16.h>
#include <cuda_fp16.h>
#include <cstdint>
#include <math.h>

#define Tn 4096
#define Cn 256
#define Bn 2
#define SCALE_QK 0.35355339059327373f   // 64^-0.25
#define LOG2E    1.4426950408889634f
// exp(s-2) = 2^(s*LOG2E - 2*LOG2E); 2*LOG2E = 2.8853900817779268
#define EXSHIFT  2.8853900817779268f

// ---- scratch (__device__ globals: allocation-free) ----
__device__ float         g_attn [Bn * Cn * Tn];     // attention out  [B,256,T]
__device__ float2        g_stats[Bn * 32];          // per (b,group): mean, rstd
__device__ __nv_bfloat16 g_qb   [Bn * 4 * Tn * 64]; // q [bh][t][c] bf16 scaled
__device__ __nv_bfloat16 g_kb   [Bn * 4 * Tn * 64]; // k [bh][s][c] bf16 scaled
__device__ __half        g_vh   [Bn * 4 * 64 * Tn]; // v [bh][c][t] fp16

// ---- helpers ----
__device__ __forceinline__ unsigned pack_bf2(float a, float b) {
    __nv_bfloat162 h = __floats2bfloat162_rn(a, b);
    return *(unsigned*)&h;
}
__device__ __forceinline__ unsigned pack_h2(float a, float b) {
    __half2 h = __floats2half2_rn(a, b);
    return *(unsigned*)&h;
}
__device__ __forceinline__ unsigned cvt_f16x2(float hi, float lo) {
    unsigned d;
    asm("cvt.rn.f16x2.f32 %0, %1, %2;" : "=r"(d) : "f"(hi), "f"(lo));
    return d;
}
__device__ __forceinline__ unsigned ex2_f16x2(unsigned a) {
    unsigned d;
    asm("ex2.approx.f16x2 %0, %1;" : "=r"(d) : "r"(a));
    return d;
}
__device__ __forceinline__ unsigned hadd2(unsigned a, unsigned b) {
    unsigned d;
    asm("add.f16x2 %0, %1, %2;" : "=r"(d) : "r"(a), "r"(b));
    return d;
}
__device__ __forceinline__ float hsum2_f32(unsigned h) {
    __half2 v = *(__half2*)&h;
    float2 f = __half22float2(v);
    return f.x + f.y;
}
__device__ __forceinline__ void mma_bf16(float c[4],
                                         unsigned a0, unsigned a1, unsigned a2, unsigned a3,
                                         unsigned b0, unsigned b1) {
    asm volatile(
        "mma.sync.aligned.m16n8k16.row.col.f32.bf16.bf16.f32 "
        "{%0,%1,%2,%3},{%4,%5,%6,%7},{%8,%9},{%0,%1,%2,%3};"
        : "+f"(c[0]), "+f"(c[1]), "+f"(c[2]), "+f"(c[3])
        : "r"(a0), "r"(a1), "r"(a2), "r"(a3), "r"(b0), "r"(b1));
}
__device__ __forceinline__ void mma_f16(float c[4],
                                        unsigned a0, unsigned a1, unsigned a2, unsigned a3,
                                        unsigned b0, unsigned b1) {
    asm volatile(
        "mma.sync.aligned.m16n8k16.row.col.f32.f16.f16.f32 "
        "{%0,%1,%2,%3},{%4,%5,%6,%7},{%8,%9},{%0,%1,%2,%3};"
        : "+f"(c[0]), "+f"(c[1]), "+f"(c[2]), "+f"(c[3])
        : "r"(a0), "r"(a1), "r"(a2), "r"(a3), "r"(b0), "r"(b1));
}

// ============================================================================
// 1) GroupNorm stats only: grid 64 (b,g), 512 threads. Writes (mean, rstd).
// ============================================================================
__global__ __launch_bounds__(512) void gn_stats_kernel(const float* __restrict__ x) {
    const int b = blockIdx.x >> 5;
    const int g = blockIdx.x & 31;
    const size_t base = ((size_t)b * Cn + g * 8) * Tn;
    const float4* xp = (const float4*)(x + base);
    const int N4 = 8 * Tn / 4;  // 8192

    float s = 0.f, s2 = 0.f;
    for (int i = threadIdx.x; i < N4; i += 512) {
        float4 v = xp[i];
        s  += v.x + v.y + v.z + v.w;
        s2 += v.x*v.x + v.y*v.y + v.z*v.z + v.w*v.w;
    }
    __shared__ float rs[512], rs2[512];
    rs[threadIdx.x] = s; rs2[threadIdx.x] = s2;
    __syncthreads();
    for (int off = 256; off > 0; off >>= 1) {
        if (threadIdx.x < off) {
            rs [threadIdx.x] += rs [threadIdx.x + off];
            rs2[threadIdx.x] += rs2[threadIdx.x + off];
        }
        __syncthreads();
    }
    if (threadIdx.x == 0) {
        const float inv  = 1.f / (8.f * Tn);
        const float mean = rs[0] * inv;
        const float var  = rs2[0] * inv - mean * mean;
        g_stats[blockIdx.x] = make_float2(mean, rsqrtf(var + 1e-5f));
    }
}

// ============================================================================
// 2/4) bf16 tensor-core GEMM, K=256, 128m x 128n tiles, ping-pong smem,
//   __launch_bounds__(256,2) so 2 CTAs/SM overlap staging with MMAs.
//   8 warps (4m x 2n); warp = m32 x n64.
//   MODE 0: A=qkv_w, B = groupnorm(x) on the fly; q/k -> [bh][t][c] bf16
//           scaled; v -> [bh][c][t] fp16; coalesced epilogue via smem staging.
//   MODE 1: A=proj_w, B=g_attn; out = proj + bias + residual (fp32).
// ============================================================================
template<int MODE>
__global__ __launch_bounds__(256, 2) void gemm_bf(const float* __restrict__ A,
                                                  const float* __restrict__ bias,
                                                  const float* __restrict__ Bsrc,
                                                  const float* __restrict__ nw,
                                                  const float* __restrict__ nb,
                                                  const float* __restrict__ resid,
                                                  float* __restrict__ out_param) {
    __shared__ unsigned smem_all[10240];
    const int K = 256;
    const int tid  = threadIdx.x;
    const int wid  = tid >> 5;
    const int lane = tid & 31;
    const int g    = lane >> 2;
    const int t4   = lane & 3;
    const int wm   = (wid >> 1) * 32;   // 0,32,64,96
    const int wn   = (wid & 1) * 64;
    const int m0 = blockIdx.y * 128, n0 = blockIdx.x * 128;
    const float* __restrict__ Bmat = (MODE == 0) ? Bsrc : g_attn;
    const size_t bb = (size_t)blockIdx.z * K * Tn;

    const int m_a = tid >> 2, kq_a = (tid & 3) * 8;

    float4 pa[4];
    float2 pbA[4], pbB[4];

    // ---- prologue: load + stage slice 0 into buf 0 ----
    {
        const float* apt0 = A + (size_t)(m0 + m_a) * K + kq_a;
        const float* apt1 = A + (size_t)(m0 + m_a + 64) * K + kq_a;
        pa[0] = *(const float4*)apt0; pa[1] = *(const float4*)(apt0 + 4);
        pa[2] = *(const float4*)apt1; pa[3] = *(const float4*)(apt1 + 4);
        #pragma unroll
        for (int r = 0; r < 4; r++) {
            int idx = tid + r * 256;
            int kp = idx >> 6, nn = (idx & 63) * 2;
            const float* rp = Bmat + bb + (size_t)(2 * kp) * Tn + n0 + nn;
            pbA[r] = *(const float2*)rp;
            pbB[r] = *(const float2*)(rp + Tn);
        }
        unsigned* asn = smem_all;
        unsigned* bsn = smem_all + 2560;
        uint4 q0, q1;
        q0.x = pack_bf2(pa[0].x, pa[0].y); q0.y = pack_bf2(pa[0].z, pa[0].w);
        q0.z = pack_bf2(pa[1].x, pa[1].y); q0.w = pack_bf2(pa[1].z, pa[1].w);
        q1.x = pack_bf2(pa[2].x, pa[2].y); q1.y = pack_bf2(pa[2].z, pa[2].w);
        q1.z = pack_bf2(pa[3].x, pa[3].y); q1.w = pack_bf2(pa[3].z, pa[3].w);
        *(uint4*)&asn[(m_a     ) * 20 + kq_a / 2] = q0;
        *(uint4*)&asn[(m_a + 64) * 20 + kq_a / 2] = q1;
        #pragma unroll
        for (int r = 0; r < 4; r++) {
            int idx = tid + r * 256;
            int kp = idx >> 6, nn = (idx & 63) * 2;
            int c0 = 2 * kp;
            float wc0 = 1.f, bc0 = 0.f, wc1 = 1.f, bc1 = 0.f;
            if (MODE == 0) {
                float2 st = g_stats[(blockIdx.z << 5) + (c0 >> 3)];
                wc0 = nw[c0] * st.y;     bc0 = nb[c0] - st.x * wc0;
                wc1 = nw[c0 + 1] * st.y; bc1 = nb[c0 + 1] - st.x * wc1;
            }
            bsn[(nn    ) * 20 + kp] = pack_bf2(pbA[r].x * wc0 + bc0, pbB[r].x * wc1 + bc1);
            bsn[(nn + 1) * 20 + kp] = pack_bf2(pbA[r].y * wc0 + bc0, pbB[r].y * wc1 + bc1);
        }
    }
    __syncthreads();

    float acc[2][8][4] = {};
    #pragma unroll 2
    for (int s = 0; s < 8; s++) {
        unsigned* asb = smem_all + (s & 1) * 5120;
        unsigned* bsb = asb + 2560;
        const int k1 = (s + 1) * 32;
        // ---- issue LDG for slice s+1 ----
        if (s < 7) {
            const float* apt0 = A + (size_t)(m0 + m_a) * K + k1 + kq_a;
            const float* apt1 = A + (size_t)(m0 + m_a + 64) * K + k1 + kq_a;
            pa[0] = *(const float4*)apt0; pa[1] = *(const float4*)(apt0 + 4);
            pa[2] = *(const float4*)apt1; pa[3] = *(const float4*)(apt1 + 4);
            #pragma unroll
            for (int r = 0; r < 4; r++) {
                int idx = tid + r * 256;
                int kp = idx >> 6, nn = (idx & 63) * 2;
                const float* rp = Bmat + bb + (size_t)(k1 + 2 * kp) * Tn + n0 + nn;
                pbA[r] = *(const float2*)rp;
                pbB[r] = *(const float2*)(rp + Tn);
            }
        }
        // ---- MMAs on slice s ----
        #pragma unroll
        for (int kk = 0; kk < 2; kk++) {
            unsigned a00 = asb[(wm + g     ) * 20 + kk * 8 + t4    ];
            unsigned a01 = asb[(wm + g +  8) * 20 + kk * 8 + t4    ];
            unsigned a02 = asb[(wm + g     ) * 20 + kk * 8 + t4 + 4];
            unsigned a03 = asb[(wm + g +  8) * 20 + kk * 8 + t4 + 4];
            unsigned a10 = asb[(wm + g + 16) * 20 + kk * 8 + t4    ];
            unsigned a11 = asb[(wm + g + 24) * 20 + kk * 8 + t4    ];
            unsigned a12 = asb[(wm + g + 16) * 20 + kk * 8 + t4 + 4];
            unsigned a13 = asb[(wm + g + 24) * 20 + kk * 8 + t4 + 4];
            #pragma unroll
            for (int n = 0; n < 8; n++) {
                unsigned b0 = bsb[(wn + n * 8 + g) * 20 + kk * 8 + t4    ];
                unsigned b1 = bsb[(wn + n * 8 + g) * 20 + kk * 8 + t4 + 4];
                mma_bf16(acc[0][n], a00, a01, a02, a03, b0, b1);
                mma_bf16(acc[1][n], a10, a11, a12, a13, b0, b1);
            }
        }
        // ---- stage slice s+1 into buf nxt ----
        if (s < 7) {
            unsigned* asn = smem_all + ((s + 1) & 1) * 5120;
            unsigned* bsn = asn + 2560;
            uint4 q0, q1;
            q0.x = pack_bf2(pa[0].x, pa[0].y); q0.y = pack_bf2(pa[0].z, pa[0].w);
            q0.z = pack_bf2(pa[1].x, pa[1].y); q0.w = pack_bf2(pa[1].z, pa[1].w);
            q1.x = pack_bf2(pa[2].x, pa[2].y); q1.y = pack_bf2(pa[2].z, pa[2].w);
            q1.z = pack_bf2(pa[3].x, pa[3].y); q1.w = pack_bf2(pa[3].z, pa[3].w);
            *(uint4*)&asn[(m_a     ) * 20 + kq_a / 2] = q0;
            *(uint4*)&asn[(m_a + 64) * 20 + kq_a / 2] = q1;
            #pragma unroll
            for (int r = 0; r < 4; r++) {
                int idx = tid + r * 256;
                int kp = idx >> 6, nn = (idx & 63) * 2;
                int c0 = k1 + 2 * kp;
                float wc0 = 1.f, bc0 = 0.f, wc1 = 1.f, bc1 = 0.f;
                if (MODE == 0) {
                    float2 st = g_stats[(blockIdx.z << 5) + (c0 >> 3)];
                    wc0 = nw[c0] * st.y;     bc0 = nb[c0] - st.x * wc0;
                    wc1 = nw[c0 + 1] * st.y; bc1 = nb[c0 + 1] - st.x * wc1;
                }
                bsn[(nn    ) * 20 + kp] = pack_bf2(pbA[r].x * wc0 + bc0, pbB[r].x * wc1 + bc1);
                bsn[(nn + 1) * 20 + kp] = pack_bf2(pbA[r].y * wc0 + bc0, pbB[r].y * wc1 + bc1);
            }
        }
        __syncthreads();
    }

    const float bi0 = bias[m0 + wm + g     ];
    const float bi1 = bias[m0 + wm + g +  8];
    const float bi2 = bias[m0 + wm + g + 16];
    const float bi3 = bias[m0 + wm + g + 24];

    if (MODE == 0) {
        const int rbw  = m0 + wm;
        const int cls  = (rbw % 192) / 64;      // 0=q 1=k 2=v
        const int band = wm >> 6;               // 0 or 1
        const int cb   = (wm & 63) + g;         // col within class (c dim)
        const float sc = (cls != 2) ? SCALE_QK : 1.f;
        if (cls != 2) {
            __nv_bfloat16* sb = (__nv_bfloat16*)(smem_all + band * 4608);
            #pragma unroll
            for (int n = 0; n < 8; n++) {
                int t = wn + n * 8 + 2 * t4;
                sb[(t    ) * 72 + cb     ] = __float2bfloat16((acc[0][n][0] + bi0) * sc);
                sb[(t + 1) * 72 + cb     ] = __float2bfloat16((acc[0][n][1] + bi0) * sc);
                sb[(t    ) * 72 + cb +  8] = __float2bfloat16((acc[0][n][2] + bi1) * sc);
                sb[(t + 1) * 72 + cb +  8] = __float2bfloat16((acc[0][n][3] + bi1) * sc);
                sb[(t    ) * 72 + cb + 16] = __float2bfloat16((acc[1][n][0] + bi2) * sc);
                sb[(t + 1) * 72 + cb + 16] = __float2bfloat16((acc[1][n][1] + bi2) * sc);
                sb[(t    ) * 72 + cb + 24] = __float2bfloat16((acc[1][n][2] + bi3) * sc);
                sb[(t + 1) * 72 + cb + 24] = __float2bfloat16((acc[1][n][3] + bi3) * sc);
            }
        } else {
            unsigned* sv = smem_all + band * 4608;
            #pragma unroll
            for (int n = 0; n < 8; n++) {
                int th = wn / 2 + n * 4 + t4;
                sv[(cb     ) * 72 + th] = pack_h2(acc[0][n][0] + bi0, acc[0][n][1] + bi0);
                sv[(cb +  8) * 72 + th] = pack_h2(acc[0][n][2] + bi1, acc[0][n][3] + bi1);
                sv[(cb + 16) * 72 + th] = pack_h2(acc[1][n][0] + bi2, acc[1][n][1] + bi2);
                sv[(cb + 24) * 72 + th] = pack_h2(acc[1][n][2] + bi3, acc[1][n][3] + bi3);
            }
        }
        __syncthreads();
        #pragma unroll
        for (int bandi = 0; bandi < 2; bandi++) {
            const int rb   = m0 + bandi * 64;
            const int clsb = (rb % 192) / 64;
            const int bhb  = blockIdx.z * 4 + rb / 192;
            const char* srcb = (const char*)(smem_all + bandi * 4608);
            if (clsb != 2) {
                char* dstb = (char*)((clsb == 0 ? g_qb : g_kb) + (size_t)bhb * Tn * 64);
                #pragma unroll
                for (int r = 0; r < 4; r++) {
                    int ch = tid + r * 256;
                    int trow = ch >> 3, qc = ch & 7;
                    uint4 v = *(const uint4*)(srcb + trow * 144 + qc * 16);
                    *(uint4*)(dstb + (size_t)(n0 + trow) * 128 + qc * 16) = v;
                }
            } else {
                char* vbs = (char*)(g_vh + (size_t)bhb * 64 * Tn);
                #pragma unroll
                for (int r = 0; r < 4; r++) {
                    int ch = tid + r * 256;
                    int crow = ch >> 4, qc = ch & 15;
                    uint4 v = *(const uint4*)(srcb + crow * 288 + qc * 16);
                    *(uint4*)(vbs + (size_t)crow * (Tn * 2) + (size_t)n0 * 2 + qc * 16) = v;
                }
            }
        }
    } else {
        const float bis[4] = {bi0, bi1, bi2, bi3};
        #pragma unroll
        for (int mi = 0; mi < 2; mi++) {
            const int rA = m0 + wm + g + mi * 16;
            const size_t o0 = ((size_t)blockIdx.z * Cn + rA    ) * Tn + n0 + wn;
            const size_t o1 = ((size_t)blockIdx.z * Cn + rA + 8) * Tn + n0 + wn;
            const float ba = bis[mi * 2], bbv = bis[mi * 2 + 1];
            #pragma unroll
            for (int n = 0; n < 8; n++) {
                int col = n * 8 + 2 * t4;
                *(float2*)(out_param + o0 + col) = make_float2(
                    acc[mi][n][0] + ba  + resid[o0 + col],
                    acc[mi][n][1] + ba  + resid[o0 + col + 1]);
                *(float2*)(out_param + o1 + col) = make_float2(
                    acc[mi][n][2] + bbv + resid[o1 + col],
                    acc[mi][n][3] + bbv + resid[o1 + col + 1]);
            }
        }
    }
}

// ============================================================================
// 3) Flash attention, m32-per-warp. S: bf16 mma. P: fp16 via ex2.approx.f16x2
//    (p = exp(s-2), exact softmax). PV: fp16 mma (no l-rows: l accumulated via
//    HADD2 tree + fp32, quad-reduced by shuffles at the end).
//    Double-buffered K/V, 1 sync/iter. smem stride 36, conflict-free.
// ============================================================================
#define KBUF 2304
#define VOFF 4608
#define VBUF 2304
#define SMU  (VOFF + 2 * VBUF)    // 9216 u32 = 36864 B

__global__ __launch_bounds__(128, 2) void attn_kernel() {
    extern __shared__ unsigned su[];
    const int tid  = threadIdx.x;
    const int wid  = tid >> 5;
    const int lane = tid & 31;
    const int g    = lane >> 2;
    const int t4   = lane & 3;
    const int tw   = wid * 32;

    const int t0 = blockIdx.x * 128;
    const int bh = blockIdx.y;
    const __nv_bfloat16* qb = g_qb + ((size_t)bh * Tn + t0) * 64;
    const char* kb = (const char*)(g_kb + (size_t)bh * Tn * 64);
    const char* vb = (const char*)(g_vh + (size_t)bh * 64 * Tn);
    float* ap = g_attn + ((size_t)(bh >> 2) * Cn + (bh & 3) * 64) * Tn;

    #pragma unroll
    for (int r = 0; r < 8; r++) {
        int ch = tid + r * 128;
        int row = ch >> 3, q = ch & 7;
        uint4 v = *(const uint4*)((const char*)qb + ch * 16);
        *(uint4*)&su[row * 36 + q * 4] = v;
    }
    __syncthreads();
    unsigned qf0[4][4], qf1[4][4];
    #pragma unroll
    for (int kk = 0; kk < 4; kk++) {
        qf0[kk][0] = su[(tw + g     ) * 36 + kk * 8 + t4    ];
        qf0[kk][1] = su[(tw + g +  8) * 36 + kk * 8 + t4    ];
        qf0[kk][2] = su[(tw + g     ) * 36 + kk * 8 + t4 + 4];
        qf0[kk][3] = su[(tw + g +  8) * 36 + kk * 8 + t4 + 4];
        qf1[kk][0] = su[(tw + g + 16) * 36 + kk * 8 + t4    ];
        qf1[kk][1] = su[(tw + g + 24) * 36 + kk * 8 + t4    ];
        qf1[kk][2] = su[(tw + g + 16) * 36 + kk * 8 + t4 + 4];
        qf1[kk][3] = su[(tw + g + 24) * 36 + kk * 8 + t4 + 4];
    }
    __syncthreads();

    #pragma unroll
    for (int r = 0; r < 4; r++) {
        int ch = tid + r * 128;
        int row = ch >> 3, q = ch & 7;
        uint4 kv = *(const uint4*)(kb + ch * 16);
        *(uint4*)&su[row * 36 + q * 4] = kv;
        uint4 vv = *(const uint4*)(vb + (size_t)row * (Tn * 2) + q * 16);
        *(uint4*)&su[VOFF + row * 36 + q * 4] = vv;
    }
    __syncthreads();

    float acc_o[16][4];
    #pragma unroll
    for (int n = 0; n < 16; n++)
        #pragma unroll
        for (int r = 0; r < 4; r++) acc_o[n][r] = 0.f;
    float l0 = 0.f, l1 = 0.f, l2 = 0.f, l3 = 0.f;

    for (int i = 0; i < 64; i++) {
        const int cur = i & 1, nxt = cur ^ 1;
        const unsigned* ku = su + cur * KBUF;
        const unsigned* vu = su + VOFF + cur * VBUF;

        uint4 pk[4], pv[4];
        if (i < 63) {
            const char* kg = kb + (size_t)(i + 1) * 8192;
            #pragma unroll
            for (int r = 0; r < 4; r++) {
                int ch = tid + r * 128;
                int row = ch >> 3, q = ch & 7;
                pk[r] = *(const uint4*)(kg + ch * 16);
                pv[r] = *(const uint4*)(vb + (size_t)row * (Tn * 2)
                                        + (size_t)(i + 1) * 128 + q * 16);
            }
        }

        float sacc[16][4];
        #pragma unroll
        for (int n = 0; n < 16; n++)
            #pragma unroll
            for (int r = 0; r < 4; r++) sacc[n][r] = 0.f;
        #pragma unroll
        for (int kk = 0; kk < 4; kk++) {
            #pragma unroll
            for (int n = 0; n < 8; n++) {
                unsigned b0 = ku[(n * 8 + g) * 36 + kk * 8 + t4    ];
                unsigned b1 = ku[(n * 8 + g) * 36 + kk * 8 + t4 + 4];
                mma_bf16(sacc[2*n    ], qf0[kk][0], qf0[kk][1], qf0[kk][2], qf0[kk][3], b0, b1);
                mma_bf16(sacc[2*n + 1], qf1[kk][0], qf1[kk][1], qf1[kk][2], qf1[kk][3], b0, b1);
            }
        }

        unsigned pf0[8], pg0[8], pf1[8], pg1[8];
        #pragma unroll
        for (int n = 0; n < 8; n++) {
            {
                float u0 = fmaf(sacc[2*n][0], LOG2E, -EXSHIFT);
                float u1 = fmaf(sacc[2*n][1], LOG2E, -EXSHIFT);
                float u2 = fmaf(sacc[2*n][2], LOG2E, -EXSHIFT);
                float u3 = fmaf(sacc[2*n][3], LOG2E, -EXSHIFT);
                pf0[n] = ex2_f16x2(cvt_f16x2(u1, u0));
                pg0[n] = ex2_f16x2(cvt_f16x2(u3, u2));
            }
            {
                float u0 = fmaf(sacc[2*n+1][0], LOG2E, -EXSHIFT);
                float u1 = fmaf(sacc[2*n+1][1], LOG2E, -EXSHIFT);
                float u2 = fmaf(sacc[2*n+1][2], LOG2E, -EXSHIFT);
                float u3 = fmaf(sacc[2*n+1][3], LOG2E, -EXSHIFT);
                pf1[n] = ex2_f16x2(cvt_f16x2(u1, u0));
                pg1[n] = ex2_f16x2(cvt_f16x2(u3, u2));
            }
        }

        // ---- l accumulation: HADD2 trees (fma/alu pipes, overlap tensor) ----
        {
            unsigned s0 = hadd2(hadd2(hadd2(pf0[0], pf0[1]), hadd2(pf0[2], pf0[3])),
                                hadd2(hadd2(pf0[4], pf0[5]), hadd2(pf0[6], pf0[7])));
            unsigned s1 = hadd2(hadd2(hadd2(pg0[0], pg0[1]), hadd2(pg0[2], pg0[3])),
                                hadd2(hadd2(pg0[4], pg0[5]), hadd2(pg0[6], pg0[7])));
            unsigned s2 = hadd2(hadd2(hadd2(pf1[0], pf1[1]), hadd2(pf1[2], pf1[3])),
                                hadd2(hadd2(pf1[4], pf1[5]), hadd2(pf1[6], pf1[7])));
            unsigned s3 = hadd2(hadd2(hadd2(pg1[0], pg1[1]), hadd2(pg1[2], pg1[3])),
                                hadd2(hadd2(pg1[4], pg1[5]), hadd2(pg1[6], pg1[7])));
            l0 += hsum2_f32(s0);
            l1 += hsum2_f32(s1);
            l2 += hsum2_f32(s2);
            l3 += hsum2_f32(s3);
        }

        #pragma unroll
        for (int kk = 0; kk < 4; kk++) {
            unsigned a00 = pf0[2*kk], a01 = pg0[2*kk], a02 = pf0[2*kk+1], a03 = pg0[2*kk+1];
            unsigned a10 = pf1[2*kk], a11 = pg1[2*kk], a12 = pf1[2*kk+1], a13 = pg1[2*kk+1];
            #pragma unroll
            for (int n = 0; n < 8; n++) {
                unsigned b0 = vu[(n * 8 + g) * 36 + kk * 8 + t4    ];
                unsigned b1 = vu[(n * 8 + g) * 36 + kk * 8 + t4 + 4];
                mma_f16(acc_o[2*n    ], a00, a01, a02, a03, b0, b1);
                mma_f16(acc_o[2*n + 1], a10, a11, a12, a13, b0, b1);
            }
        }

        if (i < 63) {
            unsigned* kd = su + nxt * KBUF;
            unsigned* vd = su + VOFF + nxt * VBUF;
            #pragma unroll
            for (int r = 0; r < 4; r++) {
                int ch = tid + r * 128;
                int row = ch >> 3, q = ch & 7;
                *(uint4*)&kd[row * 36 + q * 4] = pk[r];
                *(uint4*)&vd[row * 36 + q * 4] = pv[r];
            }
        }
        __syncthreads();
    }

    // ---- quad-reduce l (4 threads per row share t4) ----
    l0 += __shfl_xor_sync(0xffffffffu, l0, 1);
    l0 += __shfl_xor_sync(0xffffffffu, l0, 2);
    l1 += __shfl_xor_sync(0xffffffffu, l1, 1);
    l1 += __shfl_xor_sync(0xffffffffu, l1, 2);
    l2 += __shfl_xor_sync(0xffffffffu, l2, 1);
    l2 += __shfl_xor_sync(0xffffffffu, l2, 2);
    l3 += __shfl_xor_sync(0xffffffffu, l3, 1);
    l3 += __shfl_xor_sync(0xffffffffu, l3, 2);
    const float rl0 = 1.f / l0, rl1 = 1.f / l1, rl2 = 1.f / l2, rl3 = 1.f / l3;

    float* o_sm = (float*)su;
    #pragma unroll
    for (int n = 0; n < 8; n++) {
        int c = n * 8 + 2 * t4;
        o_sm[(c    ) * 132 + tw + g     ] = acc_o[2*n  ][0] * rl0;
        o_sm[(c + 1) * 132 + tw + g     ] = acc_o[2*n  ][1] * rl0;
        o_sm[(c    ) * 132 + tw + g +  8] = acc_o[2*n  ][2] * rl1;
        o_sm[(c + 1) * 132 + tw + g +  8] = acc_o[2*n  ][3] * rl1;
        o_sm[(c    ) * 132 + tw + g + 16] = acc_o[2*n+1][0] * rl2;
        o_sm[(c + 1) * 132 + tw + g + 16] = acc_o[2*n+1][1] * rl2;
        o_sm[(c    ) * 132 + tw + g + 24] = acc_o[2*n+1][2] * rl3;
        o_sm[(c + 1) * 132 + tw + g + 24] = acc_o[2*n+1][3] * rl3;
    }
    __syncthreads();
    for (int idx = tid; idx < 2048; idx += 128) {
        int c = idx >> 5, tj = (idx & 31) * 4;
        float4 o4 = *(float4*)&o_sm[c * 132 + tj];
        *(float4*)(ap + (size_t)c * Tn + t0 + tj) = o4;
    }
}

// ============================================================================
extern "C" void kernel_launch(void* const* d_in, const int* in_sizes, int n_in,
                              void* d_out, int out_size) {
    const float* x     = (const float*)d_in[0];
    const float* nw    = (const float*)d_in[1];
    const float* nb    = (const float*)d_in[2];
    const float* qkvw  = (const float*)d_in[3];
    const float* qkvb  = (const float*)d_in[4];
    const float* projw = (const float*)d_in[5];
    const float* projb = (const float*)d_in[6];
    float* out = (float*)d_out;

    const int ATTN_SMEM = SMU * 4;   // 36864 B
    cudaFuncSetAttribute(attn_kernel, cudaFuncAttributeMaxDynamicSharedMemorySize,
                         ATTN_SMEM);

    gn_stats_kernel<<<Bn * 32, 512>>>(x);
    gemm_bf<0><<<dim3(Tn / 128, 768 / 128, Bn), 256>>>(qkvw, qkvb, x, nw, nb,
                                                       nullptr, nullptr);
    attn_kernel<<<dim3(Tn / 128, Bn * 4), 128, ATTN_SMEM>>>();
    gemm_bf<1><<<dim3(Tn / 128, Cn / 128, Bn), 256>>>(projw, projb, nullptr, nullptr,
                                                      nullptr, x, out);
}

// round 14
// speedup vs baseline: 13.9018x; 1.0440x over previous
#include <cuda_runtime.h>
#include <cuda_bf16.h>
#include <cuda_fp16.h>
#include <cstdint>
#include <math.h>

#define Tn 4096
#define Cn 256
#define Bn 2
#define SCALE_QK 0.35355339059327373f   // 64^-0.25
#define LOG2E    1.4426950408889634f
// exp(s-2) = 2^(s*LOG2E - 2*LOG2E); 2*LOG2E = 2.8853900817779268
#define EXSHIFT  2.8853900817779268f

// B smem: [kpair][n], stride 136 u32 (136 % 32 == 8 -> conflict-free frags+stores)
#define BST 136
#define ABUF 2560               // A: 128 rows x 20 u32
#define BBUF (16 * BST)         // 2176 u32
#define GBUF (ABUF + BBUF)      // 4736 u32 per ping-pong buffer

// ---- scratch (__device__ globals: allocation-free) ----
__device__ float         g_attn [Bn * Cn * Tn];     // attention out  [B,256,T]
__device__ float2        g_stats[Bn * 32];          // per (b,group): mean, rstd
__device__ __nv_bfloat16 g_qb   [Bn * 4 * Tn * 64]; // q [bh][t][c] bf16 scaled
__device__ __nv_bfloat16 g_kb   [Bn * 4 * Tn * 64]; // k [bh][s][c] bf16 scaled
__device__ __half        g_vh   [Bn * 4 * 64 * Tn]; // v [bh][c][t] fp16

// ---- helpers ----
__device__ __forceinline__ unsigned pack_bf2(float a, float b) {
    __nv_bfloat162 h = __floats2bfloat162_rn(a, b);
    return *(unsigned*)&h;
}
__device__ __forceinline__ unsigned pack_h2(float a, float b) {
    __half2 h = __floats2half2_rn(a, b);
    return *(unsigned*)&h;
}
__device__ __forceinline__ unsigned cvt_f16x2(float hi, float lo) {
    unsigned d;
    asm("cvt.rn.f16x2.f32 %0, %1, %2;" : "=r"(d) : "f"(hi), "f"(lo));
    return d;
}
__device__ __forceinline__ unsigned ex2_f16x2(unsigned a) {
    unsigned d;
    asm("ex2.approx.f16x2 %0, %1;" : "=r"(d) : "r"(a));
    return d;
}
__device__ __forceinline__ unsigned hadd2(unsigned a, unsigned b) {
    unsigned d;
    asm("add.f16x2 %0, %1, %2;" : "=r"(d) : "r"(a), "r"(b));
    return d;
}
__device__ __forceinline__ float hsum2_f32(unsigned h) {
    __half2 v = *(__half2*)&h;
    float2 f = __half22float2(v);
    return f.x + f.y;
}
__device__ __forceinline__ void mma_bf16(float c[4],
                                         unsigned a0, unsigned a1, unsigned a2, unsigned a3,
                                         unsigned b0, unsigned b1) {
    asm volatile(
        "mma.sync.aligned.m16n8k16.row.col.f32.bf16.bf16.f32 "
        "{%0,%1,%2,%3},{%4,%5,%6,%7},{%8,%9},{%0,%1,%2,%3};"
        : "+f"(c[0]), "+f"(c[1]), "+f"(c[2]), "+f"(c[3])
        : "r"(a0), "r"(a1), "r"(a2), "r"(a3), "r"(b0), "r"(b1));
}
__device__ __forceinline__ void mma_f16(float c[4],
                                        unsigned a0, unsigned a1, unsigned a2, unsigned a3,
                                        unsigned b0, unsigned b1) {
    asm volatile(
        "mma.sync.aligned.m16n8k16.row.col.f32.f16.f16.f32 "
        "{%0,%1,%2,%3},{%4,%5,%6,%7},{%8,%9},{%0,%1,%2,%3};"
        : "+f"(c[0]), "+f"(c[1]), "+f"(c[2]), "+f"(c[3])
        : "r"(a0), "r"(a1), "r"(a2), "r"(a3), "r"(b0), "r"(b1));
}

// ============================================================================
// 1) GroupNorm stats only: grid 64 (b,g), 512 threads. Writes (mean, rstd).
// ============================================================================
__global__ __launch_bounds__(512) void gn_stats_kernel(const float* __restrict__ x) {
    const int b = blockIdx.x >> 5;
    const int g = blockIdx.x & 31;
    const size_t base = ((size_t)b * Cn + g * 8) * Tn;
    const float4* xp = (const float4*)(x + base);
    const int N4 = 8 * Tn / 4;  // 8192

    float s = 0.f, s2 = 0.f;
    for (int i = threadIdx.x; i < N4; i += 512) {
        float4 v = xp[i];
        s  += v.x + v.y + v.z + v.w;
        s2 += v.x*v.x + v.y*v.y + v.z*v.z + v.w*v.w;
    }
    __shared__ float rs[512], rs2[512];
    rs[threadIdx.x] = s; rs2[threadIdx.x] = s2;
    __syncthreads();
    for (int off = 256; off > 0; off >>= 1) {
        if (threadIdx.x < off) {
            rs [threadIdx.x] += rs [threadIdx.x + off];
            rs2[threadIdx.x] += rs2[threadIdx.x + off];
        }
        __syncthreads();
    }
    if (threadIdx.x == 0) {
        const float inv  = 1.f / (8.f * Tn);
        const float mean = rs[0] * inv;
        const float var  = rs2[0] * inv - mean * mean;
        g_stats[blockIdx.x] = make_float2(mean, rsqrtf(var + 1e-5f));
    }
}

// ============================================================================
// 2/4) bf16 tensor-core GEMM, K=256, 128m x 128n tiles, ping-pong smem.
//   B smem flipped to [kpair][n] stride 136: conflict-free STS.64 staging AND
//   conflict-free fragment loads (bank = 8*t4 + g).
//   8 warps (4m x 2n); warp = m32 x n64.
//   MODE 0: A=qkv_w, B = groupnorm(x) on the fly; q/k -> [bh][t][c] bf16
//           scaled; v -> [bh][c][t] fp16; coalesced epilogue via smem staging.
//   MODE 1: A=proj_w, B=g_attn; out = proj + bias + residual (fp32).
// ============================================================================
template<int MODE>
__global__ __launch_bounds__(256, 2) void gemm_bf(const float* __restrict__ A,
                                                  const float* __restrict__ bias,
                                                  const float* __restrict__ Bsrc,
                                                  const float* __restrict__ nw,
                                                  const float* __restrict__ nb,
                                                  const float* __restrict__ resid,
                                                  float* __restrict__ out_param) {
    __shared__ unsigned smem_all[2 * GBUF];   // 9472 u32 = 37888 B
    const int K = 256;
    const int tid  = threadIdx.x;
    const int wid  = tid >> 5;
    const int lane = tid & 31;
    const int g    = lane >> 2;
    const int t4   = lane & 3;
    const int wm   = (wid >> 1) * 32;   // 0,32,64,96
    const int wn   = (wid & 1) * 64;
    const int m0 = blockIdx.y * 128, n0 = blockIdx.x * 128;
    const float* __restrict__ Bmat = (MODE == 0) ? Bsrc : g_attn;
    const size_t bb = (size_t)blockIdx.z * K * Tn;

    const int m_a = tid >> 2, kq_a = (tid & 3) * 8;
    const int kp_b = tid >> 6;             // base k-pair (r adds 4)
    const int nn_b = (tid & 63) * 2;

    float4 pa[4];
    float2 pbA[4], pbB[4];

    // ---- prologue: load + stage slice 0 into buf 0 ----
    {
        const float* apt0 = A + (size_t)(m0 + m_a) * K + kq_a;
        const float* apt1 = A + (size_t)(m0 + m_a + 64) * K + kq_a;
        pa[0] = *(const float4*)apt0; pa[1] = *(const float4*)(apt0 + 4);
        pa[2] = *(const float4*)apt1; pa[3] = *(const float4*)(apt1 + 4);
        #pragma unroll
        for (int r = 0; r < 4; r++) {
            int kp = kp_b + r * 4;
            const float* rp = Bmat + bb + (size_t)(2 * kp) * Tn + n0 + nn_b;
            pbA[r] = *(const float2*)rp;
            pbB[r] = *(const float2*)(rp + Tn);
        }
        unsigned* asn = smem_all;
        unsigned* bsn = smem_all + ABUF;
        uint4 q0, q1;
        q0.x = pack_bf2(pa[0].x, pa[0].y); q0.y = pack_bf2(pa[0].z, pa[0].w);
        q0.z = pack_bf2(pa[1].x, pa[1].y); q0.w = pack_bf2(pa[1].z, pa[1].w);
        q1.x = pack_bf2(pa[2].x, pa[2].y); q1.y = pack_bf2(pa[2].z, pa[2].w);
        q1.z = pack_bf2(pa[3].x, pa[3].y); q1.w = pack_bf2(pa[3].z, pa[3].w);
        *(uint4*)&asn[(m_a     ) * 20 + kq_a / 2] = q0;
        *(uint4*)&asn[(m_a + 64) * 20 + kq_a / 2] = q1;
        #pragma unroll
        for (int r = 0; r < 4; r++) {
            int kp = kp_b + r * 4;
            int c0 = 2 * kp;
            float wc0 = 1.f, bc0 = 0.f, wc1 = 1.f, bc1 = 0.f;
            if (MODE == 0) {
                float2 st = g_stats[(blockIdx.z << 5) + (c0 >> 3)];
                wc0 = nw[c0] * st.y;     bc0 = nb[c0] - st.x * wc0;
                wc1 = nw[c0 + 1] * st.y; bc1 = nb[c0 + 1] - st.x * wc1;
            }
            uint2 pkd;
            pkd.x = pack_bf2(pbA[r].x * wc0 + bc0, pbB[r].x * wc1 + bc1);
            pkd.y = pack_bf2(pbA[r].y * wc0 + bc0, pbB[r].y * wc1 + bc1);
            *(uint2*)&bsn[kp * BST + nn_b] = pkd;
        }
    }
    __syncthreads();

    float acc[2][8][4] = {};
    #pragma unroll 2
    for (int s = 0; s < 8; s++) {
        unsigned* asb = smem_all + (s & 1) * GBUF;
        unsigned* bsb = asb + ABUF;
        const int k1 = (s + 1) * 32;
        // ---- issue LDG for slice s+1 ----
        if (s < 7) {
            const float* apt0 = A + (size_t)(m0 + m_a) * K + k1 + kq_a;
            const float* apt1 = A + (size_t)(m0 + m_a + 64) * K + k1 + kq_a;
            pa[0] = *(const float4*)apt0; pa[1] = *(const float4*)(apt0 + 4);
            pa[2] = *(const float4*)apt1; pa[3] = *(const float4*)(apt1 + 4);
            #pragma unroll
            for (int r = 0; r < 4; r++) {
                int kp = kp_b + r * 4;
                const float* rp = Bmat + bb + (size_t)(k1 + 2 * kp) * Tn + n0 + nn_b;
                pbA[r] = *(const float2*)rp;
                pbB[r] = *(const float2*)(rp + Tn);
            }
        }
        // ---- MMAs on slice s ----
        #pragma unroll
        for (int kk = 0; kk < 2; kk++) {
            unsigned a00 = asb[(wm + g     ) * 20 + kk * 8 + t4    ];
            unsigned a01 = asb[(wm + g +  8) * 20 + kk * 8 + t4    ];
            unsigned a02 = asb[(wm + g     ) * 20 + kk * 8 + t4 + 4];
            unsigned a03 = asb[(wm + g +  8) * 20 + kk * 8 + t4 + 4];
            unsigned a10 = asb[(wm + g + 16) * 20 + kk * 8 + t4    ];
            unsigned a11 = asb[(wm + g + 24) * 20 + kk * 8 + t4    ];
            unsigned a12 = asb[(wm + g + 16) * 20 + kk * 8 + t4 + 4];
            unsigned a13 = asb[(wm + g + 24) * 20 + kk * 8 + t4 + 4];
            #pragma unroll
            for (int n = 0; n < 8; n++) {
                unsigned b0 = bsb[(kk * 8 + t4    ) * BST + wn + n * 8 + g];
                unsigned b1 = bsb[(kk * 8 + t4 + 4) * BST + wn + n * 8 + g];
                mma_bf16(acc[0][n], a00, a01, a02, a03, b0, b1);
                mma_bf16(acc[1][n], a10, a11, a12, a13, b0, b1);
            }
        }
        // ---- stage slice s+1 into buf nxt ----
        if (s < 7) {
            unsigned* asn = smem_all + ((s + 1) & 1) * GBUF;
            unsigned* bsn = asn + ABUF;
            uint4 q0, q1;
            q0.x = pack_bf2(pa[0].x, pa[0].y); q0.y = pack_bf2(pa[0].z, pa[0].w);
            q0.z = pack_bf2(pa[1].x, pa[1].y); q0.w = pack_bf2(pa[1].z, pa[1].w);
            q1.x = pack_bf2(pa[2].x, pa[2].y); q1.y = pack_bf2(pa[2].z, pa[2].w);
            q1.z = pack_bf2(pa[3].x, pa[3].y); q1.w = pack_bf2(pa[3].z, pa[3].w);
            *(uint4*)&asn[(m_a     ) * 20 + kq_a / 2] = q0;
            *(uint4*)&asn[(m_a + 64) * 20 + kq_a / 2] = q1;
            #pragma unroll
            for (int r = 0; r < 4; r++) {
                int kp = kp_b + r * 4;
                int c0 = k1 + 2 * kp;
                float wc0 = 1.f, bc0 = 0.f, wc1 = 1.f, bc1 = 0.f;
                if (MODE == 0) {
                    float2 st = g_stats[(blockIdx.z << 5) + (c0 >> 3)];
                    wc0 = nw[c0] * st.y;     bc0 = nb[c0] - st.x * wc0;
                    wc1 = nw[c0 + 1] * st.y; bc1 = nb[c0 + 1] - st.x * wc1;
                }
                uint2 pkd;
                pkd.x = pack_bf2(pbA[r].x * wc0 + bc0, pbB[r].x * wc1 + bc1);
                pkd.y = pack_bf2(pbA[r].y * wc0 + bc0, pbB[r].y * wc1 + bc1);
                *(uint2*)&bsn[kp * BST + nn_b] = pkd;
            }
        }
        __syncthreads();
    }

    const float bi0 = bias[m0 + wm + g     ];
    const float bi1 = bias[m0 + wm + g +  8];
    const float bi2 = bias[m0 + wm + g + 16];
    const float bi3 = bias[m0 + wm + g + 24];

    if (MODE == 0) {
        const int rbw  = m0 + wm;
        const int cls  = (rbw % 192) / 64;      // 0=q 1=k 2=v
        const int band = wm >> 6;               // 0 or 1
        const int cb   = (wm & 63) + g;         // col within class (c dim)
        const float sc = (cls != 2) ? SCALE_QK : 1.f;
        if (cls != 2) {
            __nv_bfloat16* sb = (__nv_bfloat16*)(smem_all + band * 4608);
            #pragma unroll
            for (int n = 0; n < 8; n++) {
                int t = wn + n * 8 + 2 * t4;
                sb[(t    ) * 72 + cb     ] = __float2bfloat16((acc[0][n][0] + bi0) * sc);
                sb[(t + 1) * 72 + cb     ] = __float2bfloat16((acc[0][n][1] + bi0) * sc);
                sb[(t    ) * 72 + cb +  8] = __float2bfloat16((acc[0][n][2] + bi1) * sc);
                sb[(t + 1) * 72 + cb +  8] = __float2bfloat16((acc[0][n][3] + bi1) * sc);
                sb[(t    ) * 72 + cb + 16] = __float2bfloat16((acc[1][n][0] + bi2) * sc);
                sb[(t + 1) * 72 + cb + 16] = __float2bfloat16((acc[1][n][1] + bi2) * sc);
                sb[(t    ) * 72 + cb + 24] = __float2bfloat16((acc[1][n][2] + bi3) * sc);
                sb[(t + 1) * 72 + cb + 24] = __float2bfloat16((acc[1][n][3] + bi3) * sc);
            }
        } else {
            unsigned* sv = smem_all + band * 4608;
            #pragma unroll
            for (int n = 0; n < 8; n++) {
                int th = wn / 2 + n * 4 + t4;
                sv[(cb     ) * 72 + th] = pack_h2(acc[0][n][0] + bi0, acc[0][n][1] + bi0);
                sv[(cb +  8) * 72 + th] = pack_h2(acc[0][n][2] + bi1, acc[0][n][3] + bi1);
                sv[(cb + 16) * 72 + th] = pack_h2(acc[1][n][0] + bi2, acc[1][n][1] + bi2);
                sv[(cb + 24) * 72 + th] = pack_h2(acc[1][n][2] + bi3, acc[1][n][3] + bi3);
            }
        }
        __syncthreads();
        #pragma unroll
        for (int bandi = 0; bandi < 2; bandi++) {
            const int rb   = m0 + bandi * 64;
            const int clsb = (rb % 192) / 64;
            const int bhb  = blockIdx.z * 4 + rb / 192;
            const char* srcb = (const char*)(smem_all + bandi * 4608);
            if (clsb != 2) {
                char* dstb = (char*)((clsb == 0 ? g_qb : g_kb) + (size_t)bhb * Tn * 64);
                #pragma unroll
                for (int r = 0; r < 4; r++) {
                    int ch = tid + r * 256;
                    int trow = ch >> 3, qc = ch & 7;
                    uint4 v = *(const uint4*)(srcb + trow * 144 + qc * 16);
                    *(uint4*)(dstb + (size_t)(n0 + trow) * 128 + qc * 16) = v;
                }
            } else {
                char* vbs = (char*)(g_vh + (size_t)bhb * 64 * Tn);
                #pragma unroll
                for (int r = 0; r < 4; r++) {
                    int ch = tid + r * 256;
                    int crow = ch >> 4, qc = ch & 15;
                    uint4 v = *(const uint4*)(srcb + crow * 288 + qc * 16);
                    *(uint4*)(vbs + (size_t)crow * (Tn * 2) + (size_t)n0 * 2 + qc * 16) = v;
                }
            }
        }
    } else {
        const float bis[4] = {bi0, bi1, bi2, bi3};
        #pragma unroll
        for (int mi = 0; mi < 2; mi++) {
            const int rA = m0 + wm + g + mi * 16;
            const size_t o0 = ((size_t)blockIdx.z * Cn + rA    ) * Tn + n0 + wn;
            const size_t o1 = ((size_t)blockIdx.z * Cn + rA + 8) * Tn + n0 + wn;
            const float ba = bis[mi * 2], bbv = bis[mi * 2 + 1];
            #pragma unroll
            for (int n = 0; n < 8; n++) {
                int col = n * 8 + 2 * t4;
                *(float2*)(out_param + o0 + col) = make_float2(
                    acc[mi][n][0] + ba  + resid[o0 + col],
                    acc[mi][n][1] + ba  + resid[o0 + col + 1]);
                *(float2*)(out_param + o1 + col) = make_float2(
                    acc[mi][n][2] + bbv + resid[o1 + col],
                    acc[mi][n][3] + bbv + resid[o1 + col + 1]);
            }
        }
    }
}

// ============================================================================
// 3) Flash attention, m32-per-warp (unchanged from R13). S: bf16 mma.
//    P: fp16 via ex2.approx.f16x2 (p = exp(s-2), exact softmax). PV: fp16 mma;
//    l via HADD2 tree + fp32 + end shuffles. Double-buffered K/V, 1 sync/iter.
// ============================================================================
#define KBUF 2304
#define VOFF 4608
#define VBUF 2304
#define SMU  (VOFF + 2 * VBUF)    // 9216 u32 = 36864 B

__global__ __launch_bounds__(128, 2) void attn_kernel() {
    extern __shared__ unsigned su[];
    const int tid  = threadIdx.x;
    const int wid  = tid >> 5;
    const int lane = tid & 31;
    const int g    = lane >> 2;
    const int t4   = lane & 3;
    const int tw   = wid * 32;

    const int t0 = blockIdx.x * 128;
    const int bh = blockIdx.y;
    const __nv_bfloat16* qb = g_qb + ((size_t)bh * Tn + t0) * 64;
    const char* kb = (const char*)(g_kb + (size_t)bh * Tn * 64);
    const char* vb = (const char*)(g_vh + (size_t)bh * 64 * Tn);
    float* ap = g_attn + ((size_t)(bh >> 2) * Cn + (bh & 3) * 64) * Tn;

    #pragma unroll
    for (int r = 0; r < 8; r++) {
        int ch = tid + r * 128;
        int row = ch >> 3, q = ch & 7;
        uint4 v = *(const uint4*)((const char*)qb + ch * 16);
        *(uint4*)&su[row * 36 + q * 4] = v;
    }
    __syncthreads();
    unsigned qf0[4][4], qf1[4][4];
    #pragma unroll
    for (int kk = 0; kk < 4; kk++) {
        qf0[kk][0] = su[(tw + g     ) * 36 + kk * 8 + t4    ];
        qf0[kk][1] = su[(tw + g +  8) * 36 + kk * 8 + t4    ];
        qf0[kk][2] = su[(tw + g     ) * 36 + kk * 8 + t4 + 4];
        qf0[kk][3] = su[(tw + g +  8) * 36 + kk * 8 + t4 + 4];
        qf1[kk][0] = su[(tw + g + 16) * 36 + kk * 8 + t4    ];
        qf1[kk][1] = su[(tw + g + 24) * 36 + kk * 8 + t4    ];
        qf1[kk][2] = su[(tw + g + 16) * 36 + kk * 8 + t4 + 4];
        qf1[kk][3] = su[(tw + g + 24) * 36 + kk * 8 + t4 + 4];
    }
    __syncthreads();

    #pragma unroll
    for (int r = 0; r < 4; r++) {
        int ch = tid + r * 128;
        int row = ch >> 3, q = ch & 7;
        uint4 kv = *(const uint4*)(kb + ch * 16);
        *(uint4*)&su[row * 36 + q * 4] = kv;
        uint4 vv = *(const uint4*)(vb + (size_t)row * (Tn * 2) + q * 16);
        *(uint4*)&su[VOFF + row * 36 + q * 4] = vv;
    }
    __syncthreads();

    float acc_o[16][4];
    #pragma unroll
    for (int n = 0; n < 16; n++)
        #pragma unroll
        for (int r = 0; r < 4; r++) acc_o[n][r] = 0.f;
    float l0 = 0.f, l1 = 0.f, l2 = 0.f, l3 = 0.f;

    for (int i = 0; i < 64; i++) {
        const int cur = i & 1, nxt = cur ^ 1;
        const unsigned* ku = su + cur * KBUF;
        const unsigned* vu = su + VOFF + cur * VBUF;

        uint4 pk[4], pv[4];
        if (i < 63) {
            const char* kg = kb + (size_t)(i + 1) * 8192;
            #pragma unroll
            for (int r = 0; r < 4; r++) {
                int ch = tid + r * 128;
                int row = ch >> 3, q = ch & 7;
                pk[r] = *(const uint4*)(kg + ch * 16);
                pv[r] = *(const uint4*)(vb + (size_t)row * (Tn * 2)
                                        + (size_t)(i + 1) * 128 + q * 16);
            }
        }

        float sacc[16][4];
        #pragma unroll
        for (int n = 0; n < 16; n++)
            #pragma unroll
            for (int r = 0; r < 4; r++) sacc[n][r] = 0.f;
        #pragma unroll
        for (int kk = 0; kk < 4; kk++) {
            #pragma unroll
            for (int n = 0; n < 8; n++) {
                unsigned b0 = ku[(n * 8 + g) * 36 + kk * 8 + t4    ];
                unsigned b1 = ku[(n * 8 + g) * 36 + kk * 8 + t4 + 4];
                mma_bf16(sacc[2*n    ], qf0[kk][0], qf0[kk][1], qf0[kk][2], qf0[kk][3], b0, b1);
                mma_bf16(sacc[2*n + 1], qf1[kk][0], qf1[kk][1], qf1[kk][2], qf1[kk][3], b0, b1);
            }
        }

        unsigned pf0[8], pg0[8], pf1[8], pg1[8];
        #pragma unroll
        for (int n = 0; n < 8; n++) {
            {
                float u0 = fmaf(sacc[2*n][0], LOG2E, -EXSHIFT);
                float u1 = fmaf(sacc[2*n][1], LOG2E, -EXSHIFT);
                float u2 = fmaf(sacc[2*n][2], LOG2E, -EXSHIFT);
                float u3 = fmaf(sacc[2*n][3], LOG2E, -EXSHIFT);
                pf0[n] = ex2_f16x2(cvt_f16x2(u1, u0));
                pg0[n] = ex2_f16x2(cvt_f16x2(u3, u2));
            }
            {
                float u0 = fmaf(sacc[2*n+1][0], LOG2E, -EXSHIFT);
                float u1 = fmaf(sacc[2*n+1][1], LOG2E, -EXSHIFT);
                float u2 = fmaf(sacc[2*n+1][2], LOG2E, -EXSHIFT);
                float u3 = fmaf(sacc[2*n+1][3], LOG2E, -EXSHIFT);
                pf1[n] = ex2_f16x2(cvt_f16x2(u1, u0));
                pg1[n] = ex2_f16x2(cvt_f16x2(u3, u2));
            }
        }

        {
            unsigned s0 = hadd2(hadd2(hadd2(pf0[0], pf0[1]), hadd2(pf0[2], pf0[3])),
                                hadd2(hadd2(pf0[4], pf0[5]), hadd2(pf0[6], pf0[7])));
            unsigned s1 = hadd2(hadd2(hadd2(pg0[0], pg0[1]), hadd2(pg0[2], pg0[3])),
                                hadd2(hadd2(pg0[4], pg0[5]), hadd2(pg0[6], pg0[7])));
            unsigned s2 = hadd2(hadd2(hadd2(pf1[0], pf1[1]), hadd2(pf1[2], pf1[3])),
                                hadd2(hadd2(pf1[4], pf1[5]), hadd2(pf1[6], pf1[7])));
            unsigned s3 = hadd2(hadd2(hadd2(pg1[0], pg1[1]), hadd2(pg1[2], pg1[3])),
                                hadd2(hadd2(pg1[4], pg1[5]), hadd2(pg1[6], pg1[7])));
            l0 += hsum2_f32(s0);
            l1 += hsum2_f32(s1);
            l2 += hsum2_f32(s2);
            l3 += hsum2_f32(s3);
        }

        #pragma unroll
        for (int kk = 0; kk < 4; kk++) {
            unsigned a00 = pf0[2*kk], a01 = pg0[2*kk], a02 = pf0[2*kk+1], a03 = pg0[2*kk+1];
            unsigned a10 = pf1[2*kk], a11 = pg1[2*kk], a12 = pf1[2*kk+1], a13 = pg1[2*kk+1];
            #pragma unroll
            for (int n = 0; n < 8; n++) {
                unsigned b0 = vu[(n * 8 + g) * 36 + kk * 8 + t4    ];
                unsigned b1 = vu[(n * 8 + g) * 36 + kk * 8 + t4 + 4];
                mma_f16(acc_o[2*n    ], a00, a01, a02, a03, b0, b1);
                mma_f16(acc_o[2*n + 1], a10, a11, a12, a13, b0, b1);
            }
        }

        if (i < 63) {
            unsigned* kd = su + nxt * KBUF;
            unsigned* vd = su + VOFF + nxt * VBUF;
            #pragma unroll
            for (int r = 0; r < 4; r++) {
                int ch = tid + r * 128;
                int row = ch >> 3, q = ch & 7;
                *(uint4*)&kd[row * 36 + q * 4] = pk[r];
                *(uint4*)&vd[row * 36 + q * 4] = pv[r];
            }
        }
        __syncthreads();
    }

    l0 += __shfl_xor_sync(0xffffffffu, l0, 1);
    l0 += __shfl_xor_sync(0xffffffffu, l0, 2);
    l1 += __shfl_xor_sync(0xffffffffu, l1, 1);
    l1 += __shfl_xor_sync(0xffffffffu, l1, 2);
    l2 += __shfl_xor_sync(0xffffffffu, l2, 1);
    l2 += __shfl_xor_sync(0xffffffffu, l2, 2);
    l3 += __shfl_xor_sync(0xffffffffu, l3, 1);
    l3 += __shfl_xor_sync(0xffffffffu, l3, 2);
    const float rl0 = 1.f / l0, rl1 = 1.f / l1, rl2 = 1.f / l2, rl3 = 1.f / l3;

    float* o_sm = (float*)su;
    #pragma unroll
    for (int n = 0; n < 8; n++) {
        int c = n * 8 + 2 * t4;
        o_sm[(c    ) * 132 + tw + g     ] = acc_o[2*n  ][0] * rl0;
        o_sm[(c + 1) * 132 + tw + g     ] = acc_o[2*n  ][1] * rl0;
        o_sm[(c    ) * 132 + tw + g +  8] = acc_o[2*n  ][2] * rl1;
        o_sm[(c + 1) * 132 + tw + g +  8] = acc_o[2*n  ][3] * rl1;
        o_sm[(c    ) * 132 + tw + g + 16] = acc_o[2*n+1][0] * rl2;
        o_sm[(c + 1) * 132 + tw + g + 16] = acc_o[2*n+1][1] * rl2;
        o_sm[(c    ) * 132 + tw + g + 24] = acc_o[2*n+1][2] * rl3;
        o_sm[(c + 1) * 132 + tw + g + 24] = acc_o[2*n+1][3] * rl3;
    }
    __syncthreads();
    for (int idx = tid; idx < 2048; idx += 128) {
        int c = idx >> 5, tj = (idx & 31) * 4;
        float4 o4 = *(float4*)&o_sm[c * 132 + tj];
        *(float4*)(ap + (size_t)c * Tn + t0 + tj) = o4;
    }
}

// ============================================================================
extern "C" void kernel_launch(void* const* d_in, const int* in_sizes, int n_in,
                              void* d_out, int out_size) {
    const float* x     = (const float*)d_in[0];
    const float* nw    = (const float*)d_in[1];
    const float* nb    = (const float*)d_in[2];
    const float* qkvw  = (const float*)d_in[3];
    const float* qkvb  = (const float*)d_in[4];
    const float* projw = (const float*)d_in[5];
    const float* projb = (const float*)d_in[6];
    float* out = (float*)d_out;

    const int ATTN_SMEM = SMU * 4;   // 36864 B
    cudaFuncSetAttribute(attn_kernel, cudaFuncAttributeMaxDynamicSharedMemorySize,
                         ATTN_SMEM);

    gn_stats_kernel<<<Bn * 32, 512>>>(x);
    gemm_bf<0><<<dim3(Tn / 128, 768 / 128, Bn), 256>>>(qkvw, qkvb, x, nw, nb,
                                                       nullptr, nullptr);
    attn_kernel<<<dim3(Tn / 128, Bn * 4), 128, ATTN_SMEM>>>();
    gemm_bf<1><<<dim3(Tn / 128, Cn / 128, Bn), 256>>>(projw, projb, nullptr, nullptr,
                                                      nullptr, x, out);
}

// round 15
// speedup vs baseline: 14.5444x; 1.0462x over previous
#include <cuda_runtime.h>
#include <cuda_bf16.h>
#include <cuda_fp16.h>
#include <cstdint>
#include <math.h>

#define Tn 4096
#define Cn 256
#define Bn 2
#define SCALE_QK 0.35355339059327373f   // 64^-0.25
#define LOG2E    1.4426950408889634f
#define EXSHIFT  2.8853900817779268f    // 2*log2(e):  p = exp(s-2)

// GEMM smem geometry (per pipeline stage)
#define BST  136                 // B row stride u32 (136%32==8: conflict-free)
#define ABUF 2560                // A: 128 rows x 20 u32
#define BBUF (16 * BST)          // 2176 u32
#define GBUF (ABUF + BBUF)       // 4736 u32 per stage
#define NSTAGE 4
#define GEMM_SMEM (NSTAGE * GBUF * 4)   // 75776 B

// ---- scratch (__device__ globals: allocation-free) ----
__device__ float2        g_stats[Bn * 32];            // (mean, rstd) per (b,grp)
__device__ unsigned      g_xp [Bn * 128 * Tn];        // x packed bf16 pairs [b][kp][t]
__device__ unsigned      g_op [Bn * 128 * Tn];        // attn out packed [b][kp][t]
__device__ __nv_bfloat16 g_aq [Bn * 768 * 256];       // qkv_w * wc (bf16, per batch)
__device__ float         g_bq [Bn * 768];             // qkvb + qkv_w . bc
__device__ __nv_bfloat16 g_ap [256 * 256];            // proj_w bf16
__device__ __nv_bfloat16 g_qb [Bn * 4 * Tn * 64];     // q [bh][t][c] bf16 scaled
__device__ __nv_bfloat16 g_kb [Bn * 4 * Tn * 64];     // k [bh][s][c] bf16 scaled
__device__ __half        g_vh [Bn * 4 * 64 * Tn];     // v [bh][c][t] fp16

// ---- helpers ----
__device__ __forceinline__ unsigned pack_bf2(float a, float b) {
    __nv_bfloat162 h = __floats2bfloat162_rn(a, b);
    return *(unsigned*)&h;
}
__device__ __forceinline__ unsigned pack_h2(float a, float b) {
    __half2 h = __floats2half2_rn(a, b);
    return *(unsigned*)&h;
}
__device__ __forceinline__ unsigned cvt_f16x2(float hi, float lo) {
    unsigned d;
    asm("cvt.rn.f16x2.f32 %0, %1, %2;" : "=r"(d) : "f"(hi), "f"(lo));
    return d;
}
__device__ __forceinline__ unsigned ex2_f16x2(unsigned a) {
    unsigned d;
    asm("ex2.approx.f16x2 %0, %1;" : "=r"(d) : "r"(a));
    return d;
}
__device__ __forceinline__ unsigned hadd2(unsigned a, unsigned b) {
    unsigned d;
    asm("add.f16x2 %0, %1, %2;" : "=r"(d) : "r"(a), "r"(b));
    return d;
}
__device__ __forceinline__ float hsum2_f32(unsigned h) {
    __half2 v = *(__half2*)&h;
    float2 f = __half22float2(v);
    return f.x + f.y;
}
__device__ __forceinline__ uint32_t smem_u32(const void* p) {
    uint32_t a;
    asm("{ .reg .u64 t; cvta.to.shared.u64 t, %1; cvt.u32.u64 %0, t; }"
        : "=r"(a) : "l"(p));
    return a;
}
#define CP16(dst, src) \
    asm volatile("cp.async.ca.shared.global [%0], [%1], 16;" \
                 :: "r"(dst), "l"(src))
#define CP_COMMIT() asm volatile("cp.async.commit_group;" ::: "memory")
#define CP_WAIT(N)  asm volatile("cp.async.wait_group %0;" :: "n"(N) : "memory")

__device__ __forceinline__ void mma_bf16(float c[4],
                                         unsigned a0, unsigned a1, unsigned a2, unsigned a3,
                                         unsigned b0, unsigned b1) {
    asm volatile(
        "mma.sync.aligned.m16n8k16.row.col.f32.bf16.bf16.f32 "
        "{%0,%1,%2,%3},{%4,%5,%6,%7},{%8,%9},{%0,%1,%2,%3};"
        : "+f"(c[0]), "+f"(c[1]), "+f"(c[2]), "+f"(c[3])
        : "r"(a0), "r"(a1), "r"(a2), "r"(a3), "r"(b0), "r"(b1));
}
__device__ __forceinline__ void mma_f16(float c[4],
                                        unsigned a0, unsigned a1, unsigned a2, unsigned a3,
                                        unsigned b0, unsigned b1) {
    asm volatile(
        "mma.sync.aligned.m16n8k16.row.col.f32.f16.f16.f32 "
        "{%0,%1,%2,%3},{%4,%5,%6,%7},{%8,%9},{%0,%1,%2,%3};"
        : "+f"(c[0]), "+f"(c[1]), "+f"(c[2]), "+f"(c[3])
        : "r"(a0), "r"(a1), "r"(a2), "r"(a3), "r"(b0), "r"(b1));
}

// ============================================================================
// 1) GroupNorm stats + pack x to bf16 k-pair layout g_xp[b][kp][t].
//    grid 64 (b,g), 512 threads. Each block owns 4 k-pairs (8 channels).
// ============================================================================
__global__ __launch_bounds__(512) void gn_stats_pack(const float* __restrict__ x) {
    const int b = blockIdx.x >> 5;
    const int g = blockIdx.x & 31;

    float s = 0.f, s2 = 0.f;
    for (int i = threadIdx.x; i < 4096; i += 512) {
        const int kp_l = i >> 10;
        const int tt   = (i & 1023) * 4;
        const int c0   = g * 8 + kp_l * 2;
        float4 fa = *(const float4*)(x + ((size_t)b * Cn + c0    ) * Tn + tt);
        float4 fb = *(const float4*)(x + ((size_t)b * Cn + c0 + 1) * Tn + tt);
        s  += fa.x + fa.y + fa.z + fa.w + fb.x + fb.y + fb.z + fb.w;
        s2 += fa.x*fa.x + fa.y*fa.y + fa.z*fa.z + fa.w*fa.w
            + fb.x*fb.x + fb.y*fb.y + fb.z*fb.z + fb.w*fb.w;
        uint4 u;
        u.x = pack_bf2(fa.x, fb.x); u.y = pack_bf2(fa.y, fb.y);
        u.z = pack_bf2(fa.z, fb.z); u.w = pack_bf2(fa.w, fb.w);
        *(uint4*)&g_xp[((size_t)b * 128 + g * 4 + kp_l) * Tn + tt] = u;
    }
    __shared__ float rs[512], rs2[512];
    rs[threadIdx.x] = s; rs2[threadIdx.x] = s2;
    __syncthreads();
    for (int off = 256; off > 0; off >>= 1) {
        if (threadIdx.x < off) {
            rs [threadIdx.x] += rs [threadIdx.x + off];
            rs2[threadIdx.x] += rs2[threadIdx.x + off];
        }
        __syncthreads();
    }
    if (threadIdx.x == 0) {
        const float inv  = 1.f / (8.f * Tn);
        const float mean = rs[0] * inv;
        const float var  = rs2[0] * inv - mean * mean;
        g_stats[blockIdx.x] = make_float2(mean, rsqrtf(var + 1e-5f));
    }
}

// ============================================================================
// 1b) Fold GN into A: g_aq[b][m][k] = bf16(qkv_w[m][k] * wc[b][k]);
//     g_bq[b][m] = qkvb[m] + sum_k qkv_w[m][k] * bc[b][k].
//     Also g_ap = bf16(proj_w). 224 blocks x 256 thr (warp per row).
// ============================================================================
__global__ __launch_bounds__(256) void prep_a(const float* __restrict__ qkvw,
                                              const float* __restrict__ qkvb,
                                              const float* __restrict__ nw,
                                              const float* __restrict__ nb,
                                              const float* __restrict__ projw) {
    const int w    = threadIdx.x >> 5;
    const int lane = threadIdx.x & 31;
    const int blk  = blockIdx.x;
    if (blk < 192) {
        const int b  = blk / 96;
        const int m  = (blk % 96) * 8 + w;
        const int k0 = lane * 8;
        float4 v0 = *(const float4*)(qkvw + (size_t)m * 256 + k0);
        float4 v1 = *(const float4*)(qkvw + (size_t)m * 256 + k0 + 4);
        float wv[8] = {v0.x, v0.y, v0.z, v0.w, v1.x, v1.y, v1.z, v1.w};
        float av[8];
        float bsum = 0.f;
        #pragma unroll
        for (int j = 0; j < 8; j++) {
            int k = k0 + j;
            float2 st = g_stats[b * 32 + (k >> 3)];
            float wc = nw[k] * st.y;
            float bc = nb[k] - st.x * wc;
            av[j] = wv[j] * wc;
            bsum += wv[j] * bc;
        }
        uint4 u;
        u.x = pack_bf2(av[0], av[1]); u.y = pack_bf2(av[2], av[3]);
        u.z = pack_bf2(av[4], av[5]); u.w = pack_bf2(av[6], av[7]);
        ((uint4*)(g_aq + ((size_t)b * 768 + m) * 256))[lane] = u;
        #pragma unroll
        for (int off = 16; off > 0; off >>= 1)
            bsum += __shfl_xor_sync(0xffffffffu, bsum, off);
        if (lane == 0) g_bq[b * 768 + m] = qkvb[m] + bsum;
    } else {
        const int m  = (blk - 192) * 8 + w;
        const int k0 = lane * 8;
        float4 v0 = *(const float4*)(projw + (size_t)m * 256 + k0);
        float4 v1 = *(const float4*)(projw + (size_t)m * 256 + k0 + 4);
        uint4 u;
        u.x = pack_bf2(v0.x, v0.y); u.y = pack_bf2(v0.z, v0.w);
        u.z = pack_bf2(v1.x, v1.y); u.w = pack_bf2(v1.z, v1.w);
        ((uint4*)(g_ap + (size_t)m * 256))[lane] = u;
    }
}

// ============================================================================
// 2/4) bf16 GEMM, K=256, 128x128 tiles, cp.async 4-stage pipeline (depth 3).
//   A (bf16 row-major) and B (packed-pair u32 [kp][t]) staged by raw copies.
//   MODE 0: A=g_aq[b], bias=g_bq[b], B=g_xp[b]; epilogue -> g_qb/g_kb/g_vh.
//   MODE 1: A=g_ap, bias=projb, B=g_op[b]; out = gemm + bias + resid.
// ============================================================================
template<int MODE>
__global__ __launch_bounds__(256, 2) void gemm_cp(const float* __restrict__ bias_p,
                                                  const float* __restrict__ resid,
                                                  float* __restrict__ out_param) {
    extern __shared__ unsigned smem_all[];
    const uint32_t smem_b = smem_u32(smem_all);
    const int tid  = threadIdx.x;
    const int wid  = tid >> 5;
    const int lane = tid & 31;
    const int g    = lane >> 2;
    const int t4   = lane & 3;
    const int wm   = (wid >> 1) * 32;
    const int wn   = (wid & 1) * 64;
    const int m0 = blockIdx.y * 128, n0 = blockIdx.x * 128;
    const int z  = blockIdx.z;
    const char* Ab = (const char*)((MODE == 0) ? (g_aq + (size_t)z * 768 * 256)
                                               : g_ap);
    const unsigned* Bp = ((MODE == 0) ? g_xp : g_op) + (size_t)z * 128 * Tn;
    const float* biasp = (MODE == 0) ? (g_bq + z * 768) : bias_p;

    // per-thread copy assignments (2 A-chunks + 2 B-chunks per slice)
    const int am = tid >> 1, akq = (tid & 1) * 2;      // A: m row, chunk pair
    const int bkp = tid >> 5, bc4 = (tid & 31);        // B: kpair row, chunk

    auto issue = [&](int s) {
        const uint32_t base = smem_b + (s & (NSTAGE - 1)) * (GBUF * 4);
        // A slice: rows m0..m0+127, k bytes s*64..+63 (row = 512 B)
        #pragma unroll
        for (int r = 0; r < 2; r++) {
            int kq = akq + r;
            CP16(base + am * 80 + kq * 16,
                 Ab + (size_t)(m0 + am) * 512 + s * 64 + kq * 16);
        }
        // B slice: kpairs s*16..+15, cols n0..n0+127 (seg = 512 B)
        #pragma unroll
        for (int r = 0; r < 2; r++) {
            int kp = bkp + r * 8;
            CP16(base + ABUF * 4 + kp * (BST * 4) + bc4 * 16,
                 (const char*)(Bp + (size_t)(s * 16 + kp) * Tn + n0) + bc4 * 16);
        }
        CP_COMMIT();
    };

    issue(0); issue(1); issue(2);

    float acc[2][8][4] = {};
    #pragma unroll
    for (int s = 0; s < 8; s++) {
        if (s <= 5) CP_WAIT(2);
        else if (s == 6) CP_WAIT(1);
        else CP_WAIT(0);
        __syncthreads();
        const unsigned* asb = smem_all + (s & (NSTAGE - 1)) * GBUF;
        const unsigned* bsb = asb + ABUF;
        #pragma unroll
        for (int kk = 0; kk < 2; kk++) {
            unsigned a00 = asb[(wm + g     ) * 20 + kk * 8 + t4    ];
            unsigned a01 = asb[(wm + g +  8) * 20 + kk * 8 + t4    ];
            unsigned a02 = asb[(wm + g     ) * 20 + kk * 8 + t4 + 4];
            unsigned a03 = asb[(wm + g +  8) * 20 + kk * 8 + t4 + 4];
            unsigned a10 = asb[(wm + g + 16) * 20 + kk * 8 + t4    ];
            unsigned a11 = asb[(wm + g + 24) * 20 + kk * 8 + t4    ];
            unsigned a12 = asb[(wm + g + 16) * 20 + kk * 8 + t4 + 4];
            unsigned a13 = asb[(wm + g + 24) * 20 + kk * 8 + t4 + 4];
            #pragma unroll
            for (int n = 0; n < 8; n++) {
                unsigned b0 = bsb[(kk * 8 + t4    ) * BST + wn + n * 8 + g];
                unsigned b1 = bsb[(kk * 8 + t4 + 4) * BST + wn + n * 8 + g];
                mma_bf16(acc[0][n], a00, a01, a02, a03, b0, b1);
                mma_bf16(acc[1][n], a10, a11, a12, a13, b0, b1);
            }
        }
        if (s < 5) issue(s + 3);
    }
    __syncthreads();   // all MMAs done before epilogue reuses smem

    const float bi0 = biasp[m0 + wm + g     ];
    const float bi1 = biasp[m0 + wm + g +  8];
    const float bi2 = biasp[m0 + wm + g + 16];
    const float bi3 = biasp[m0 + wm + g + 24];

    if (MODE == 0) {
        const int rbw  = m0 + wm;
        const int cls  = (rbw % 192) / 64;      // 0=q 1=k 2=v
        const int band = wm >> 6;
        const int cb   = (wm & 63) + g;
        const float sc = (cls != 2) ? SCALE_QK : 1.f;
        if (cls != 2) {
            __nv_bfloat16* sb = (__nv_bfloat16*)(smem_all + band * 4608);
            #pragma unroll
            for (int n = 0; n < 8; n++) {
                int t = wn + n * 8 + 2 * t4;
                sb[(t    ) * 72 + cb     ] = __float2bfloat16((acc[0][n][0] + bi0) * sc);
                sb[(t + 1) * 72 + cb     ] = __float2bfloat16((acc[0][n][1] + bi0) * sc);
                sb[(t    ) * 72 + cb +  8] = __float2bfloat16((acc[0][n][2] + bi1) * sc);
                sb[(t + 1) * 72 + cb +  8] = __float2bfloat16((acc[0][n][3] + bi1) * sc);
                sb[(t    ) * 72 + cb + 16] = __float2bfloat16((acc[1][n][0] + bi2) * sc);
                sb[(t + 1) * 72 + cb + 16] = __float2bfloat16((acc[1][n][1] + bi2) * sc);
                sb[(t    ) * 72 + cb + 24] = __float2bfloat16((acc[1][n][2] + bi3) * sc);
                sb[(t + 1) * 72 + cb + 24] = __float2bfloat16((acc[1][n][3] + bi3) * sc);
            }
        } else {
            unsigned* sv = smem_all + band * 4608;
            #pragma unroll
            for (int n = 0; n < 8; n++) {
                int th = wn / 2 + n * 4 + t4;
                sv[(cb     ) * 72 + th] = pack_h2(acc[0][n][0] + bi0, acc[0][n][1] + bi0);
                sv[(cb +  8) * 72 + th] = pack_h2(acc[0][n][2] + bi1, acc[0][n][3] + bi1);
                sv[(cb + 16) * 72 + th] = pack_h2(acc[1][n][0] + bi2, acc[1][n][1] + bi2);
                sv[(cb + 24) * 72 + th] = pack_h2(acc[1][n][2] + bi3, acc[1][n][3] + bi3);
            }
        }
        __syncthreads();
        #pragma unroll
        for (int bandi = 0; bandi < 2; bandi++) {
            const int rb   = m0 + bandi * 64;
            const int clsb = (rb % 192) / 64;
            const int bhb  = z * 4 + rb / 192;
            const char* srcb = (const char*)(smem_all + bandi * 4608);
            if (clsb != 2) {
                char* dstb = (char*)((clsb == 0 ? g_qb : g_kb) + (size_t)bhb * Tn * 64);
                #pragma unroll
                for (int r = 0; r < 4; r++) {
                    int ch = tid + r * 256;
                    int trow = ch >> 3, qc = ch & 7;
                    uint4 v = *(const uint4*)(srcb + trow * 144 + qc * 16);
                    *(uint4*)(dstb + (size_t)(n0 + trow) * 128 + qc * 16) = v;
                }
            } else {
                char* vbs = (char*)(g_vh + (size_t)bhb * 64 * Tn);
                #pragma unroll
                for (int r = 0; r < 4; r++) {
                    int ch = tid + r * 256;
                    int crow = ch >> 4, qc = ch & 15;
                    uint4 v = *(const uint4*)(srcb + crow * 288 + qc * 16);
                    *(uint4*)(vbs + (size_t)crow * (Tn * 2) + (size_t)n0 * 2 + qc * 16) = v;
                }
            }
        }
    } else {
        const float bis[4] = {bi0, bi1, bi2, bi3};
        #pragma unroll
        for (int mi = 0; mi < 2; mi++) {
            const int rA = m0 + wm + g + mi * 16;
            const size_t o0 = ((size_t)z * Cn + rA    ) * Tn + n0 + wn;
            const size_t o1 = ((size_t)z * Cn + rA + 8) * Tn + n0 + wn;
            const float ba = bis[mi * 2], bbv = bis[mi * 2 + 1];
            #pragma unroll
            for (int n = 0; n < 8; n++) {
                int col = n * 8 + 2 * t4;
                *(float2*)(out_param + o0 + col) = make_float2(
                    acc[mi][n][0] + ba  + resid[o0 + col],
                    acc[mi][n][1] + ba  + resid[o0 + col + 1]);
                *(float2*)(out_param + o1 + col) = make_float2(
                    acc[mi][n][2] + bbv + resid[o1 + col],
                    acc[mi][n][3] + bbv + resid[o1 + col + 1]);
            }
        }
    }
}

// ============================================================================
// 3) Flash attention (R14 core). Epilogue now emits packed-pair bf16 into
//    g_op[b][kp][t] (adjacent-c fragment pairs pack directly; stride-136 smem
//    staging is conflict-free; coalesced 512B-row writeback).
// ============================================================================
#define KBUF 2304
#define VOFF 4608
#define VBUF 2304
#define SMU  (VOFF + 2 * VBUF)    // 9216 u32 = 36864 B

__global__ __launch_bounds__(128, 2) void attn_kernel() {
    extern __shared__ unsigned su[];
    const int tid  = threadIdx.x;
    const int wid  = tid >> 5;
    const int lane = tid & 31;
    const int g    = lane >> 2;
    const int t4   = lane & 3;
    const int tw   = wid * 32;

    const int t0 = blockIdx.x * 128;
    const int bh = blockIdx.y;
    const __nv_bfloat16* qb = g_qb + ((size_t)bh * Tn + t0) * 64;
    const char* kb = (const char*)(g_kb + (size_t)bh * Tn * 64);
    const char* vb = (const char*)(g_vh + (size_t)bh * 64 * Tn);

    #pragma unroll
    for (int r = 0; r < 8; r++) {
        int ch = tid + r * 128;
        int row = ch >> 3, q = ch & 7;
        uint4 v = *(const uint4*)((const char*)qb + ch * 16);
        *(uint4*)&su[row * 36 + q * 4] = v;
    }
    __syncthreads();
    unsigned qf0[4][4], qf1[4][4];
    #pragma unroll
    for (int kk = 0; kk < 4; kk++) {
        qf0[kk][0] = su[(tw + g     ) * 36 + kk * 8 + t4    ];
        qf0[kk][1] = su[(tw + g +  8) * 36 + kk * 8 + t4    ];
        qf0[kk][2] = su[(tw + g     ) * 36 + kk * 8 + t4 + 4];
        qf0[kk][3] = su[(tw + g +  8) * 36 + kk * 8 + t4 + 4];
        qf1[kk][0] = su[(tw + g + 16) * 36 + kk * 8 + t4    ];
        qf1[kk][1] = su[(tw + g + 24) * 36 + kk * 8 + t4    ];
        qf1[kk][2] = su[(tw + g + 16) * 36 + kk * 8 + t4 + 4];
        qf1[kk][3] = su[(tw + g + 24) * 36 + kk * 8 + t4 + 4];
    }
    __syncthreads();

    #pragma unroll
    for (int r = 0; r < 4; r++) {
        int ch = tid + r * 128;
        int row = ch >> 3, q = ch & 7;
        uint4 kv = *(const uint4*)(kb + ch * 16);
        *(uint4*)&su[row * 36 + q * 4] = kv;
        uint4 vv = *(const uint4*)(vb + (size_t)row * (Tn * 2) + q * 16);
        *(uint4*)&su[VOFF + row * 36 + q * 4] = vv;
    }
    __syncthreads();

    float acc_o[16][4];
    #pragma unroll
    for (int n = 0; n < 16; n++)
        #pragma unroll
        for (int r = 0; r < 4; r++) acc_o[n][r] = 0.f;
    float l0 = 0.f, l1 = 0.f, l2 = 0.f, l3 = 0.f;

    for (int i = 0; i < 64; i++) {
        const int cur = i & 1, nxt = cur ^ 1;
        const unsigned* ku = su + cur * KBUF;
        const unsigned* vu = su + VOFF + cur * VBUF;

        uint4 pk[4], pv[4];
        if (i < 63) {
            const char* kg = kb + (size_t)(i + 1) * 8192;
            #pragma unroll
            for (int r = 0; r < 4; r++) {
                int ch = tid + r * 128;
                int row = ch >> 3, q = ch & 7;
                pk[r] = *(const uint4*)(kg + ch * 16);
                pv[r] = *(const uint4*)(vb + (size_t)row * (Tn * 2)
                                        + (size_t)(i + 1) * 128 + q * 16);
            }
        }

        float sacc[16][4];
        #pragma unroll
        for (int n = 0; n < 16; n++)
            #pragma unroll
            for (int r = 0; r < 4; r++) sacc[n][r] = 0.f;
        #pragma unroll
        for (int kk = 0; kk < 4; kk++) {
            #pragma unroll
            for (int n = 0; n < 8; n++) {
                unsigned b0 = ku[(n * 8 + g) * 36 + kk * 8 + t4    ];
                unsigned b1 = ku[(n * 8 + g) * 36 + kk * 8 + t4 + 4];
                mma_bf16(sacc[2*n    ], qf0[kk][0], qf0[kk][1], qf0[kk][2], qf0[kk][3], b0, b1);
                mma_bf16(sacc[2*n + 1], qf1[kk][0], qf1[kk][1], qf1[kk][2], qf1[kk][3], b0, b1);
            }
        }

        unsigned pf0[8], pg0[8], pf1[8], pg1[8];
        #pragma unroll
        for (int n = 0; n < 8; n++) {
            {
                float u0 = fmaf(sacc[2*n][0], LOG2E, -EXSHIFT);
                float u1 = fmaf(sacc[2*n][1], LOG2E, -EXSHIFT);
                float u2 = fmaf(sacc[2*n][2], LOG2E, -EXSHIFT);
                float u3 = fmaf(sacc[2*n][3], LOG2E, -EXSHIFT);
                pf0[n] = ex2_f16x2(cvt_f16x2(u1, u0));
                pg0[n] = ex2_f16x2(cvt_f16x2(u3, u2));
            }
            {
                float u0 = fmaf(sacc[2*n+1][0], LOG2E, -EXSHIFT);
                float u1 = fmaf(sacc[2*n+1][1], LOG2E, -EXSHIFT);
                float u2 = fmaf(sacc[2*n+1][2], LOG2E, -EXSHIFT);
                float u3 = fmaf(sacc[2*n+1][3], LOG2E, -EXSHIFT);
                pf1[n] = ex2_f16x2(cvt_f16x2(u1, u0));
                pg1[n] = ex2_f16x2(cvt_f16x2(u3, u2));
            }
        }

        {
            unsigned s0 = hadd2(hadd2(hadd2(pf0[0], pf0[1]), hadd2(pf0[2], pf0[3])),
                                hadd2(hadd2(pf0[4], pf0[5]), hadd2(pf0[6], pf0[7])));
            unsigned s1 = hadd2(hadd2(hadd2(pg0[0], pg0[1]), hadd2(pg0[2], pg0[3])),
                                hadd2(hadd2(pg0[4], pg0[5]), hadd2(pg0[6], pg0[7])));
            unsigned s2 = hadd2(hadd2(hadd2(pf1[0], pf1[1]), hadd2(pf1[2], pf1[3])),
                                hadd2(hadd2(pf1[4], pf1[5]), hadd2(pf1[6], pf1[7])));
            unsigned s3 = hadd2(hadd2(hadd2(pg1[0], pg1[1]), hadd2(pg1[2], pg1[3])),
                                hadd2(hadd2(pg1[4], pg1[5]), hadd2(pg1[6], pg1[7])));
            l0 += hsum2_f32(s0);
            l1 += hsum2_f32(s1);
            l2 += hsum2_f32(s2);
            l3 += hsum2_f32(s3);
        }

        #pragma unroll
        for (int kk = 0; kk < 4; kk++) {
            unsigned a00 = pf0[2*kk], a01 = pg0[2*kk], a02 = pf0[2*kk+1], a03 = pg0[2*kk+1];
            unsigned a10 = pf1[2*kk], a11 = pg1[2*kk], a12 = pf1[2*kk+1], a13 = pg1[2*kk+1];
            #pragma unroll
            for (int n = 0; n < 8; n++) {
                unsigned b0 = vu[(n * 8 + g) * 36 + kk * 8 + t4    ];
                unsigned b1 = vu[(n * 8 + g) * 36 + kk * 8 + t4 + 4];
                mma_f16(acc_o[2*n    ], a00, a01, a02, a03, b0, b1);
                mma_f16(acc_o[2*n + 1], a10, a11, a12, a13, b0, b1);
            }
        }

        if (i < 63) {
            unsigned* kd = su + nxt * KBUF;
            unsigned* vd = su + VOFF + nxt * VBUF;
            #pragma unroll
            for (int r = 0; r < 4; r++) {
                int ch = tid + r * 128;
                int row = ch >> 3, q = ch & 7;
                *(uint4*)&kd[row * 36 + q * 4] = pk[r];
                *(uint4*)&vd[row * 36 + q * 4] = pv[r];
            }
        }
        __syncthreads();
    }

    l0 += __shfl_xor_sync(0xffffffffu, l0, 1);
    l0 += __shfl_xor_sync(0xffffffffu, l0, 2);
    l1 += __shfl_xor_sync(0xffffffffu, l1, 1);
    l1 += __shfl_xor_sync(0xffffffffu, l1, 2);
    l2 += __shfl_xor_sync(0xffffffffu, l2, 1);
    l2 += __shfl_xor_sync(0xffffffffu, l2, 2);
    l3 += __shfl_xor_sync(0xffffffffu, l3, 1);
    l3 += __shfl_xor_sync(0xffffffffu, l3, 2);
    const float rl0 = 1.f / l0, rl1 = 1.f / l1, rl2 = 1.f / l2, rl3 = 1.f / l3;

    // ---- epilogue: pack adjacent-c pairs to bf16x2, stage [kp][t], write ----
    unsigned* sp = su;   // [32 kp][136]
    #pragma unroll
    for (int n = 0; n < 8; n++) {
        int kp = n * 4 + t4;
        sp[kp * 136 + tw + g     ] = pack_bf2(acc_o[2*n  ][0] * rl0, acc_o[2*n  ][1] * rl0);
        sp[kp * 136 + tw + g +  8] = pack_bf2(acc_o[2*n  ][2] * rl1, acc_o[2*n  ][3] * rl1);
        sp[kp * 136 + tw + g + 16] = pack_bf2(acc_o[2*n+1][0] * rl2, acc_o[2*n+1][1] * rl2);
        sp[kp * 136 + tw + g + 24] = pack_bf2(acc_o[2*n+1][2] * rl3, acc_o[2*n+1][3] * rl3);
    }
    __syncthreads();
    unsigned* op = g_op + ((size_t)(bh >> 2) * 128 + (bh & 3) * 32) * Tn + t0;
    #pragma unroll
    for (int r = 0; r < 8; r++) {
        int ch = tid + r * 128;
        int kp_l = ch >> 5, q = ch & 31;
        uint4 v = *(uint4*)&sp[kp_l * 136 + q * 4];
        *(uint4*)(op + (size_t)kp_l * Tn + q * 4) = v;
    }
}

// ============================================================================
extern "C" void kernel_launch(void* const* d_in, const int* in_sizes, int n_in,
                              void* d_out, int out_size) {
    const float* x     = (const float*)d_in[0];
    const float* nw    = (const float*)d_in[1];
    const float* nb    = (const float*)d_in[2];
    const float* qkvw  = (const float*)d_in[3];
    const float* qkvb  = (const float*)d_in[4];
    const float* projw = (const float*)d_in[5];
    const float* projb = (const float*)d_in[6];
    float* out = (float*)d_out;

    const int ATTN_SMEM = SMU * 4;   // 36864 B
    cudaFuncSetAttribute(attn_kernel, cudaFuncAttributeMaxDynamicSharedMemorySize,
                         ATTN_SMEM);
    cudaFuncSetAttribute(gemm_cp<0>, cudaFuncAttributeMaxDynamicSharedMemorySize,
                         GEMM_SMEM);
    cudaFuncSetAttribute(gemm_cp<1>, cudaFuncAttributeMaxDynamicSharedMemorySize,
                         GEMM_SMEM);

    gn_stats_pack<<<Bn * 32, 512>>>(x);
    prep_a<<<224, 256>>>(qkvw, qkvb, nw, nb, projw);
    gemm_cp<0><<<dim3(Tn / 128, 768 / 128, Bn), 256, GEMM_SMEM>>>(nullptr, nullptr,
                                                                  nullptr);
    attn_kernel<<<dim3(Tn / 128, Bn * 4), 128, ATTN_SMEM>>>();
    gemm_cp<1><<<dim3(Tn / 128, Cn / 128, Bn), 256, GEMM_SMEM>>>(projb, x, out);
}